// round 3
// baseline (speedup 1.0000x reference)
#include <cuda_runtime.h>
#include <cstdint>
#include <math.h>

// ---------------------------------------------------------------------------
// Static scratch (no allocations allowed)
// ---------------------------------------------------------------------------
#define BF 256          // B*F = 16*16 frame windows
#define NT 256          // frames per window (time)
__device__ __align__(16) float g_x0[(size_t)BF*16*NT*27];    // conv0 out
__device__ __align__(16) float g_x1[(size_t)BF*32*NT*9];     // conv1 out
__device__ __align__(16) float g_x2[(size_t)BF*64*NT*3];     // conv2 out
__device__ __align__(16) float g_xT[(size_t)NT*BF*128];      // conv3 out, [t][n][c]
__device__ __align__(16) float g_G[(size_t)2*65536*512];     // precomputed x@Wih.T + bias, per dir
__device__ __align__(16) float g_hcat[(size_t)BF*65536];     // [n][t*256 + dir*128 + j]
__device__ __align__(16) float g_fc1part[(size_t)64*256*128];// split-K partials
__device__ __align__(16) float g_z1[(size_t)256*128];        // relu(fc1)

// ---------------------------------------------------------------------------
// Conv + ReLU, NCHW, 3x3, stride (1,3), pad (1,1). One block = (frame, time tile).
// ---------------------------------------------------------------------------
template<int CIN,int COUT,int WIN,int WOUT,int TT,int COC,bool TOUT>
__global__ void conv_relu_k(const float* __restrict__ in, const float* __restrict__ w,
                            const float* __restrict__ bias, float* __restrict__ out)
{
    extern __shared__ float sm[];
    float* tile = sm;                           // [CIN][TT+2][WIN]
    float* wsm  = sm + CIN*(TT+2)*WIN;          // [COC][CIN][9]
    const int bf  = blockIdx.y;
    const int t0  = blockIdx.x * TT;
    const int tid = threadIdx.x;

    const int tileN = CIN*(TT+2)*WIN;
    for (int idx = tid; idx < tileN; idx += 256) {
        int ci = idx / ((TT+2)*WIN);
        int r  = idx % ((TT+2)*WIN);
        int tl = r / WIN, wl = r % WIN;
        int tg = t0 + tl - 1;
        float v = 0.f;
        if (tg >= 0 && tg < NT)
            v = in[(((size_t)bf*CIN + ci)*NT + tg)*WIN + wl];
        tile[idx] = v;
    }
    __syncthreads();

    for (int cc = 0; cc < COUT; cc += COC) {
        for (int idx = tid; idx < COC*CIN*9; idx += 256)
            wsm[idx] = w[(size_t)cc*CIN*9 + idx];
        __syncthreads();

        const int NOUT = COC*TT*WOUT;
        for (int o = tid; o < NOUT; o += 256) {
            int col = o % WOUT;
            int r   = o / WOUT;
            int tl  = r % TT;
            int co  = r / TT;
            float acc = bias[cc + co];
            const float* wq = wsm + co*CIN*9;
            for (int ci = 0; ci < CIN; ci++) {
                #pragma unroll
                for (int kh = 0; kh < 3; kh++) {
                    #pragma unroll
                    for (int kw = 0; kw < 3; kw++) {
                        int wc = 3*col + kw - 1;
                        if (wc >= 0 && wc < WIN)
                            acc += wq[ci*9 + kh*3 + kw] *
                                   tile[(ci*(TT+2) + tl + kh)*WIN + wc];
                    }
                }
            }
            acc = fmaxf(acc, 0.f);
            if (TOUT)
                out[((size_t)(t0+tl)*BF + bf)*COUT + (cc+co)] = acc;
            else
                out[(((size_t)bf*COUT + (cc+co))*NT + (t0+tl))*WOUT + col] = acc;
        }
        __syncthreads();
    }
}

// ---------------------------------------------------------------------------
// Input-projection GEMM: G[dir][m][g] = X[m][:] @ W[g][:] + (bih+bhh)[g]
// M=65536, N=512, K=128.  BM=BN=128, BK=16, 8x8 per thread, 256 threads.
// ---------------------------------------------------------------------------
__global__ void gemm_xw_k(const float* __restrict__ X,
                          const float* __restrict__ Wf, const float* __restrict__ Wb,
                          const float* __restrict__ bihf, const float* __restrict__ bhhf,
                          const float* __restrict__ bihb, const float* __restrict__ bhhb)
{
    const int dir = blockIdx.z;
    const float* W  = dir ? Wb   : Wf;
    const float* b1 = dir ? bihb : bihf;
    const float* b2 = dir ? bhhb : bhhf;
    float* out = g_G + (size_t)dir*65536*512;

    __shared__ __align__(16) float As[16][132];
    __shared__ __align__(16) float Bs[16][132];
    const int tid = threadIdx.x;
    const int tx = tid & 15, ty = tid >> 4;
    const int m0 = blockIdx.y * 128, n0 = blockIdx.x * 128;

    float acc[8][8];
    #pragma unroll
    for (int i = 0; i < 8; i++) {
        #pragma unroll
        for (int j = 0; j < 8; j++) acc[i][j] = 0.f;
    }

    for (int kt = 0; kt < 128; kt += 16) {
        #pragma unroll
        for (int i = 0; i < 2; i++) {
            int l = tid*2 + i;
            int row = l >> 2, kq = l & 3;
            float4 v = *(const float4*)(X + (size_t)(m0+row)*128 + kt + kq*4);
            As[kq*4+0][row]=v.x; As[kq*4+1][row]=v.y; As[kq*4+2][row]=v.z; As[kq*4+3][row]=v.w;
            float4 u = *(const float4*)(W + (size_t)(n0+row)*128 + kt + kq*4);
            Bs[kq*4+0][row]=u.x; Bs[kq*4+1][row]=u.y; Bs[kq*4+2][row]=u.z; Bs[kq*4+3][row]=u.w;
        }
        __syncthreads();
        #pragma unroll
        for (int k = 0; k < 16; k++) {
            float a[8], b[8];
            *(float4*)(a  ) = *(const float4*)&As[k][ty*8];
            *(float4*)(a+4) = *(const float4*)&As[k][ty*8+4];
            *(float4*)(b  ) = *(const float4*)&Bs[k][tx*8];
            *(float4*)(b+4) = *(const float4*)&Bs[k][tx*8+4];
            #pragma unroll
            for (int i=0;i<8;i++)
                #pragma unroll
                for (int j=0;j<8;j++)
                    acc[i][j] += a[i]*b[j];
        }
        __syncthreads();
    }
    #pragma unroll
    for (int j = 0; j < 8; j++) {
        int g = n0 + tx*8 + j;
        float bv = b1[g] + b2[g];
        #pragma unroll
        for (int i = 0; i < 8; i++)
            out[(size_t)(m0 + ty*8 + i)*512 + g] = acc[i][j] + bv;
    }
}

// ---------------------------------------------------------------------------
// LSTM recurrence. Cluster of 2 CTAs; each CTA owns half the hidden units
// (gate rows {j, 128+j, 256+j, 384+j} for j in its half -> 128KB smem) and a
// slice of 8 batch elements for all 256 steps. h halves exchanged via DSMEM.
// 128 threads: tid -> (j = tid&63, ng = tid>>6), each thread: 1 j x 4 n.
// ---------------------------------------------------------------------------
__device__ __forceinline__ float sigf(float x) { return 1.f / (1.f + expf(-x)); }

__global__ void __cluster_dims__(2,1,1) __launch_bounds__(128,1)
lstm_k(const float* __restrict__ Whhf, const float* __restrict__ Whhb)
{
    extern __shared__ float sm[];
    float* whh  = sm;                    // [4][64][132]
    float* hbuf = sm + 4*64*132;         // [2][8][132]
    const int tid  = threadIdx.x;
    const int rank = blockIdx.x & 1;
    const int dir  = blockIdx.z;
    const int nb0  = blockIdx.y * 8;
    const float* Whh = dir ? Whhb : Whhf;
    const float* G   = g_G + (size_t)dir*65536*512;

    for (int idx = tid; idx < 4*64*128; idx += 128) {
        int g = idx >> 13;
        int r = (idx >> 7) & 63;
        int k = idx & 127;
        whh[(g*64 + r)*132 + k] = Whh[((size_t)(g*128 + rank*64 + r))*128 + k];
    }
    for (int idx = tid; idx < 2*8*132; idx += 128) hbuf[idx] = 0.f;

    uint32_t hbuf_u32;
    { uint64_t tmp;
      asm("cvta.to.shared.u64 %0, %1;" : "=l"(tmp) : "l"(hbuf));
      hbuf_u32 = (uint32_t)tmp; }

    asm volatile("barrier.cluster.arrive.aligned;\n\tbarrier.cluster.wait.aligned;" ::: "memory");

    const int j    = tid & 63;
    const int ng   = tid >> 6;
    const int gcol = rank*64 + j;
    const int peer = rank ^ 1;
    float c[4] = {0.f, 0.f, 0.f, 0.f};

    const float* wi = whh + (0*64 + j)*132;
    const float* wf = whh + (1*64 + j)*132;
    const float* wg = whh + (2*64 + j)*132;
    const float* wo = whh + (3*64 + j)*132;

    for (int s = 0; s < 256; s++) {
        const int t   = dir ? (255 - s) : s;
        const int cur = s & 1, nxt = cur ^ 1;

        float Gi[4], Gf[4], Gg[4], Go[4];
        #pragma unroll
        for (int nn = 0; nn < 4; nn++) {
            size_t base = ((size_t)t*256 + nb0 + ng*4 + nn)*512 + gcol;
            Gi[nn] = G[base];       Gf[nn] = G[base+128];
            Gg[nn] = G[base+256];   Go[nn] = G[base+384];
        }

        float ai[4]={0,0,0,0}, af[4]={0,0,0,0}, ag[4]={0,0,0,0}, ao[4]={0,0,0,0};
        const float* hb = hbuf + (cur*8 + ng*4)*132;
        #pragma unroll 4
        for (int k4 = 0; k4 < 32; k4++) {
            float4 vi = *(const float4*)(wi + k4*4);
            float4 vf = *(const float4*)(wf + k4*4);
            float4 vg = *(const float4*)(wg + k4*4);
            float4 vo = *(const float4*)(wo + k4*4);
            #pragma unroll
            for (int nn = 0; nn < 4; nn++) {
                float4 hv = *(const float4*)(hb + nn*132 + k4*4);
                ai[nn] += vi.x*hv.x + vi.y*hv.y + vi.z*hv.z + vi.w*hv.w;
                af[nn] += vf.x*hv.x + vf.y*hv.y + vf.z*hv.z + vf.w*hv.w;
                ag[nn] += vg.x*hv.x + vg.y*hv.y + vg.z*hv.z + vg.w*hv.w;
                ao[nn] += vo.x*hv.x + vo.y*hv.y + vo.z*hv.z + vo.w*hv.w;
            }
        }

        #pragma unroll
        for (int nn = 0; nn < 4; nn++) {
            float iv = sigf(ai[nn] + Gi[nn]);
            float fv = sigf(af[nn] + Gf[nn]);
            float gv = tanhf(ag[nn] + Gg[nn]);
            float ov = sigf(ao[nn] + Go[nn]);
            c[nn] = fv*c[nn] + iv*gv;
            float hv = ov * tanhf(c[nn]);
            int n = nb0 + ng*4 + nn;
            g_hcat[(size_t)n*65536 + t*256 + dir*128 + gcol] = hv;
            int off = (nxt*8 + ng*4 + nn)*132 + gcol;
            hbuf[off] = hv;
            uint32_t raddr;
            asm volatile("mapa.shared::cluster.u32 %0, %1, %2;"
                         : "=r"(raddr) : "r"(hbuf_u32 + (uint32_t)off*4u), "r"(peer));
            asm volatile("st.shared::cluster.f32 [%0], %1;" :: "r"(raddr), "f"(hv) : "memory");
        }
        asm volatile("barrier.cluster.arrive.aligned;\n\tbarrier.cluster.wait.aligned;" ::: "memory");
    }
}

// ---------------------------------------------------------------------------
// FC1 split-K partials: z1pre[m][h] = hcat[m][:] @ fc1_w[h][:]
// BM=64, BN=128(all h), per-block K chunk = 1024. grid (4 m-tiles, 64 k-chunks)
// ---------------------------------------------------------------------------
__global__ void fc1_part_k(const float* __restrict__ fw)
{
    __shared__ __align__(16) float As[16][68];
    __shared__ __align__(16) float Bs[16][132];
    const int tid = threadIdx.x;
    const int tx = tid & 15, ty = tid >> 4;
    const int m0 = blockIdx.x * 64;
    const int k0 = blockIdx.y * 1024;

    float acc[4][8];
    #pragma unroll
    for (int i = 0; i < 4; i++) {
        #pragma unroll
        for (int j = 0; j < 8; j++) acc[i][j] = 0.f;
    }

    for (int kt = 0; kt < 1024; kt += 16) {
        {
            int l = tid;               // 256 float4 for A (64x16)
            int row = l >> 2, kq = l & 3;
            float4 v = *(const float4*)(g_hcat + (size_t)(m0+row)*65536 + k0 + kt + kq*4);
            As[kq*4+0][row]=v.x; As[kq*4+1][row]=v.y; As[kq*4+2][row]=v.z; As[kq*4+3][row]=v.w;
        }
        #pragma unroll
        for (int i = 0; i < 2; i++) {  // 512 float4 for B (128x16)
            int l = tid*2 + i;
            int row = l >> 2, kq = l & 3;
            float4 u = *(const float4*)(fw + (size_t)row*65536 + k0 + kt + kq*4);
            Bs[kq*4+0][row]=u.x; Bs[kq*4+1][row]=u.y; Bs[kq*4+2][row]=u.z; Bs[kq*4+3][row]=u.w;
        }
        __syncthreads();
        #pragma unroll
        for (int k = 0; k < 16; k++) {
            float a[4], b[8];
            *(float4*)(a  ) = *(const float4*)&As[k][ty*4];
            *(float4*)(b  ) = *(const float4*)&Bs[k][tx*8];
            *(float4*)(b+4) = *(const float4*)&Bs[k][tx*8+4];
            #pragma unroll
            for (int i=0;i<4;i++)
                #pragma unroll
                for (int jj=0;jj<8;jj++)
                    acc[i][jj] += a[i]*b[jj];
        }
        __syncthreads();
    }
    #pragma unroll
    for (int i = 0; i < 4; i++)
        #pragma unroll
        for (int jj = 0; jj < 8; jj++)
            g_fc1part[((size_t)blockIdx.y*256 + m0 + ty*4 + i)*128 + tx*8 + jj] = acc[i][jj];
}

__global__ void fc1_reduce_k(const float* __restrict__ fc1b)
{
    int idx = blockIdx.x*256 + threadIdx.x;      // 32768 total
    int m = idx >> 7, h = idx & 127;
    float s = fc1b[h];
    #pragma unroll 8
    for (int kc = 0; kc < 64; kc++)
        s += g_fc1part[((size_t)kc*256 + m)*128 + h];
    g_z1[(size_t)m*128 + h] = fmaxf(s, 0.f);
}

// frames + utterance means -> d_out[0:16)=utt, d_out[16:272)=frames
__global__ void score_k(const float* __restrict__ fsw, const float* __restrict__ fsb,
                        float* __restrict__ out)
{
    __shared__ float w[128];
    __shared__ float fr[256];
    int tid = threadIdx.x;
    if (tid < 128) w[tid] = fsw[tid];
    __syncthreads();
    float acc = fsb[0];
    #pragma unroll 8
    for (int h = 0; h < 128; h++) acc += g_z1[(size_t)tid*128 + h] * w[h];
    float sc = 1.f / (1.f + expf(-acc)) * 4.f + 1.f;
    out[16 + tid] = sc;
    fr[tid] = sc;
    __syncthreads();
    if (tid < 16) {
        float s = 0.f;
        #pragma unroll
        for (int f = 0; f < 16; f++) s += fr[tid*16 + f];
        out[tid] = s * (1.f/16.f);
    }
}

// ---------------------------------------------------------------------------
extern "C" void kernel_launch(void* const* d_in, const int* in_sizes, int n_in,
                              void* d_out, int out_size)
{
    // Input order detection: signature order has w0 (144 elems) at index 1;
    // dict order has sample_lengths (16) there.
    const float *audio,*w0,*b0,*w1,*b1,*w2,*b2,*w3,*b3;
    const float *Wihf,*Whhf,*bihf,*bhhf,*Wihb,*Whhb,*bihb,*bhhb;
    const float *fc1w,*fc1b,*fsw,*fsb;
    if (n_in >= 22 && in_sizes[1] == 144) {
        audio=(const float*)d_in[0];
        w0=(const float*)d_in[1];  b0=(const float*)d_in[2];
        w1=(const float*)d_in[3];  b1=(const float*)d_in[4];
        w2=(const float*)d_in[5];  b2=(const float*)d_in[6];
        w3=(const float*)d_in[7];  b3=(const float*)d_in[8];
        Wihf=(const float*)d_in[9];  Whhf=(const float*)d_in[10];
        bihf=(const float*)d_in[11]; bhhf=(const float*)d_in[12];
        Wihb=(const float*)d_in[13]; Whhb=(const float*)d_in[14];
        bihb=(const float*)d_in[15]; bhhb=(const float*)d_in[16];
        fc1w=(const float*)d_in[17]; fc1b=(const float*)d_in[18];
        fsw=(const float*)d_in[19];  fsb=(const float*)d_in[20];
    } else {
        audio=(const float*)d_in[0];
        // d_in[1] = sample_lengths (unused; all == T)
        w0=(const float*)d_in[2];  b0=(const float*)d_in[3];
        w1=(const float*)d_in[4];  b1=(const float*)d_in[5];
        w2=(const float*)d_in[6];  b2=(const float*)d_in[7];
        w3=(const float*)d_in[8];  b3=(const float*)d_in[9];
        Wihf=(const float*)d_in[10]; Whhf=(const float*)d_in[11];
        bihf=(const float*)d_in[12]; bhhf=(const float*)d_in[13];
        Wihb=(const float*)d_in[14]; Whhb=(const float*)d_in[15];
        bihb=(const float*)d_in[16]; bhhb=(const float*)d_in[17];
        fc1w=(const float*)d_in[18]; fc1b=(const float*)d_in[19];
        fsw=(const float*)d_in[20];  fsb=(const float*)d_in[21];
    }

    float* xT; cudaGetSymbolAddress((void**)&xT, g_xT);  // host-side, capture-safe
    float* x0; cudaGetSymbolAddress((void**)&x0, g_x0);
    float* x1; cudaGetSymbolAddress((void**)&x1, g_x1);
    float* x2; cudaGetSymbolAddress((void**)&x2, g_x2);

    // dynamic smem sizes
    const int s0 = (1*66*81  + 16*1*9 )*4;   // 21.9 KB
    const int s1 = (16*34*27 + 32*16*9)*4;   // 77.2 KB
    const int s2 = (32*66*9  + 32*32*9)*4;   // 112.9 KB
    const int s3 = (64*66*3  + 32*64*9)*4;   // 124.4 KB
    const int sl = (4*64*132 + 2*8*132)*4;   // 143.6 KB
    cudaFuncSetAttribute(conv_relu_k<1 ,16 ,81,27,64,16,false>, cudaFuncAttributeMaxDynamicSharedMemorySize, s0);
    cudaFuncSetAttribute(conv_relu_k<16,32 ,27, 9,32,32,false>, cudaFuncAttributeMaxDynamicSharedMemorySize, s1);
    cudaFuncSetAttribute(conv_relu_k<32,64 , 9, 3,64,32,false>, cudaFuncAttributeMaxDynamicSharedMemorySize, s2);
    cudaFuncSetAttribute(conv_relu_k<64,128, 3, 1,64,32,true >, cudaFuncAttributeMaxDynamicSharedMemorySize, s3);
    cudaFuncSetAttribute(lstm_k, cudaFuncAttributeMaxDynamicSharedMemorySize, sl);

    conv_relu_k<1 ,16 ,81,27,64,16,false><<<dim3(4,BF), 256, s0>>>(audio, w0, b0, x0);
    conv_relu_k<16,32 ,27, 9,32,32,false><<<dim3(8,BF), 256, s1>>>(x0, w1, b1, x1);
    conv_relu_k<32,64 , 9, 3,64,32,false><<<dim3(4,BF), 256, s2>>>(x1, w2, b2, x2);
    conv_relu_k<64,128, 3, 1,64,32,true ><<<dim3(4,BF), 256, s3>>>(x2, w3, b3, xT);

    gemm_xw_k<<<dim3(4,512,2), 256>>>(xT, Wihf, Wihb, bihf, bhhf, bihb, bhhb);

    lstm_k<<<dim3(2,32,2), 128, sl>>>(Whhf, Whhb);

    fc1_part_k<<<dim3(4,64), 256>>>(fc1w);
    fc1_reduce_k<<<128, 256>>>(fc1b);
    score_k<<<1, 256>>>(fsw, fsb, (float*)d_out);
}

// round 4
// speedup vs baseline: 1.5594x; 1.5594x over previous
#include <cuda_runtime.h>
#include <cstdint>
#include <math.h>

// ---------------------------------------------------------------------------
// Static scratch (no allocations allowed)
// ---------------------------------------------------------------------------
#define BF 256          // B*F = 16*16 frame windows
#define NT 256          // frames per window (time)
__device__ __align__(16) float g_x0[(size_t)BF*NT*27*16];    // conv0 out NHWC
__device__ __align__(16) float g_x1[(size_t)BF*NT*9*32];     // conv1 out NHWC
__device__ __align__(16) float g_x2[(size_t)BF*NT*3*64];     // conv2 out NHWC
__device__ __align__(16) float g_xT[(size_t)NT*BF*128];      // conv3 out, [t][n][c]
__device__ __align__(16) float g_G[(size_t)2*65536*512];     // x@Wih.T + bias, per dir
__device__ __align__(16) float g_hcat[(size_t)BF*65536];     // [n][t*256 + dir*128 + j]
__device__ __align__(16) float g_fc1part[(size_t)64*256*128];// split-K partials
__device__ __align__(16) float g_z1[(size_t)256*128];        // relu(fc1)
__device__ __align__(16) float g_wT1[9*16*32];               // conv1 weights [tap][ci][co]
__device__ __align__(16) float g_wT2[9*32*64];
__device__ __align__(16) float g_wT3[9*64*128];

// ---------------------------------------------------------------------------
// Weight transform: w[co][ci][kh][kw] -> wT[tap][ci][co]
// ---------------------------------------------------------------------------
__global__ void wtrans_k(const float* __restrict__ w, float* __restrict__ wT,
                         int CIN, int COUT)
{
    int idx = blockIdx.x*256 + threadIdx.x;
    int total = 9*CIN*COUT;
    if (idx >= total) return;
    int co  = idx % COUT;
    int r   = idx / COUT;
    int ci  = r % CIN;
    int tap = r / CIN;
    wT[idx] = w[(co*CIN + ci)*9 + tap];
}

// ---------------------------------------------------------------------------
// conv0: CIN=1 -> 16, direct (memory bound). out NHWC [bf][t][27][16].
// ---------------------------------------------------------------------------
__global__ void conv0_k(const float* __restrict__ audio, const float* __restrict__ w,
                        const float* __restrict__ bias, float* __restrict__ out)
{
    __shared__ float wsm[9][16];
    __shared__ float bsm[16];
    int tid = threadIdx.x;
    if (tid < 144) wsm[tid % 9][tid / 9] = w[tid];
    if (tid < 16)  bsm[tid] = bias[tid];
    __syncthreads();

    size_t idx = (size_t)blockIdx.x*256 + tid;   // (bf, t, wo)
    int wo = (int)(idx % 27);
    size_t r = idx / 27;
    int t  = (int)(r % NT);
    int bf = (int)(r / NT);

    float acc[16];
    #pragma unroll
    for (int co = 0; co < 16; co++) acc[co] = bsm[co];

    #pragma unroll
    for (int kh = 0; kh < 3; kh++) {
        int ti = t + kh - 1;
        if (ti < 0 || ti >= NT) continue;
        #pragma unroll
        for (int kw = 0; kw < 3; kw++) {
            int wc = 3*wo + kw - 1;
            if (wc < 0 || wc >= 81) continue;
            float v = audio[((size_t)bf*NT + ti)*81 + wc];
            #pragma unroll
            for (int co = 0; co < 16; co++) acc[co] += v * wsm[kh*3+kw][co];
        }
    }
    float* o = out + idx*16;
    #pragma unroll
    for (int q = 0; q < 4; q++) {
        float4 v;
        v.x = fmaxf(acc[q*4+0], 0.f); v.y = fmaxf(acc[q*4+1], 0.f);
        v.z = fmaxf(acc[q*4+2], 0.f); v.w = fmaxf(acc[q*4+3], 0.f);
        *(float4*)(o + q*4) = v;
    }
}

// ---------------------------------------------------------------------------
// Implicit-GEMM conv (NHWC). Block = (t-tile of 128, wo, bf); N = COUT.
// K = valid taps x CIN, chunked by 16. Register tile TM x TN per thread.
// ---------------------------------------------------------------------------
template<int CIN,int COUT,int WIN,int WOUT,int TM,int TN,bool TOUT>
__global__ void conv_igemm_k(const float* __restrict__ x, const float* __restrict__ wT,
                             const float* __restrict__ bias, float* __restrict__ out)
{
    constexpr int BM  = 128;
    constexpr int NTX = COUT / TN;
    constexpr int NCHK = CIN / 16;
    static_assert(NTX * (BM/TM) == 256, "thread tiling");
    __shared__ __align__(16) float As[16][BM + 4];
    __shared__ __align__(16) float Bs[16][COUT + 4];

    const int tid = threadIdx.x;
    const int t0  = blockIdx.x * BM;
    const int wo  = blockIdx.y;
    const int bf  = blockIdx.z;
    const int tx  = tid % NTX, ty = tid / NTX;

    float acc[TM][TN];
    #pragma unroll
    for (int i = 0; i < TM; i++)
        #pragma unroll
        for (int j = 0; j < TN; j++) acc[i][j] = 0.f;

    #pragma unroll
    for (int kh = 0; kh < 3; kh++) {
        #pragma unroll
        for (int kw = 0; kw < 3; kw++) {
            const int wc = 3*wo + kw - 1;
            if (wc < 0 || wc >= WIN) continue;
            #pragma unroll
            for (int cc = 0; cc < NCHK; cc++) {
                const int ci0 = cc*16;
                // A: 128 t-rows x 16 ci, transposed into As[k][m]
                #pragma unroll
                for (int i = 0; i < 2; i++) {
                    int l = tid*2 + i;
                    int m = l >> 2, kq = l & 3;
                    int t_in = t0 + m + kh - 1;
                    float4 v = make_float4(0.f, 0.f, 0.f, 0.f);
                    if (t_in >= 0 && t_in < NT)
                        v = *(const float4*)(x + (((size_t)bf*NT + t_in)*WIN + wc)*CIN + ci0 + kq*4);
                    As[kq*4+0][m]=v.x; As[kq*4+1][m]=v.y; As[kq*4+2][m]=v.z; As[kq*4+3][m]=v.w;
                }
                // B: 16 ci x COUT co (already K-major in wT)
                const float* wtap = wT + ((size_t)(kh*3+kw)*CIN + ci0)*COUT;
                for (int l = tid; l < 4*COUT; l += 256) {
                    int k = l / (COUT/4), n4 = l % (COUT/4);
                    *(float4*)&Bs[k][n4*4] = *(const float4*)(wtap + k*COUT + n4*4);
                }
                __syncthreads();
                #pragma unroll
                for (int k = 0; k < 16; k++) {
                    float a[TM], b[TN];
                    #pragma unroll
                    for (int q = 0; q < TM/4; q++)
                        *(float4*)(a+q*4) = *(const float4*)&As[k][ty*TM+q*4];
                    #pragma unroll
                    for (int q = 0; q < TN/4; q++)
                        *(float4*)(b+q*4) = *(const float4*)&Bs[k][tx*TN+q*4];
                    #pragma unroll
                    for (int i = 0; i < TM; i++)
                        #pragma unroll
                        for (int j = 0; j < TN; j++)
                            acc[i][j] += a[i]*b[j];
                }
                __syncthreads();
            }
        }
    }

    float bv[TN];
    #pragma unroll
    for (int j = 0; j < TN; j++) bv[j] = bias[tx*TN+j];
    #pragma unroll
    for (int i = 0; i < TM; i++) {
        int m = ty*TM + i;
        float o[TN];
        #pragma unroll
        for (int j = 0; j < TN; j++) o[j] = fmaxf(acc[i][j] + bv[j], 0.f);
        size_t base;
        if (TOUT) base = ((size_t)(t0+m)*BF + bf)*COUT + tx*TN;
        else      base = (((size_t)bf*NT + (t0+m))*WOUT + wo)*COUT + tx*TN;
        #pragma unroll
        for (int q = 0; q < TN/4; q++)
            *(float4*)(out + base + q*4) = *(float4*)(o + q*4);
    }
}

// ---------------------------------------------------------------------------
// Input-projection GEMM: G[dir][m][g] = X[m][:] @ W[g][:] + (bih+bhh)[g]
// M=65536, N=512, K=128.  BM=BN=128, BK=16, 8x8 per thread, 256 threads.
// ---------------------------------------------------------------------------
__global__ void gemm_xw_k(const float* __restrict__ X,
                          const float* __restrict__ Wf, const float* __restrict__ Wb,
                          const float* __restrict__ bihf, const float* __restrict__ bhhf,
                          const float* __restrict__ bihb, const float* __restrict__ bhhb)
{
    const int dir = blockIdx.z;
    const float* W  = dir ? Wb   : Wf;
    const float* b1 = dir ? bihb : bihf;
    const float* b2 = dir ? bhhb : bhhf;
    float* out = g_G + (size_t)dir*65536*512;

    __shared__ __align__(16) float As[16][132];
    __shared__ __align__(16) float Bs[16][132];
    const int tid = threadIdx.x;
    const int tx = tid & 15, ty = tid >> 4;
    const int m0 = blockIdx.y * 128, n0 = blockIdx.x * 128;

    float acc[8][8];
    #pragma unroll
    for (int i = 0; i < 8; i++) {
        #pragma unroll
        for (int j = 0; j < 8; j++) acc[i][j] = 0.f;
    }

    for (int kt = 0; kt < 128; kt += 16) {
        #pragma unroll
        for (int i = 0; i < 2; i++) {
            int l = tid*2 + i;
            int row = l >> 2, kq = l & 3;
            float4 v = *(const float4*)(X + (size_t)(m0+row)*128 + kt + kq*4);
            As[kq*4+0][row]=v.x; As[kq*4+1][row]=v.y; As[kq*4+2][row]=v.z; As[kq*4+3][row]=v.w;
            float4 u = *(const float4*)(W + (size_t)(n0+row)*128 + kt + kq*4);
            Bs[kq*4+0][row]=u.x; Bs[kq*4+1][row]=u.y; Bs[kq*4+2][row]=u.z; Bs[kq*4+3][row]=u.w;
        }
        __syncthreads();
        #pragma unroll
        for (int k = 0; k < 16; k++) {
            float a[8], b[8];
            *(float4*)(a  ) = *(const float4*)&As[k][ty*8];
            *(float4*)(a+4) = *(const float4*)&As[k][ty*8+4];
            *(float4*)(b  ) = *(const float4*)&Bs[k][tx*8];
            *(float4*)(b+4) = *(const float4*)&Bs[k][tx*8+4];
            #pragma unroll
            for (int i=0;i<8;i++)
                #pragma unroll
                for (int j=0;j<8;j++)
                    acc[i][j] += a[i]*b[j];
        }
        __syncthreads();
    }
    #pragma unroll
    for (int j = 0; j < 8; j++) {
        int g = n0 + tx*8 + j;
        float bv = b1[g] + b2[g];
        #pragma unroll
        for (int i = 0; i < 8; i++)
            out[(size_t)(m0 + ty*8 + i)*512 + g] = acc[i][j] + bv;
    }
}

// ---------------------------------------------------------------------------
// LSTM recurrence. Cluster of 2 CTAs; each CTA owns half the hidden units.
// ---------------------------------------------------------------------------
__device__ __forceinline__ float sigf(float x) { return 1.f / (1.f + expf(-x)); }

__global__ void __cluster_dims__(2,1,1) __launch_bounds__(128,1)
lstm_k(const float* __restrict__ Whhf, const float* __restrict__ Whhb)
{
    extern __shared__ float sm[];
    float* whh  = sm;                    // [4][64][132]
    float* hbuf = sm + 4*64*132;         // [2][8][132]
    const int tid  = threadIdx.x;
    const int rank = blockIdx.x & 1;
    const int dir  = blockIdx.z;
    const int nb0  = blockIdx.y * 8;
    const float* Whh = dir ? Whhb : Whhf;
    const float* G   = g_G + (size_t)dir*65536*512;

    for (int idx = tid; idx < 4*64*128; idx += 128) {
        int g = idx >> 13;
        int r = (idx >> 7) & 63;
        int k = idx & 127;
        whh[(g*64 + r)*132 + k] = Whh[((size_t)(g*128 + rank*64 + r))*128 + k];
    }
    for (int idx = tid; idx < 2*8*132; idx += 128) hbuf[idx] = 0.f;

    uint32_t hbuf_u32;
    { uint64_t tmp;
      asm("cvta.to.shared.u64 %0, %1;" : "=l"(tmp) : "l"(hbuf));
      hbuf_u32 = (uint32_t)tmp; }

    asm volatile("barrier.cluster.arrive.aligned;\n\tbarrier.cluster.wait.aligned;" ::: "memory");

    const int j    = tid & 63;
    const int ng   = tid >> 6;
    const int gcol = rank*64 + j;
    const int peer = rank ^ 1;
    float c[4] = {0.f, 0.f, 0.f, 0.f};

    const float* wi = whh + (0*64 + j)*132;
    const float* wf = whh + (1*64 + j)*132;
    const float* wg = whh + (2*64 + j)*132;
    const float* wo = whh + (3*64 + j)*132;

    for (int s = 0; s < 256; s++) {
        const int t   = dir ? (255 - s) : s;
        const int cur = s & 1, nxt = cur ^ 1;

        float Gi[4], Gf[4], Gg[4], Go[4];
        #pragma unroll
        for (int nn = 0; nn < 4; nn++) {
            size_t base = ((size_t)t*256 + nb0 + ng*4 + nn)*512 + gcol;
            Gi[nn] = G[base];       Gf[nn] = G[base+128];
            Gg[nn] = G[base+256];   Go[nn] = G[base+384];
        }

        float ai[4]={0,0,0,0}, af[4]={0,0,0,0}, ag[4]={0,0,0,0}, ao[4]={0,0,0,0};
        const float* hb = hbuf + (cur*8 + ng*4)*132;
        #pragma unroll 4
        for (int k4 = 0; k4 < 32; k4++) {
            float4 vi = *(const float4*)(wi + k4*4);
            float4 vf = *(const float4*)(wf + k4*4);
            float4 vg = *(const float4*)(wg + k4*4);
            float4 vo = *(const float4*)(wo + k4*4);
            #pragma unroll
            for (int nn = 0; nn < 4; nn++) {
                float4 hv = *(const float4*)(hb + nn*132 + k4*4);
                ai[nn] += vi.x*hv.x + vi.y*hv.y + vi.z*hv.z + vi.w*hv.w;
                af[nn] += vf.x*hv.x + vf.y*hv.y + vf.z*hv.z + vf.w*hv.w;
                ag[nn] += vg.x*hv.x + vg.y*hv.y + vg.z*hv.z + vg.w*hv.w;
                ao[nn] += vo.x*hv.x + vo.y*hv.y + vo.z*hv.z + vo.w*hv.w;
            }
        }

        #pragma unroll
        for (int nn = 0; nn < 4; nn++) {
            float iv = sigf(ai[nn] + Gi[nn]);
            float fv = sigf(af[nn] + Gf[nn]);
            float gv = tanhf(ag[nn] + Gg[nn]);
            float ov = sigf(ao[nn] + Go[nn]);
            c[nn] = fv*c[nn] + iv*gv;
            float hv = ov * tanhf(c[nn]);
            int n = nb0 + ng*4 + nn;
            g_hcat[(size_t)n*65536 + t*256 + dir*128 + gcol] = hv;
            int off = (nxt*8 + ng*4 + nn)*132 + gcol;
            hbuf[off] = hv;
            uint32_t raddr;
            asm volatile("mapa.shared::cluster.u32 %0, %1, %2;"
                         : "=r"(raddr) : "r"(hbuf_u32 + (uint32_t)off*4u), "r"(peer));
            asm volatile("st.shared::cluster.f32 [%0], %1;" :: "r"(raddr), "f"(hv) : "memory");
        }
        asm volatile("barrier.cluster.arrive.aligned;\n\tbarrier.cluster.wait.aligned;" ::: "memory");
    }
}

// ---------------------------------------------------------------------------
// FC1 split-K partials: z1pre[m][h] = hcat[m][:] @ fc1_w[h][:]
// ---------------------------------------------------------------------------
__global__ void fc1_part_k(const float* __restrict__ fw)
{
    __shared__ __align__(16) float As[16][68];
    __shared__ __align__(16) float Bs[16][132];
    const int tid = threadIdx.x;
    const int tx = tid & 15, ty = tid >> 4;
    const int m0 = blockIdx.x * 64;
    const int k0 = blockIdx.y * 1024;

    float acc[4][8];
    #pragma unroll
    for (int i = 0; i < 4; i++) {
        #pragma unroll
        for (int j = 0; j < 8; j++) acc[i][j] = 0.f;
    }

    for (int kt = 0; kt < 1024; kt += 16) {
        {
            int l = tid;
            int row = l >> 2, kq = l & 3;
            float4 v = *(const float4*)(g_hcat + (size_t)(m0+row)*65536 + k0 + kt + kq*4);
            As[kq*4+0][row]=v.x; As[kq*4+1][row]=v.y; As[kq*4+2][row]=v.z; As[kq*4+3][row]=v.w;
        }
        #pragma unroll
        for (int i = 0; i < 2; i++) {
            int l = tid*2 + i;
            int row = l >> 2, kq = l & 3;
            float4 u = *(const float4*)(fw + (size_t)row*65536 + k0 + kt + kq*4);
            Bs[kq*4+0][row]=u.x; Bs[kq*4+1][row]=u.y; Bs[kq*4+2][row]=u.z; Bs[kq*4+3][row]=u.w;
        }
        __syncthreads();
        #pragma unroll
        for (int k = 0; k < 16; k++) {
            float a[4], b[8];
            *(float4*)(a  ) = *(const float4*)&As[k][ty*4];
            *(float4*)(b  ) = *(const float4*)&Bs[k][tx*8];
            *(float4*)(b+4) = *(const float4*)&Bs[k][tx*8+4];
            #pragma unroll
            for (int i=0;i<4;i++)
                #pragma unroll
                for (int jj=0;jj<8;jj++)
                    acc[i][jj] += a[i]*b[jj];
        }
        __syncthreads();
    }
    #pragma unroll
    for (int i = 0; i < 4; i++)
        #pragma unroll
        for (int jj = 0; jj < 8; jj++)
            g_fc1part[((size_t)blockIdx.y*256 + m0 + ty*4 + i)*128 + tx*8 + jj] = acc[i][jj];
}

__global__ void fc1_reduce_k(const float* __restrict__ fc1b)
{
    int idx = blockIdx.x*256 + threadIdx.x;
    int m = idx >> 7, h = idx & 127;
    float s = fc1b[h];
    #pragma unroll 8
    for (int kc = 0; kc < 64; kc++)
        s += g_fc1part[((size_t)kc*256 + m)*128 + h];
    g_z1[(size_t)m*128 + h] = fmaxf(s, 0.f);
}

__global__ void score_k(const float* __restrict__ fsw, const float* __restrict__ fsb,
                        float* __restrict__ out)
{
    __shared__ float w[128];
    __shared__ float fr[256];
    int tid = threadIdx.x;
    if (tid < 128) w[tid] = fsw[tid];
    __syncthreads();
    float acc = fsb[0];
    #pragma unroll 8
    for (int h = 0; h < 128; h++) acc += g_z1[(size_t)tid*128 + h] * w[h];
    float sc = 1.f / (1.f + expf(-acc)) * 4.f + 1.f;
    out[16 + tid] = sc;
    fr[tid] = sc;
    __syncthreads();
    if (tid < 16) {
        float s = 0.f;
        #pragma unroll
        for (int f = 0; f < 16; f++) s += fr[tid*16 + f];
        out[tid] = s * (1.f/16.f);
    }
}

// ---------------------------------------------------------------------------
extern "C" void kernel_launch(void* const* d_in, const int* in_sizes, int n_in,
                              void* d_out, int out_size)
{
    const float *audio,*w0,*b0,*w1,*b1,*w2,*b2,*w3,*b3;
    const float *Wihf,*Whhf,*bihf,*bhhf,*Wihb,*Whhb,*bihb,*bhhb;
    const float *fc1w,*fc1b,*fsw,*fsb;
    if (n_in >= 22 && in_sizes[1] == 144) {
        audio=(const float*)d_in[0];
        w0=(const float*)d_in[1];  b0=(const float*)d_in[2];
        w1=(const float*)d_in[3];  b1=(const float*)d_in[4];
        w2=(const float*)d_in[5];  b2=(const float*)d_in[6];
        w3=(const float*)d_in[7];  b3=(const float*)d_in[8];
        Wihf=(const float*)d_in[9];  Whhf=(const float*)d_in[10];
        bihf=(const float*)d_in[11]; bhhf=(const float*)d_in[12];
        Wihb=(const float*)d_in[13]; Whhb=(const float*)d_in[14];
        bihb=(const float*)d_in[15]; bhhb=(const float*)d_in[16];
        fc1w=(const float*)d_in[17]; fc1b=(const float*)d_in[18];
        fsw=(const float*)d_in[19];  fsb=(const float*)d_in[20];
    } else {
        audio=(const float*)d_in[0];
        w0=(const float*)d_in[2];  b0=(const float*)d_in[3];
        w1=(const float*)d_in[4];  b1=(const float*)d_in[5];
        w2=(const float*)d_in[6];  b2=(const float*)d_in[7];
        w3=(const float*)d_in[8];  b3=(const float*)d_in[9];
        Wihf=(const float*)d_in[10]; Whhf=(const float*)d_in[11];
        bihf=(const float*)d_in[12]; bhhf=(const float*)d_in[13];
        Wihb=(const float*)d_in[14]; Whhb=(const float*)d_in[15];
        bihb=(const float*)d_in[16]; bhhb=(const float*)d_in[17];
        fc1w=(const float*)d_in[18]; fc1b=(const float*)d_in[19];
        fsw=(const float*)d_in[20];  fsb=(const float*)d_in[21];
    }

    float *x0,*x1,*x2,*xT,*wT1,*wT2,*wT3;
    cudaGetSymbolAddress((void**)&x0, g_x0);
    cudaGetSymbolAddress((void**)&x1, g_x1);
    cudaGetSymbolAddress((void**)&x2, g_x2);
    cudaGetSymbolAddress((void**)&xT, g_xT);
    cudaGetSymbolAddress((void**)&wT1, g_wT1);
    cudaGetSymbolAddress((void**)&wT2, g_wT2);
    cudaGetSymbolAddress((void**)&wT3, g_wT3);

    const int sl = (4*64*132 + 2*8*132)*4;   // 143.6 KB
    cudaFuncSetAttribute(lstm_k, cudaFuncAttributeMaxDynamicSharedMemorySize, sl);

    // weight transforms (tiny)
    wtrans_k<<<(9*16*32 + 255)/256, 256>>>(w1, wT1, 16, 32);
    wtrans_k<<<(9*32*64 + 255)/256, 256>>>(w2, wT2, 32, 64);
    wtrans_k<<<(9*64*128+ 255)/256, 256>>>(w3, wT3, 64, 128);

    // conv stack (NHWC)
    conv0_k<<<(BF*NT*27)/256, 256>>>(audio, w0, b0, x0);
    conv_igemm_k<16, 32,27,9,4,4,false><<<dim3(2,9,BF), 256>>>(x0, wT1, b1, x1);
    conv_igemm_k<32, 64, 9,3,8,4,false><<<dim3(2,3,BF), 256>>>(x1, wT2, b2, x2);
    conv_igemm_k<64,128, 3,1,8,8,true ><<<dim3(2,1,BF), 256>>>(x2, wT3, b3, xT);

    gemm_xw_k<<<dim3(4,512,2), 256>>>(xT, Wihf, Wihb, bihf, bhhf, bihb, bhhb);

    lstm_k<<<dim3(2,32,2), 128, sl>>>(Whhf, Whhb);

    fc1_part_k<<<dim3(4,64), 256>>>(fc1w);
    fc1_reduce_k<<<128, 256>>>(fc1b);
    score_k<<<1, 256>>>(fsw, fsb, (float*)d_out);
}

// round 5
// speedup vs baseline: 1.6358x; 1.0490x over previous
#include <cuda_runtime.h>
#include <cstdint>
#include <math.h>

// ---------------------------------------------------------------------------
// Static scratch (no allocations allowed)
// ---------------------------------------------------------------------------
#define BF 256          // B*F = 16*16 frame windows
#define NT 256          // frames per window (time)
__device__ __align__(16) float g_x0[(size_t)BF*NT*27*16];    // conv0 out NHWC
__device__ __align__(16) float g_x1[(size_t)BF*NT*9*32];     // conv1 out NHWC
__device__ __align__(16) float g_x2[(size_t)BF*NT*3*64];     // conv2 out NHWC
__device__ __align__(16) float g_xT[(size_t)NT*BF*128];      // conv3 out, [t][n][c]
__device__ __align__(16) float g_G[(size_t)2*65536*512];     // x@Wih.T + bias, per dir
__device__ __align__(16) float g_hcat[(size_t)BF*65536];     // [n][t*256 + dir*128 + j]
__device__ __align__(16) float g_fc1part[(size_t)64*256*128];// split-K partials
__device__ __align__(16) float g_z1[(size_t)256*128];        // relu(fc1)
__device__ __align__(16) float g_wT1[9*16*32];               // conv1 weights [tap][ci][co]
__device__ __align__(16) float g_wT2[9*32*64];
__device__ __align__(16) float g_wT3[9*64*128];

// ---------------------------------------------------------------------------
// f32x2 packed-FMA helpers (sm_103a)
// ---------------------------------------------------------------------------
union F2U { float4 v; unsigned long long u[2]; };
union F2S { unsigned long long u; float f[2]; };

__device__ __forceinline__ unsigned long long ffma2(unsigned long long a,
                                                    unsigned long long b,
                                                    unsigned long long c)
{
    unsigned long long d;
    asm("fma.rn.f32x2 %0, %1, %2, %3;" : "=l"(d) : "l"(a), "l"(b), "l"(c));
    return d;
}
__device__ __forceinline__ unsigned long long dup2(float x)
{
    unsigned long long r;
    asm("mov.b64 %0, {%1, %1};" : "=l"(r) : "f"(x));
    return r;
}

// ---------------------------------------------------------------------------
// Weight transform: w[co][ci][kh][kw] -> wT[tap][ci][co]
// ---------------------------------------------------------------------------
__global__ void wtrans_k(const float* __restrict__ w, float* __restrict__ wT,
                         int CIN, int COUT)
{
    int idx = blockIdx.x*256 + threadIdx.x;
    int total = 9*CIN*COUT;
    if (idx >= total) return;
    int co  = idx % COUT;
    int r   = idx / COUT;
    int ci  = r % CIN;
    int tap = r / CIN;
    wT[idx] = w[(co*CIN + ci)*9 + tap];
}

// ---------------------------------------------------------------------------
// conv0: CIN=1 -> 16, direct (memory bound). out NHWC [bf][t][27][16].
// ---------------------------------------------------------------------------
__global__ void conv0_k(const float* __restrict__ audio, const float* __restrict__ w,
                        const float* __restrict__ bias, float* __restrict__ out)
{
    __shared__ float wsm[9][16];
    __shared__ float bsm[16];
    int tid = threadIdx.x;
    if (tid < 144) wsm[tid % 9][tid / 9] = w[tid];
    if (tid < 16)  bsm[tid] = bias[tid];
    __syncthreads();

    size_t idx = (size_t)blockIdx.x*256 + tid;   // (bf, t, wo)
    int wo = (int)(idx % 27);
    size_t r = idx / 27;
    int t  = (int)(r % NT);
    int bf = (int)(r / NT);

    float acc[16];
    #pragma unroll
    for (int co = 0; co < 16; co++) acc[co] = bsm[co];

    #pragma unroll
    for (int kh = 0; kh < 3; kh++) {
        int ti = t + kh - 1;
        if (ti < 0 || ti >= NT) continue;
        #pragma unroll
        for (int kw = 0; kw < 3; kw++) {
            int wc = 3*wo + kw - 1;
            if (wc < 0 || wc >= 81) continue;
            float v = audio[((size_t)bf*NT + ti)*81 + wc];
            #pragma unroll
            for (int co = 0; co < 16; co++) acc[co] += v * wsm[kh*3+kw][co];
        }
    }
    float* o = out + idx*16;
    #pragma unroll
    for (int q = 0; q < 4; q++) {
        float4 v;
        v.x = fmaxf(acc[q*4+0], 0.f); v.y = fmaxf(acc[q*4+1], 0.f);
        v.z = fmaxf(acc[q*4+2], 0.f); v.w = fmaxf(acc[q*4+3], 0.f);
        *(float4*)(o + q*4) = v;
    }
}

// ---------------------------------------------------------------------------
// Implicit-GEMM conv (NHWC) with f32x2 FMA. Block = (t-tile 128, wo, bf).
// ---------------------------------------------------------------------------
template<int CIN,int COUT,int WIN,int WOUT,int TM,int TN,bool TOUT>
__global__ void conv_igemm_k(const float* __restrict__ x, const float* __restrict__ wT,
                             const float* __restrict__ bias, float* __restrict__ out)
{
    constexpr int BM  = 128;
    constexpr int NTX = COUT / TN;
    constexpr int NCHK = CIN / 16;
    static_assert(NTX * (BM/TM) == 256, "thread tiling");
    __shared__ __align__(16) float As[16][BM + 4];
    __shared__ __align__(16) float Bs[16][COUT + 4];

    const int tid = threadIdx.x;
    const int t0  = blockIdx.x * BM;
    const int wo  = blockIdx.y;
    const int bf  = blockIdx.z;
    const int tx  = tid % NTX, ty = tid / NTX;

    unsigned long long acc2[TM/2][TN];
    #pragma unroll
    for (int i = 0; i < TM/2; i++)
        #pragma unroll
        for (int j = 0; j < TN; j++) acc2[i][j] = 0ull;

    #pragma unroll
    for (int kh = 0; kh < 3; kh++) {
        #pragma unroll
        for (int kw = 0; kw < 3; kw++) {
            const int wc = 3*wo + kw - 1;
            if (wc < 0 || wc >= WIN) continue;
            #pragma unroll
            for (int cc = 0; cc < NCHK; cc++) {
                const int ci0 = cc*16;
                #pragma unroll
                for (int i = 0; i < 2; i++) {
                    int l = tid*2 + i;
                    int m = l >> 2, kq = l & 3;
                    int t_in = t0 + m + kh - 1;
                    float4 v = make_float4(0.f, 0.f, 0.f, 0.f);
                    if (t_in >= 0 && t_in < NT)
                        v = *(const float4*)(x + (((size_t)bf*NT + t_in)*WIN + wc)*CIN + ci0 + kq*4);
                    As[kq*4+0][m]=v.x; As[kq*4+1][m]=v.y; As[kq*4+2][m]=v.z; As[kq*4+3][m]=v.w;
                }
                const float* wtap = wT + ((size_t)(kh*3+kw)*CIN + ci0)*COUT;
                for (int l = tid; l < 4*COUT; l += 256) {
                    int k = l / (COUT/4), n4 = l % (COUT/4);
                    *(float4*)&Bs[k][n4*4] = *(const float4*)(wtap + k*COUT + n4*4);
                }
                __syncthreads();
                #pragma unroll
                for (int k = 0; k < 16; k++) {
                    F2U a4[TM/4];
                    #pragma unroll
                    for (int q = 0; q < TM/4; q++)
                        a4[q].v = *(const float4*)&As[k][ty*TM+q*4];
                    float b[TN];
                    #pragma unroll
                    for (int q = 0; q < TN/4; q++)
                        *(float4*)(b+q*4) = *(const float4*)&Bs[k][tx*TN+q*4];
                    unsigned long long bd[TN];
                    #pragma unroll
                    for (int j = 0; j < TN; j++) bd[j] = dup2(b[j]);
                    #pragma unroll
                    for (int i2 = 0; i2 < TM/2; i2++)
                        #pragma unroll
                        for (int j = 0; j < TN; j++)
                            acc2[i2][j] = ffma2(a4[i2>>1].u[i2&1], bd[j], acc2[i2][j]);
                }
                __syncthreads();
            }
        }
    }

    float bv[TN];
    #pragma unroll
    for (int j = 0; j < TN; j++) bv[j] = bias[tx*TN+j];
    #pragma unroll
    for (int i2 = 0; i2 < TM/2; i2++) {
        #pragma unroll
        for (int p = 0; p < 2; p++) {
            int m = ty*TM + i2*2 + p;
            float o[TN];
            #pragma unroll
            for (int j = 0; j < TN; j++) {
                F2S s; s.u = acc2[i2][j];
                o[j] = fmaxf(s.f[p] + bv[j], 0.f);
            }
            size_t base;
            if (TOUT) base = ((size_t)(t0+m)*BF + bf)*COUT + tx*TN;
            else      base = (((size_t)bf*NT + (t0+m))*WOUT + wo)*COUT + tx*TN;
            #pragma unroll
            for (int q = 0; q < TN/4; q++)
                *(float4*)(out + base + q*4) = *(float4*)(o + q*4);
        }
    }
}

// ---------------------------------------------------------------------------
// Input-projection GEMM with f32x2: G[dir][m][g] = X[m][:] @ W[g][:] + bias
// M=65536, N=512, K=128.  BM=BN=128, BK=16, 8x8 per thread, 256 threads.
// ---------------------------------------------------------------------------
__global__ void gemm_xw_k(const float* __restrict__ X,
                          const float* __restrict__ Wf, const float* __restrict__ Wb,
                          const float* __restrict__ bihf, const float* __restrict__ bhhf,
                          const float* __restrict__ bihb, const float* __restrict__ bhhb)
{
    const int dir = blockIdx.z;
    const float* W  = dir ? Wb   : Wf;
    const float* b1 = dir ? bihb : bihf;
    const float* b2 = dir ? bhhb : bhhf;
    float* out = g_G + (size_t)dir*65536*512;

    __shared__ __align__(16) float As[16][132];
    __shared__ __align__(16) float Bs[16][132];
    const int tid = threadIdx.x;
    const int tx = tid & 15, ty = tid >> 4;
    const int m0 = blockIdx.y * 128, n0 = blockIdx.x * 128;

    unsigned long long acc2[4][8];
    #pragma unroll
    for (int i = 0; i < 4; i++) {
        #pragma unroll
        for (int j = 0; j < 8; j++) acc2[i][j] = 0ull;
    }

    for (int kt = 0; kt < 128; kt += 16) {
        #pragma unroll
        for (int i = 0; i < 2; i++) {
            int l = tid*2 + i;
            int row = l >> 2, kq = l & 3;
            float4 v = *(const float4*)(X + (size_t)(m0+row)*128 + kt + kq*4);
            As[kq*4+0][row]=v.x; As[kq*4+1][row]=v.y; As[kq*4+2][row]=v.z; As[kq*4+3][row]=v.w;
            float4 u = *(const float4*)(W + (size_t)(n0+row)*128 + kt + kq*4);
            Bs[kq*4+0][row]=u.x; Bs[kq*4+1][row]=u.y; Bs[kq*4+2][row]=u.z; Bs[kq*4+3][row]=u.w;
        }
        __syncthreads();
        #pragma unroll
        for (int k = 0; k < 16; k++) {
            F2U a0, a1;
            a0.v = *(const float4*)&As[k][ty*8];
            a1.v = *(const float4*)&As[k][ty*8+4];
            float b[8];
            *(float4*)(b  ) = *(const float4*)&Bs[k][tx*8];
            *(float4*)(b+4) = *(const float4*)&Bs[k][tx*8+4];
            unsigned long long bd[8];
            #pragma unroll
            for (int j = 0; j < 8; j++) bd[j] = dup2(b[j]);
            #pragma unroll
            for (int j = 0; j < 8; j++) {
                acc2[0][j] = ffma2(a0.u[0], bd[j], acc2[0][j]);
                acc2[1][j] = ffma2(a0.u[1], bd[j], acc2[1][j]);
                acc2[2][j] = ffma2(a1.u[0], bd[j], acc2[2][j]);
                acc2[3][j] = ffma2(a1.u[1], bd[j], acc2[3][j]);
            }
        }
        __syncthreads();
    }
    #pragma unroll
    for (int j = 0; j < 8; j++) {
        int g = n0 + tx*8 + j;
        float bv = b1[g] + b2[g];
        #pragma unroll
        for (int i2 = 0; i2 < 4; i2++) {
            F2S s; s.u = acc2[i2][j];
            out[(size_t)(m0 + ty*8 + i2*2    )*512 + g] = s.f[0] + bv;
            out[(size_t)(m0 + ty*8 + i2*2 + 1)*512 + g] = s.f[1] + bv;
        }
    }
}

// ---------------------------------------------------------------------------
// LSTM recurrence, phase-split. Cluster of 2 CTAs; 256 threads each.
// Phase A: thread (gt=tid>>6, j=tid&63) owns ONE gate row; weights read once
// per step; h loads are warp-broadcast. Phase B: gate-combine via smem,
// state update, h exchanged via DSMEM.
// ---------------------------------------------------------------------------
__device__ __forceinline__ float sigf(float x) { return 1.f / (1.f + expf(-x)); }

__global__ void __cluster_dims__(2,1,1) __launch_bounds__(256,1)
lstm_k(const float* __restrict__ Whhf, const float* __restrict__ Whhb)
{
    extern __shared__ float sm[];
    float* whh  = sm;                    // [4][64][132]
    float* hbuf = sm + 4*64*132;         // [2][8][132]
    float* gsm  = hbuf + 2*8*132;        // [4][8][64]
    const int tid  = threadIdx.x;
    const int rank = blockIdx.x & 1;
    const int dir  = blockIdx.z;
    const int nb0  = blockIdx.y * 8;
    const float* Whh = dir ? Whhb : Whhf;
    const float* G   = g_G + (size_t)dir*65536*512;

    for (int idx = tid; idx < 4*64*128; idx += 256) {
        int g = idx >> 13;
        int r = (idx >> 7) & 63;
        int k = idx & 127;
        whh[(g*64 + r)*132 + k] = Whh[((size_t)(g*128 + rank*64 + r))*128 + k];
    }
    for (int idx = tid; idx < 2*8*132; idx += 256) hbuf[idx] = 0.f;

    uint32_t hbuf_u32;
    { uint64_t tmp;
      asm("cvta.to.shared.u64 %0, %1;" : "=l"(tmp) : "l"(hbuf));
      hbuf_u32 = (uint32_t)tmp; }

    asm volatile("barrier.cluster.arrive.aligned;\n\tbarrier.cluster.wait.aligned;" ::: "memory");

    const int j    = tid & 63;
    const int gt   = tid >> 6;   // phase-A gate index
    const int np   = tid >> 6;   // phase-B n-pair index
    const int gcol = rank*64 + j;
    const int peer = rank ^ 1;
    float c[2] = {0.f, 0.f};
    const float* wrow = whh + (gt*64 + j)*132;

    // G double-buffered prefetch
    float Gc[8], Gn[8];
    {
        int t0 = dir ? 255 : 0;
        #pragma unroll
        for (int h2 = 0; h2 < 2; h2++)
            #pragma unroll
            for (int g = 0; g < 4; g++)
                Gc[h2*4+g] = G[((size_t)t0*256 + nb0 + np*2 + h2)*512 + g*128 + gcol];
    }

    for (int s = 0; s < 256; s++) {
        const int t   = dir ? (255 - s) : s;
        const int cur = s & 1, nxt = cur ^ 1;

        // ---- phase A: recurrent dot products (one gate row per thread) ----
        unsigned long long acc2[8];
        #pragma unroll
        for (int n = 0; n < 8; n++) acc2[n] = 0ull;
        const float* hb = hbuf + cur*8*132;
        #pragma unroll 4
        for (int k4 = 0; k4 < 32; k4++) {
            F2U w4;
            w4.v = *(const float4*)(wrow + k4*4);
            #pragma unroll
            for (int n = 0; n < 8; n++) {
                F2U h4;
                h4.v = *(const float4*)(hb + n*132 + k4*4);
                acc2[n] = ffma2(w4.u[0], h4.u[0], acc2[n]);
                acc2[n] = ffma2(w4.u[1], h4.u[1], acc2[n]);
            }
        }
        #pragma unroll
        for (int n = 0; n < 8; n++) {
            F2S s2; s2.u = acc2[n];
            gsm[(gt*8 + n)*64 + j] = s2.f[0] + s2.f[1];
        }
        __syncthreads();

        // prefetch next step's G (overlaps with phase B + barrier)
        if (s < 255) {
            int tn = dir ? (254 - s) : (s + 1);
            #pragma unroll
            for (int h2 = 0; h2 < 2; h2++)
                #pragma unroll
                for (int g = 0; g < 4; g++)
                    Gn[h2*4+g] = G[((size_t)tn*256 + nb0 + np*2 + h2)*512 + g*128 + gcol];
        }

        // ---- phase B: gate combine + state update (2 n per thread) ----
        #pragma unroll
        for (int h2 = 0; h2 < 2; h2++) {
            int n = np*2 + h2;
            float ai = gsm[(0*8+n)*64+j] + Gc[h2*4+0];
            float af = gsm[(1*8+n)*64+j] + Gc[h2*4+1];
            float ag = gsm[(2*8+n)*64+j] + Gc[h2*4+2];
            float ao = gsm[(3*8+n)*64+j] + Gc[h2*4+3];
            float iv = sigf(ai);
            float fv = sigf(af);
            float gv = tanhf(ag);
            float ov = sigf(ao);
            c[h2] = fv*c[h2] + iv*gv;
            float hv = ov * tanhf(c[h2]);
            g_hcat[(size_t)(nb0+n)*65536 + t*256 + dir*128 + gcol] = hv;
            int off = (nxt*8 + n)*132 + gcol;
            hbuf[off] = hv;
            uint32_t raddr;
            asm volatile("mapa.shared::cluster.u32 %0, %1, %2;"
                         : "=r"(raddr) : "r"(hbuf_u32 + (uint32_t)off*4u), "r"(peer));
            asm volatile("st.shared::cluster.f32 [%0], %1;" :: "r"(raddr), "f"(hv) : "memory");
        }
        #pragma unroll
        for (int q = 0; q < 8; q++) Gc[q] = Gn[q];
        asm volatile("barrier.cluster.arrive.aligned;\n\tbarrier.cluster.wait.aligned;" ::: "memory");
    }
}

// ---------------------------------------------------------------------------
// FC1 split-K partials with f32x2: z1pre[m][h] = hcat[m][:] @ fc1_w[h][:]
// ---------------------------------------------------------------------------
__global__ void fc1_part_k(const float* __restrict__ fw)
{
    __shared__ __align__(16) float As[16][68];
    __shared__ __align__(16) float Bs[16][132];
    const int tid = threadIdx.x;
    const int tx = tid & 15, ty = tid >> 4;
    const int m0 = blockIdx.x * 64;
    const int k0 = blockIdx.y * 1024;

    unsigned long long acc2[2][8];
    #pragma unroll
    for (int i = 0; i < 2; i++) {
        #pragma unroll
        for (int j = 0; j < 8; j++) acc2[i][j] = 0ull;
    }

    for (int kt = 0; kt < 1024; kt += 16) {
        {
            int l = tid;
            int row = l >> 2, kq = l & 3;
            float4 v = *(const float4*)(g_hcat + (size_t)(m0+row)*65536 + k0 + kt + kq*4);
            As[kq*4+0][row]=v.x; As[kq*4+1][row]=v.y; As[kq*4+2][row]=v.z; As[kq*4+3][row]=v.w;
        }
        #pragma unroll
        for (int i = 0; i < 2; i++) {
            int l = tid*2 + i;
            int row = l >> 2, kq = l & 3;
            float4 u = *(const float4*)(fw + (size_t)row*65536 + k0 + kt + kq*4);
            Bs[kq*4+0][row]=u.x; Bs[kq*4+1][row]=u.y; Bs[kq*4+2][row]=u.z; Bs[kq*4+3][row]=u.w;
        }
        __syncthreads();
        #pragma unroll
        for (int k = 0; k < 16; k++) {
            F2U a0;
            a0.v = *(const float4*)&As[k][ty*4];
            float b[8];
            *(float4*)(b  ) = *(const float4*)&Bs[k][tx*8];
            *(float4*)(b+4) = *(const float4*)&Bs[k][tx*8+4];
            #pragma unroll
            for (int j = 0; j < 8; j++) {
                unsigned long long bd = dup2(b[j]);
                acc2[0][j] = ffma2(a0.u[0], bd, acc2[0][j]);
                acc2[1][j] = ffma2(a0.u[1], bd, acc2[1][j]);
            }
        }
        __syncthreads();
    }
    #pragma unroll
    for (int i2 = 0; i2 < 2; i2++)
        #pragma unroll
        for (int jj = 0; jj < 8; jj++) {
            F2S s; s.u = acc2[i2][jj];
            g_fc1part[((size_t)blockIdx.y*256 + m0 + ty*4 + i2*2    )*128 + tx*8 + jj] = s.f[0];
            g_fc1part[((size_t)blockIdx.y*256 + m0 + ty*4 + i2*2 + 1)*128 + tx*8 + jj] = s.f[1];
        }
}

__global__ void fc1_reduce_k(const float* __restrict__ fc1b)
{
    int idx = blockIdx.x*256 + threadIdx.x;
    int m = idx >> 7, h = idx & 127;
    float s = fc1b[h];
    #pragma unroll 8
    for (int kc = 0; kc < 64; kc++)
        s += g_fc1part[((size_t)kc*256 + m)*128 + h];
    g_z1[(size_t)m*128 + h] = fmaxf(s, 0.f);
}

__global__ void score_k(const float* __restrict__ fsw, const float* __restrict__ fsb,
                        float* __restrict__ out)
{
    __shared__ float w[128];
    __shared__ float fr[256];
    int tid = threadIdx.x;
    if (tid < 128) w[tid] = fsw[tid];
    __syncthreads();
    float acc = fsb[0];
    #pragma unroll 8
    for (int h = 0; h < 128; h++) acc += g_z1[(size_t)tid*128 + h] * w[h];
    float sc = 1.f / (1.f + expf(-acc)) * 4.f + 1.f;
    out[16 + tid] = sc;
    fr[tid] = sc;
    __syncthreads();
    if (tid < 16) {
        float s = 0.f;
        #pragma unroll
        for (int f = 0; f < 16; f++) s += fr[tid*16 + f];
        out[tid] = s * (1.f/16.f);
    }
}

// ---------------------------------------------------------------------------
extern "C" void kernel_launch(void* const* d_in, const int* in_sizes, int n_in,
                              void* d_out, int out_size)
{
    const float *audio,*w0,*b0,*w1,*b1,*w2,*b2,*w3,*b3;
    const float *Wihf,*Whhf,*bihf,*bhhf,*Wihb,*Whhb,*bihb,*bhhb;
    const float *fc1w,*fc1b,*fsw,*fsb;
    if (n_in >= 22 && in_sizes[1] == 144) {
        audio=(const float*)d_in[0];
        w0=(const float*)d_in[1];  b0=(const float*)d_in[2];
        w1=(const float*)d_in[3];  b1=(const float*)d_in[4];
        w2=(const float*)d_in[5];  b2=(const float*)d_in[6];
        w3=(const float*)d_in[7];  b3=(const float*)d_in[8];
        Wihf=(const float*)d_in[9];  Whhf=(const float*)d_in[10];
        bihf=(const float*)d_in[11]; bhhf=(const float*)d_in[12];
        Wihb=(const float*)d_in[13]; Whhb=(const float*)d_in[14];
        bihb=(const float*)d_in[15]; bhhb=(const float*)d_in[16];
        fc1w=(const float*)d_in[17]; fc1b=(const float*)d_in[18];
        fsw=(const float*)d_in[19];  fsb=(const float*)d_in[20];
    } else {
        audio=(const float*)d_in[0];
        w0=(const float*)d_in[2];  b0=(const float*)d_in[3];
        w1=(const float*)d_in[4];  b1=(const float*)d_in[5];
        w2=(const float*)d_in[6];  b2=(const float*)d_in[7];
        w3=(const float*)d_in[8];  b3=(const float*)d_in[9];
        Wihf=(const float*)d_in[10]; Whhf=(const float*)d_in[11];
        bihf=(const float*)d_in[12]; bhhf=(const float*)d_in[13];
        Wihb=(const float*)d_in[14]; Whhb=(const float*)d_in[15];
        bihb=(const float*)d_in[16]; bhhb=(const float*)d_in[17];
        fc1w=(const float*)d_in[18]; fc1b=(const float*)d_in[19];
        fsw=(const float*)d_in[20];  fsb=(const float*)d_in[21];
    }

    float *x0,*x1,*x2,*xT,*wT1,*wT2,*wT3;
    cudaGetSymbolAddress((void**)&x0, g_x0);
    cudaGetSymbolAddress((void**)&x1, g_x1);
    cudaGetSymbolAddress((void**)&x2, g_x2);
    cudaGetSymbolAddress((void**)&xT, g_xT);
    cudaGetSymbolAddress((void**)&wT1, g_wT1);
    cudaGetSymbolAddress((void**)&wT2, g_wT2);
    cudaGetSymbolAddress((void**)&wT3, g_wT3);

    const int sl = (4*64*132 + 2*8*132 + 4*8*64)*4;   // ~148.3 KB
    cudaFuncSetAttribute(lstm_k, cudaFuncAttributeMaxDynamicSharedMemorySize, sl);

    // weight transforms (tiny)
    wtrans_k<<<(9*16*32 + 255)/256, 256>>>(w1, wT1, 16, 32);
    wtrans_k<<<(9*32*64 + 255)/256, 256>>>(w2, wT2, 32, 64);
    wtrans_k<<<(9*64*128+ 255)/256, 256>>>(w3, wT3, 64, 128);

    // conv stack (NHWC)
    conv0_k<<<(BF*NT*27)/256, 256>>>(audio, w0, b0, x0);
    conv_igemm_k<16, 32,27,9,4,4,false><<<dim3(2,9,BF), 256>>>(x0, wT1, b1, x1);
    conv_igemm_k<32, 64, 9,3,8,4,false><<<dim3(2,3,BF), 256>>>(x1, wT2, b2, x2);
    conv_igemm_k<64,128, 3,1,8,8,true ><<<dim3(2,1,BF), 256>>>(x2, wT3, b3, xT);

    gemm_xw_k<<<dim3(4,512,2), 256>>>(xT, Wihf, Wihb, bihf, bhhf, bihb, bhhb);

    lstm_k<<<dim3(2,32,2), 256, sl>>>(Whhf, Whhb);

    fc1_part_k<<<dim3(4,64), 256>>>(fc1w);
    fc1_reduce_k<<<128, 256>>>(fc1b);
    score_k<<<1, 256>>>(fsw, fsb, (float*)d_out);
}

// round 6
// speedup vs baseline: 2.3874x; 1.4595x over previous
#include <cuda_runtime.h>
#include <cstdint>
#include <math.h>

// ---------------------------------------------------------------------------
// Static scratch (no allocations allowed)
// ---------------------------------------------------------------------------
#define BF 256          // B*F = 16*16 frame windows
#define NT 256          // frames per window (time)
__device__ __align__(16) float g_x0[(size_t)BF*NT*27*16];    // conv0 out NHWC
__device__ __align__(16) float g_x1[(size_t)BF*NT*9*32];     // conv1 out NHWC
__device__ __align__(16) float g_x2[(size_t)BF*NT*3*64];     // conv2 out NHWC
__device__ __align__(16) float g_xT[(size_t)NT*BF*128];      // conv3 out, [t][n][c]
__device__ __align__(16) float g_G[(size_t)2*65536*512];     // x@Wih.T + bias, per dir
__device__ __align__(16) float g_hcat[(size_t)BF*65536];     // [n][t*256 + dir*128 + j]
__device__ __align__(16) float g_fc1part[(size_t)64*256*128];// split-K partials
__device__ __align__(16) float g_z1[(size_t)256*128];        // relu(fc1)
__device__ __align__(16) float g_wT1[9*32*16];               // conv1 weights [tap][co][ci]
__device__ __align__(16) float g_wT2[9*64*32];
__device__ __align__(16) float g_wT3[9*128*64];

// ---------------------------------------------------------------------------
// helpers: f32x2 FMA (lstm/fc1), tf32 mma (convs/gemm)
// ---------------------------------------------------------------------------
union F2U { float4 v; unsigned long long u[2]; };
union F2S { unsigned long long u; float f[2]; };

__device__ __forceinline__ unsigned long long ffma2(unsigned long long a,
                                                    unsigned long long b,
                                                    unsigned long long c)
{
    unsigned long long d;
    asm("fma.rn.f32x2 %0, %1, %2, %3;" : "=l"(d) : "l"(a), "l"(b), "l"(c));
    return d;
}
__device__ __forceinline__ unsigned long long dup2(float x)
{
    unsigned long long r;
    asm("mov.b64 %0, {%1, %1};" : "=l"(r) : "f"(x));
    return r;
}
__device__ __forceinline__ uint32_t f2tf(float f)
{
    uint32_t r;
    asm("cvt.rna.tf32.f32 %0, %1;" : "=r"(r) : "f"(f));
    return r;
}
__device__ __forceinline__ void mma_tf32(float* d, const uint32_t* a, const uint32_t* b)
{
    asm("mma.sync.aligned.m16n8k8.row.col.f32.tf32.tf32.f32 "
        "{%0,%1,%2,%3}, {%4,%5,%6,%7}, {%8,%9}, {%0,%1,%2,%3};"
        : "+f"(d[0]), "+f"(d[1]), "+f"(d[2]), "+f"(d[3])
        : "r"(a[0]), "r"(a[1]), "r"(a[2]), "r"(a[3]), "r"(b[0]), "r"(b[1]));
}

// ---------------------------------------------------------------------------
// Weight transform: w[co][ci][kh][kw] -> wT[tap][co][ci]
// ---------------------------------------------------------------------------
__global__ void wtrans_k(const float* __restrict__ w, float* __restrict__ wT,
                         int CIN, int COUT)
{
    int idx = blockIdx.x*256 + threadIdx.x;
    int total = 9*CIN*COUT;
    if (idx >= total) return;
    int ci  = idx % CIN;
    int r   = idx / CIN;
    int co  = r % COUT;
    int tap = r / COUT;
    wT[idx] = w[(co*CIN + ci)*9 + tap];
}

// ---------------------------------------------------------------------------
// conv0: CIN=1 -> 16, direct (memory bound). out NHWC [bf][t][27][16].
// ---------------------------------------------------------------------------
__global__ void conv0_k(const float* __restrict__ audio, const float* __restrict__ w,
                        const float* __restrict__ bias, float* __restrict__ out)
{
    __shared__ float wsm[9][16];
    __shared__ float bsm[16];
    int tid = threadIdx.x;
    if (tid < 144) wsm[tid % 9][tid / 9] = w[tid];
    if (tid < 16)  bsm[tid] = bias[tid];
    __syncthreads();

    size_t idx = (size_t)blockIdx.x*256 + tid;   // (bf, t, wo)
    int wo = (int)(idx % 27);
    size_t r = idx / 27;
    int t  = (int)(r % NT);
    int bf = (int)(r / NT);

    float acc[16];
    #pragma unroll
    for (int co = 0; co < 16; co++) acc[co] = bsm[co];

    #pragma unroll
    for (int kh = 0; kh < 3; kh++) {
        int ti = t + kh - 1;
        if (ti < 0 || ti >= NT) continue;
        #pragma unroll
        for (int kw = 0; kw < 3; kw++) {
            int wc = 3*wo + kw - 1;
            if (wc < 0 || wc >= 81) continue;
            float v = audio[((size_t)bf*NT + ti)*81 + wc];
            #pragma unroll
            for (int co = 0; co < 16; co++) acc[co] += v * wsm[kh*3+kw][co];
        }
    }
    float* o = out + idx*16;
    #pragma unroll
    for (int q = 0; q < 4; q++) {
        float4 v;
        v.x = fmaxf(acc[q*4+0], 0.f); v.y = fmaxf(acc[q*4+1], 0.f);
        v.z = fmaxf(acc[q*4+2], 0.f); v.w = fmaxf(acc[q*4+3], 0.f);
        *(float4*)(o + q*4) = v;
    }
}

// ---------------------------------------------------------------------------
// Implicit-GEMM conv with tf32 mma. Block = (t-tile 128, wo, bf).
// A: [128 t][CIN ci] per tap (halo-shifted); B: wT[tap][co][ci].
// 8 warps: NWN = COUT/32 warps along n, WMW = 8/NWN along m.
// ---------------------------------------------------------------------------
template<int CIN,int COUT,int WIN,int WOUT,bool TOUT>
__global__ void conv_mma_k(const float* __restrict__ x, const float* __restrict__ wT,
                           const float* __restrict__ bias, float* __restrict__ out)
{
    constexpr int NWN = COUT/32;         // warps along n
    constexpr int WMW = 8/NWN;           // warps along m
    constexpr int MFR = 128/WMW/16;      // m-frags per warp
    constexpr int LDA = CIN + 4;
    extern __shared__ uint32_t dynsm[];
    uint32_t* As = dynsm;                // [128][LDA]
    uint32_t* Bs = dynsm + 128*LDA;      // [COUT][LDA]

    const int tid  = threadIdx.x;
    const int lane = tid & 31;
    const int wid  = tid >> 5;
    const int g    = lane >> 2, tq = lane & 3;
    const int wm0  = (wid % WMW) * (128/WMW);
    const int wn0  = (wid / WMW) * 32;
    const int t0   = blockIdx.x * 128;
    const int wo   = blockIdx.y;
    const int bf   = blockIdx.z;

    float acc[MFR][4][4];
    #pragma unroll
    for (int i = 0; i < MFR; i++)
        #pragma unroll
        for (int j = 0; j < 4; j++)
            #pragma unroll
            for (int q = 0; q < 4; q++) acc[i][j][q] = 0.f;

    #pragma unroll
    for (int kh = 0; kh < 3; kh++) {
        #pragma unroll
        for (int kw = 0; kw < 3; kw++) {
            const int wc = 3*wo + kw - 1;
            if (wc < 0 || wc >= WIN) continue;
            const int tap = kh*3 + kw;
            // fill A (128 x CIN), halo shift kh-1
            for (int l = tid; l < 128*(CIN/4); l += 256) {
                int m = l / (CIN/4), kq = l % (CIN/4);
                int t_in = t0 + m + kh - 1;
                float4 v = make_float4(0.f,0.f,0.f,0.f);
                if (t_in >= 0 && t_in < NT)
                    v = *(const float4*)(x + (((size_t)bf*NT + t_in)*WIN + wc)*CIN + kq*4);
                uint32_t* a = As + m*LDA + kq*4;
                a[0]=f2tf(v.x); a[1]=f2tf(v.y); a[2]=f2tf(v.z); a[3]=f2tf(v.w);
            }
            // fill B (COUT x CIN), coalesced
            const float* wtap = wT + (size_t)tap*COUT*CIN;
            for (int l = tid; l < COUT*(CIN/4); l += 256) {
                int co = l / (CIN/4), kq = l % (CIN/4);
                float4 v = *(const float4*)(wtap + co*CIN + kq*4);
                uint32_t* b = Bs + co*LDA + kq*4;
                b[0]=f2tf(v.x); b[1]=f2tf(v.y); b[2]=f2tf(v.z); b[3]=f2tf(v.w);
            }
            __syncthreads();
            #pragma unroll
            for (int k8 = 0; k8 < CIN; k8 += 8) {
                uint32_t a[MFR][4], b[4][2];
                #pragma unroll
                for (int fi = 0; fi < MFR; fi++) {
                    int r = wm0 + fi*16;
                    a[fi][0] = As[(r+g  )*LDA + k8 + tq];
                    a[fi][1] = As[(r+g+8)*LDA + k8 + tq];
                    a[fi][2] = As[(r+g  )*LDA + k8 + tq + 4];
                    a[fi][3] = As[(r+g+8)*LDA + k8 + tq + 4];
                }
                #pragma unroll
                for (int fj = 0; fj < 4; fj++) {
                    int cn = wn0 + fj*8 + g;
                    b[fj][0] = Bs[cn*LDA + k8 + tq];
                    b[fj][1] = Bs[cn*LDA + k8 + tq + 4];
                }
                #pragma unroll
                for (int fi = 0; fi < MFR; fi++)
                    #pragma unroll
                    for (int fj = 0; fj < 4; fj++)
                        mma_tf32(acc[fi][fj], a[fi], b[fj]);
            }
            __syncthreads();
        }
    }

    // epilogue: bias + relu
    #pragma unroll
    for (int fj = 0; fj < 4; fj++) {
        int co0 = wn0 + fj*8 + 2*tq;
        float bv0 = bias[co0], bv1 = bias[co0+1];
        #pragma unroll
        for (int fi = 0; fi < MFR; fi++) {
            #pragma unroll
            for (int p = 0; p < 2; p++) {
                int m = wm0 + fi*16 + g + p*8;
                float2 v;
                v.x = fmaxf(acc[fi][fj][p*2+0] + bv0, 0.f);
                v.y = fmaxf(acc[fi][fj][p*2+1] + bv1, 0.f);
                size_t base;
                if (TOUT) base = ((size_t)(t0+m)*BF + bf)*COUT + co0;
                else      base = (((size_t)bf*NT + (t0+m))*WOUT + wo)*COUT + co0;
                *(float2*)(out + base) = v;
            }
        }
    }
}

// ---------------------------------------------------------------------------
// Input-projection GEMM, tf32 mma: G[dir][m][g] = X[m][:] @ W[g][:] + bias
// M=65536, N=512, K=128. BM=BN=128, BK=32. 8 warps (2m x 4n).
// ---------------------------------------------------------------------------
__global__ void gemm_xw_k(const float* __restrict__ X,
                          const float* __restrict__ Wf, const float* __restrict__ Wb,
                          const float* __restrict__ bihf, const float* __restrict__ bhhf,
                          const float* __restrict__ bihb, const float* __restrict__ bhhb)
{
    const int dir = blockIdx.z;
    const float* W  = dir ? Wb   : Wf;
    const float* b1 = dir ? bihb : bihf;
    const float* b2 = dir ? bhhb : bhhf;
    float* out = g_G + (size_t)dir*65536*512;

    __shared__ uint32_t As[128][36];   // [m][k] tf32
    __shared__ uint32_t Bs[128][36];   // [n][k] tf32

    const int tid  = threadIdx.x;
    const int lane = tid & 31;
    const int wid  = tid >> 5;
    const int g    = lane >> 2, tq = lane & 3;
    const int wm0  = (wid & 1) * 64;
    const int wn0  = (wid >> 1) * 32;
    const int m0   = blockIdx.y * 128, n0 = blockIdx.x * 128;

    float acc[4][4][4];
    #pragma unroll
    for (int i = 0; i < 4; i++)
        #pragma unroll
        for (int j = 0; j < 4; j++)
            #pragma unroll
            for (int q = 0; q < 4; q++) acc[i][j][q] = 0.f;

    for (int kt = 0; kt < 128; kt += 32) {
        #pragma unroll
        for (int i = 0; i < 4; i++) {
            int l = i*256 + tid;
            int m = l >> 3, kq = l & 7;
            float4 v = *(const float4*)(X + (size_t)(m0+m)*128 + kt + kq*4);
            As[m][kq*4+0]=f2tf(v.x); As[m][kq*4+1]=f2tf(v.y);
            As[m][kq*4+2]=f2tf(v.z); As[m][kq*4+3]=f2tf(v.w);
            float4 u = *(const float4*)(W + (size_t)(n0+m)*128 + kt + kq*4);
            Bs[m][kq*4+0]=f2tf(u.x); Bs[m][kq*4+1]=f2tf(u.y);
            Bs[m][kq*4+2]=f2tf(u.z); Bs[m][kq*4+3]=f2tf(u.w);
        }
        __syncthreads();
        #pragma unroll
        for (int k8 = 0; k8 < 32; k8 += 8) {
            uint32_t a[4][4], b[4][2];
            #pragma unroll
            for (int fi = 0; fi < 4; fi++) {
                int r = wm0 + fi*16;
                a[fi][0] = As[r+g  ][k8+tq];
                a[fi][1] = As[r+g+8][k8+tq];
                a[fi][2] = As[r+g  ][k8+tq+4];
                a[fi][3] = As[r+g+8][k8+tq+4];
            }
            #pragma unroll
            for (int fj = 0; fj < 4; fj++) {
                int cn = wn0 + fj*8 + g;
                b[fj][0] = Bs[cn][k8+tq];
                b[fj][1] = Bs[cn][k8+tq+4];
            }
            #pragma unroll
            for (int fi = 0; fi < 4; fi++)
                #pragma unroll
                for (int fj = 0; fj < 4; fj++)
                    mma_tf32(acc[fi][fj], a[fi], b[fj]);
        }
        __syncthreads();
    }

    #pragma unroll
    for (int fj = 0; fj < 4; fj++) {
        int gate0 = n0 + wn0 + fj*8 + 2*tq;
        float bv0 = b1[gate0]   + b2[gate0];
        float bv1 = b1[gate0+1] + b2[gate0+1];
        #pragma unroll
        for (int fi = 0; fi < 4; fi++) {
            #pragma unroll
            for (int p = 0; p < 2; p++) {
                int m = m0 + wm0 + fi*16 + g + p*8;
                float2 v;
                v.x = acc[fi][fj][p*2+0] + bv0;
                v.y = acc[fi][fj][p*2+1] + bv1;
                *(float2*)(out + (size_t)m*512 + gate0) = v;
            }
        }
    }
}

// ---------------------------------------------------------------------------
// LSTM recurrence, phase-split (unchanged from R5).
// ---------------------------------------------------------------------------
__device__ __forceinline__ float sigf(float x) { return 1.f / (1.f + expf(-x)); }

__global__ void __cluster_dims__(2,1,1) __launch_bounds__(256,1)
lstm_k(const float* __restrict__ Whhf, const float* __restrict__ Whhb)
{
    extern __shared__ float sm[];
    float* whh  = sm;                    // [4][64][132]
    float* hbuf = sm + 4*64*132;         // [2][8][132]
    float* gsm  = hbuf + 2*8*132;        // [4][8][64]
    const int tid  = threadIdx.x;
    const int rank = blockIdx.x & 1;
    const int dir  = blockIdx.z;
    const int nb0  = blockIdx.y * 8;
    const float* Whh = dir ? Whhb : Whhf;
    const float* G   = g_G + (size_t)dir*65536*512;

    for (int idx = tid; idx < 4*64*128; idx += 256) {
        int g = idx >> 13;
        int r = (idx >> 7) & 63;
        int k = idx & 127;
        whh[(g*64 + r)*132 + k] = Whh[((size_t)(g*128 + rank*64 + r))*128 + k];
    }
    for (int idx = tid; idx < 2*8*132; idx += 256) hbuf[idx] = 0.f;

    uint32_t hbuf_u32;
    { uint64_t tmp;
      asm("cvta.to.shared.u64 %0, %1;" : "=l"(tmp) : "l"(hbuf));
      hbuf_u32 = (uint32_t)tmp; }

    asm volatile("barrier.cluster.arrive.aligned;\n\tbarrier.cluster.wait.aligned;" ::: "memory");

    const int j    = tid & 63;
    const int gt   = tid >> 6;
    const int np   = tid >> 6;
    const int gcol = rank*64 + j;
    const int peer = rank ^ 1;
    float c[2] = {0.f, 0.f};
    const float* wrow = whh + (gt*64 + j)*132;

    float Gc[8], Gn[8];
    {
        int t0 = dir ? 255 : 0;
        #pragma unroll
        for (int h2 = 0; h2 < 2; h2++)
            #pragma unroll
            for (int g = 0; g < 4; g++)
                Gc[h2*4+g] = G[((size_t)t0*256 + nb0 + np*2 + h2)*512 + g*128 + gcol];
    }

    for (int s = 0; s < 256; s++) {
        const int t   = dir ? (255 - s) : s;
        const int cur = s & 1, nxt = cur ^ 1;

        unsigned long long acc2[8];
        #pragma unroll
        for (int n = 0; n < 8; n++) acc2[n] = 0ull;
        const float* hb = hbuf + cur*8*132;
        #pragma unroll 4
        for (int k4 = 0; k4 < 32; k4++) {
            F2U w4;
            w4.v = *(const float4*)(wrow + k4*4);
            #pragma unroll
            for (int n = 0; n < 8; n++) {
                F2U h4;
                h4.v = *(const float4*)(hb + n*132 + k4*4);
                acc2[n] = ffma2(w4.u[0], h4.u[0], acc2[n]);
                acc2[n] = ffma2(w4.u[1], h4.u[1], acc2[n]);
            }
        }
        #pragma unroll
        for (int n = 0; n < 8; n++) {
            F2S s2; s2.u = acc2[n];
            gsm[(gt*8 + n)*64 + j] = s2.f[0] + s2.f[1];
        }
        __syncthreads();

        if (s < 255) {
            int tn = dir ? (254 - s) : (s + 1);
            #pragma unroll
            for (int h2 = 0; h2 < 2; h2++)
                #pragma unroll
                for (int g = 0; g < 4; g++)
                    Gn[h2*4+g] = G[((size_t)tn*256 + nb0 + np*2 + h2)*512 + g*128 + gcol];
        }

        #pragma unroll
        for (int h2 = 0; h2 < 2; h2++) {
            int n = np*2 + h2;
            float ai = gsm[(0*8+n)*64+j] + Gc[h2*4+0];
            float af = gsm[(1*8+n)*64+j] + Gc[h2*4+1];
            float ag = gsm[(2*8+n)*64+j] + Gc[h2*4+2];
            float ao = gsm[(3*8+n)*64+j] + Gc[h2*4+3];
            float iv = sigf(ai);
            float fv = sigf(af);
            float gv = tanhf(ag);
            float ov = sigf(ao);
            c[h2] = fv*c[h2] + iv*gv;
            float hv = ov * tanhf(c[h2]);
            g_hcat[(size_t)(nb0+n)*65536 + t*256 + dir*128 + gcol] = hv;
            int off = (nxt*8 + n)*132 + gcol;
            hbuf[off] = hv;
            uint32_t raddr;
            asm volatile("mapa.shared::cluster.u32 %0, %1, %2;"
                         : "=r"(raddr) : "r"(hbuf_u32 + (uint32_t)off*4u), "r"(peer));
            asm volatile("st.shared::cluster.f32 [%0], %1;" :: "r"(raddr), "f"(hv) : "memory");
        }
        #pragma unroll
        for (int q = 0; q < 8; q++) Gc[q] = Gn[q];
        asm volatile("barrier.cluster.arrive.aligned;\n\tbarrier.cluster.wait.aligned;" ::: "memory");
    }
}

// ---------------------------------------------------------------------------
// FC1 split-K partials with f32x2 (fp32 kept for accuracy on score path)
// ---------------------------------------------------------------------------
__global__ void fc1_part_k(const float* __restrict__ fw)
{
    __shared__ __align__(16) float As[16][68];
    __shared__ __align__(16) float Bs[16][132];
    const int tid = threadIdx.x;
    const int tx = tid & 15, ty = tid >> 4;
    const int m0 = blockIdx.x * 64;
    const int k0 = blockIdx.y * 1024;

    unsigned long long acc2[2][8];
    #pragma unroll
    for (int i = 0; i < 2; i++) {
        #pragma unroll
        for (int j = 0; j < 8; j++) acc2[i][j] = 0ull;
    }

    for (int kt = 0; kt < 1024; kt += 16) {
        {
            int l = tid;
            int row = l >> 2, kq = l & 3;
            float4 v = *(const float4*)(g_hcat + (size_t)(m0+row)*65536 + k0 + kt + kq*4);
            As[kq*4+0][row]=v.x; As[kq*4+1][row]=v.y; As[kq*4+2][row]=v.z; As[kq*4+3][row]=v.w;
        }
        #pragma unroll
        for (int i = 0; i < 2; i++) {
            int l = tid*2 + i;
            int row = l >> 2, kq = l & 3;
            float4 u = *(const float4*)(fw + (size_t)row*65536 + k0 + kt + kq*4);
            Bs[kq*4+0][row]=u.x; Bs[kq*4+1][row]=u.y; Bs[kq*4+2][row]=u.z; Bs[kq*4+3][row]=u.w;
        }
        __syncthreads();
        #pragma unroll
        for (int k = 0; k < 16; k++) {
            F2U a0;
            a0.v = *(const float4*)&As[k][ty*4];
            float b[8];
            *(float4*)(b  ) = *(const float4*)&Bs[k][tx*8];
            *(float4*)(b+4) = *(const float4*)&Bs[k][tx*8+4];
            #pragma unroll
            for (int j = 0; j < 8; j++) {
                unsigned long long bd = dup2(b[j]);
                acc2[0][j] = ffma2(a0.u[0], bd, acc2[0][j]);
                acc2[1][j] = ffma2(a0.u[1], bd, acc2[1][j]);
            }
        }
        __syncthreads();
    }
    #pragma unroll
    for (int i2 = 0; i2 < 2; i2++)
        #pragma unroll
        for (int jj = 0; jj < 8; jj++) {
            F2S s; s.u = acc2[i2][jj];
            g_fc1part[((size_t)blockIdx.y*256 + m0 + ty*4 + i2*2    )*128 + tx*8 + jj] = s.f[0];
            g_fc1part[((size_t)blockIdx.y*256 + m0 + ty*4 + i2*2 + 1)*128 + tx*8 + jj] = s.f[1];
        }
}

__global__ void fc1_reduce_k(const float* __restrict__ fc1b)
{
    int idx = blockIdx.x*256 + threadIdx.x;
    int m = idx >> 7, h = idx & 127;
    float s = fc1b[h];
    #pragma unroll 8
    for (int kc = 0; kc < 64; kc++)
        s += g_fc1part[((size_t)kc*256 + m)*128 + h];
    g_z1[(size_t)m*128 + h] = fmaxf(s, 0.f);
}

__global__ void score_k(const float* __restrict__ fsw, const float* __restrict__ fsb,
                        float* __restrict__ out)
{
    __shared__ float w[128];
    __shared__ float fr[256];
    int tid = threadIdx.x;
    if (tid < 128) w[tid] = fsw[tid];
    __syncthreads();
    float acc = fsb[0];
    #pragma unroll 8
    for (int h = 0; h < 128; h++) acc += g_z1[(size_t)tid*128 + h] * w[h];
    float sc = 1.f / (1.f + expf(-acc)) * 4.f + 1.f;
    out[16 + tid] = sc;
    fr[tid] = sc;
    __syncthreads();
    if (tid < 16) {
        float s = 0.f;
        #pragma unroll
        for (int f = 0; f < 16; f++) s += fr[tid*16 + f];
        out[tid] = s * (1.f/16.f);
    }
}

// ---------------------------------------------------------------------------
extern "C" void kernel_launch(void* const* d_in, const int* in_sizes, int n_in,
                              void* d_out, int out_size)
{
    const float *audio,*w0,*b0,*w1,*b1,*w2,*b2,*w3,*b3;
    const float *Wihf,*Whhf,*bihf,*bhhf,*Wihb,*Whhb,*bihb,*bhhb;
    const float *fc1w,*fc1b,*fsw,*fsb;
    if (n_in >= 22 && in_sizes[1] == 144) {
        audio=(const float*)d_in[0];
        w0=(const float*)d_in[1];  b0=(const float*)d_in[2];
        w1=(const float*)d_in[3];  b1=(const float*)d_in[4];
        w2=(const float*)d_in[5];  b2=(const float*)d_in[6];
        w3=(const float*)d_in[7];  b3=(const float*)d_in[8];
        Wihf=(const float*)d_in[9];  Whhf=(const float*)d_in[10];
        bihf=(const float*)d_in[11]; bhhf=(const float*)d_in[12];
        Wihb=(const float*)d_in[13]; Whhb=(const float*)d_in[14];
        bihb=(const float*)d_in[15]; bhhb=(const float*)d_in[16];
        fc1w=(const float*)d_in[17]; fc1b=(const float*)d_in[18];
        fsw=(const float*)d_in[19];  fsb=(const float*)d_in[20];
    } else {
        audio=(const float*)d_in[0];
        w0=(const float*)d_in[2];  b0=(const float*)d_in[3];
        w1=(const float*)d_in[4];  b1=(const float*)d_in[5];
        w2=(const float*)d_in[6];  b2=(const float*)d_in[7];
        w3=(const float*)d_in[8];  b3=(const float*)d_in[9];
        Wihf=(const float*)d_in[10]; Whhf=(const float*)d_in[11];
        bihf=(const float*)d_in[12]; bhhf=(const float*)d_in[13];
        Wihb=(const float*)d_in[14]; Whhb=(const float*)d_in[15];
        bihb=(const float*)d_in[16]; bhhb=(const float*)d_in[17];
        fc1w=(const float*)d_in[18]; fc1b=(const float*)d_in[19];
        fsw=(const float*)d_in[20];  fsb=(const float*)d_in[21];
    }

    float *x0,*x1,*x2,*xT,*wT1,*wT2,*wT3;
    cudaGetSymbolAddress((void**)&x0, g_x0);
    cudaGetSymbolAddress((void**)&x1, g_x1);
    cudaGetSymbolAddress((void**)&x2, g_x2);
    cudaGetSymbolAddress((void**)&xT, g_xT);
    cudaGetSymbolAddress((void**)&wT1, g_wT1);
    cudaGetSymbolAddress((void**)&wT2, g_wT2);
    cudaGetSymbolAddress((void**)&wT3, g_wT3);

    const int sl = (4*64*132 + 2*8*132 + 4*8*64)*4;   // ~148.3 KB
    cudaFuncSetAttribute(lstm_k, cudaFuncAttributeMaxDynamicSharedMemorySize, sl);
    // conv_mma dynamic smem: (128 + COUT) * (CIN+4) * 4 bytes
    const int sc1 = (128 + 32) * (16 + 4) * 4;   // 12.8 KB
    const int sc2 = (128 + 64) * (32 + 4) * 4;   // 27.6 KB
    const int sc3 = (128 +128) * (64 + 4) * 4;   // 69.6 KB
    cudaFuncSetAttribute(conv_mma_k<16, 32,27,9,false>, cudaFuncAttributeMaxDynamicSharedMemorySize, sc1);
    cudaFuncSetAttribute(conv_mma_k<32, 64, 9,3,false>, cudaFuncAttributeMaxDynamicSharedMemorySize, sc2);
    cudaFuncSetAttribute(conv_mma_k<64,128, 3,1,true >, cudaFuncAttributeMaxDynamicSharedMemorySize, sc3);

    // weight transforms (tiny)
    wtrans_k<<<(9*16*32 + 255)/256, 256>>>(w1, wT1, 16, 32);
    wtrans_k<<<(9*32*64 + 255)/256, 256>>>(w2, wT2, 32, 64);
    wtrans_k<<<(9*64*128+ 255)/256, 256>>>(w3, wT3, 64, 128);

    // conv stack (NHWC)
    conv0_k<<<(BF*NT*27)/256, 256>>>(audio, w0, b0, x0);
    conv_mma_k<16, 32,27,9,false><<<dim3(2,9,BF), 256, sc1>>>(x0, wT1, b1, x1);
    conv_mma_k<32, 64, 9,3,false><<<dim3(2,3,BF), 256, sc2>>>(x1, wT2, b2, x2);
    conv_mma_k<64,128, 3,1,true ><<<dim3(2,1,BF), 256, sc3>>>(x2, wT3, b3, xT);

    gemm_xw_k<<<dim3(4,512,2), 256>>>(xT, Wihf, Wihb, bihf, bhhf, bihb, bhhb);

    lstm_k<<<dim3(2,32,2), 256, sl>>>(Whhf, Whhb);

    fc1_part_k<<<dim3(4,64), 256>>>(fc1w);
    fc1_reduce_k<<<128, 256>>>(fc1b);
    score_k<<<1, 256>>>(fsw, fsb, (float*)d_out);
}

// round 7
// speedup vs baseline: 2.7780x; 1.1636x over previous
#include <cuda_runtime.h>
#include <cstdint>
#include <math.h>

// ---------------------------------------------------------------------------
// Static scratch (no allocations allowed)
// ---------------------------------------------------------------------------
#define BF 256          // B*F = 16*16 frame windows
#define NT 256          // frames per window (time)
__device__ __align__(16) float g_x0[(size_t)BF*NT*27*16];    // conv0 out NHWC
__device__ __align__(16) float g_x1[(size_t)BF*NT*9*32];     // conv1 out NHWC
__device__ __align__(16) float g_x2[(size_t)BF*NT*3*64];     // conv2 out NHWC
__device__ __align__(16) float g_xT[(size_t)NT*BF*128];      // conv3 out, [t][n][c]
__device__ __align__(16) float g_G[(size_t)2*65536*512];     // x@Wih.T + bias, per dir
__device__ __align__(16) float g_hcat[(size_t)BF*65536];     // [n][t*256 + dir*128 + j]
__device__ __align__(16) float g_fc1part[(size_t)64*256*128];// split-K partials
__device__ __align__(16) float g_z1[(size_t)256*128];        // relu(fc1)
__device__ __align__(16) float g_wT1[9*32*16];               // conv1 weights [tap][co][ci]
__device__ __align__(16) float g_wT2[9*64*32];
__device__ __align__(16) float g_wT3[9*128*64];

// ---------------------------------------------------------------------------
// helpers
// ---------------------------------------------------------------------------
union F2U { float4 v; unsigned long long u[2]; };
union F2S { unsigned long long u; float f[2]; };

__device__ __forceinline__ unsigned long long ffma2(unsigned long long a,
                                                    unsigned long long b,
                                                    unsigned long long c)
{
    unsigned long long d;
    asm("fma.rn.f32x2 %0, %1, %2, %3;" : "=l"(d) : "l"(a), "l"(b), "l"(c));
    return d;
}
__device__ __forceinline__ unsigned long long dup2(float x)
{
    unsigned long long r;
    asm("mov.b64 %0, {%1, %1};" : "=l"(r) : "f"(x));
    return r;
}
__device__ __forceinline__ uint32_t f2tf(float f)
{
    uint32_t r;
    asm("cvt.rna.tf32.f32 %0, %1;" : "=r"(r) : "f"(f));
    return r;
}
__device__ __forceinline__ void mma_tf32(float* d, const uint32_t* a, const uint32_t* b)
{
    asm("mma.sync.aligned.m16n8k8.row.col.f32.tf32.tf32.f32 "
        "{%0,%1,%2,%3}, {%4,%5,%6,%7}, {%8,%9}, {%0,%1,%2,%3};"
        : "+f"(d[0]), "+f"(d[1]), "+f"(d[2]), "+f"(d[3])
        : "r"(a[0]), "r"(a[1]), "r"(a[2]), "r"(a[3]), "r"(b[0]), "r"(b[1]));
}

// ---------------------------------------------------------------------------
// Weight transform: w[co][ci][kh][kw] -> wT[tap][co][ci]
// ---------------------------------------------------------------------------
__global__ void wtrans_k(const float* __restrict__ w, float* __restrict__ wT,
                         int CIN, int COUT)
{
    int idx = blockIdx.x*256 + threadIdx.x;
    int total = 9*CIN*COUT;
    if (idx >= total) return;
    int ci  = idx % CIN;
    int r   = idx / CIN;
    int co  = r % COUT;
    int tap = r / COUT;
    wT[idx] = w[(co*CIN + ci)*9 + tap];
}

// ---------------------------------------------------------------------------
// conv0: CIN=1 -> 16, direct (memory bound). out NHWC [bf][t][27][16].
// ---------------------------------------------------------------------------
__global__ void conv0_k(const float* __restrict__ audio, const float* __restrict__ w,
                        const float* __restrict__ bias, float* __restrict__ out)
{
    __shared__ float wsm[9][16];
    __shared__ float bsm[16];
    int tid = threadIdx.x;
    if (tid < 144) wsm[tid % 9][tid / 9] = w[tid];
    if (tid < 16)  bsm[tid] = bias[tid];
    __syncthreads();

    size_t idx = (size_t)blockIdx.x*256 + tid;   // (bf, t, wo)
    int wo = (int)(idx % 27);
    size_t r = idx / 27;
    int t  = (int)(r % NT);
    int bf = (int)(r / NT);

    float acc[16];
    #pragma unroll
    for (int co = 0; co < 16; co++) acc[co] = bsm[co];

    #pragma unroll
    for (int kh = 0; kh < 3; kh++) {
        int ti = t + kh - 1;
        if (ti < 0 || ti >= NT) continue;
        #pragma unroll
        for (int kw = 0; kw < 3; kw++) {
            int wc = 3*wo + kw - 1;
            if (wc < 0 || wc >= 81) continue;
            float v = audio[((size_t)bf*NT + ti)*81 + wc];
            #pragma unroll
            for (int co = 0; co < 16; co++) acc[co] += v * wsm[kh*3+kw][co];
        }
    }
    float* o = out + idx*16;
    #pragma unroll
    for (int q = 0; q < 4; q++) {
        float4 v;
        v.x = fmaxf(acc[q*4+0], 0.f); v.y = fmaxf(acc[q*4+1], 0.f);
        v.z = fmaxf(acc[q*4+2], 0.f); v.w = fmaxf(acc[q*4+3], 0.f);
        *(float4*)(o + q*4) = v;
    }
}

// ---------------------------------------------------------------------------
// Implicit-GEMM conv with tf32 mma. Block = (t-tile 128, wo, bf).
// ---------------------------------------------------------------------------
template<int CIN,int COUT,int WIN,int WOUT,bool TOUT>
__global__ void conv_mma_k(const float* __restrict__ x, const float* __restrict__ wT,
                           const float* __restrict__ bias, float* __restrict__ out)
{
    constexpr int NWN = COUT/32;         // warps along n
    constexpr int WMW = 8/NWN;           // warps along m
    constexpr int MFR = 128/WMW/16;      // m-frags per warp
    constexpr int LDA = CIN + 4;
    extern __shared__ uint32_t dynsm[];
    uint32_t* As = dynsm;                // [128][LDA]
    uint32_t* Bs = dynsm + 128*LDA;      // [COUT][LDA]

    const int tid  = threadIdx.x;
    const int lane = tid & 31;
    const int wid  = tid >> 5;
    const int g    = lane >> 2, tq = lane & 3;
    const int wm0  = (wid % WMW) * (128/WMW);
    const int wn0  = (wid / WMW) * 32;
    const int t0   = blockIdx.x * 128;
    const int wo   = blockIdx.y;
    const int bf   = blockIdx.z;

    float acc[MFR][4][4];
    #pragma unroll
    for (int i = 0; i < MFR; i++)
        #pragma unroll
        for (int j = 0; j < 4; j++)
            #pragma unroll
            for (int q = 0; q < 4; q++) acc[i][j][q] = 0.f;

    #pragma unroll
    for (int kh = 0; kh < 3; kh++) {
        #pragma unroll
        for (int kw = 0; kw < 3; kw++) {
            const int wc = 3*wo + kw - 1;
            if (wc < 0 || wc >= WIN) continue;
            const int tap = kh*3 + kw;
            for (int l = tid; l < 128*(CIN/4); l += 256) {
                int m = l / (CIN/4), kq = l % (CIN/4);
                int t_in = t0 + m + kh - 1;
                float4 v = make_float4(0.f,0.f,0.f,0.f);
                if (t_in >= 0 && t_in < NT)
                    v = *(const float4*)(x + (((size_t)bf*NT + t_in)*WIN + wc)*CIN + kq*4);
                uint32_t* a = As + m*LDA + kq*4;
                a[0]=f2tf(v.x); a[1]=f2tf(v.y); a[2]=f2tf(v.z); a[3]=f2tf(v.w);
            }
            const float* wtap = wT + (size_t)tap*COUT*CIN;
            for (int l = tid; l < COUT*(CIN/4); l += 256) {
                int co = l / (CIN/4), kq = l % (CIN/4);
                float4 v = *(const float4*)(wtap + co*CIN + kq*4);
                uint32_t* b = Bs + co*LDA + kq*4;
                b[0]=f2tf(v.x); b[1]=f2tf(v.y); b[2]=f2tf(v.z); b[3]=f2tf(v.w);
            }
            __syncthreads();
            #pragma unroll
            for (int k8 = 0; k8 < CIN; k8 += 8) {
                uint32_t a[MFR][4], b[4][2];
                #pragma unroll
                for (int fi = 0; fi < MFR; fi++) {
                    int r = wm0 + fi*16;
                    a[fi][0] = As[(r+g  )*LDA + k8 + tq];
                    a[fi][1] = As[(r+g+8)*LDA + k8 + tq];
                    a[fi][2] = As[(r+g  )*LDA + k8 + tq + 4];
                    a[fi][3] = As[(r+g+8)*LDA + k8 + tq + 4];
                }
                #pragma unroll
                for (int fj = 0; fj < 4; fj++) {
                    int cn = wn0 + fj*8 + g;
                    b[fj][0] = Bs[cn*LDA + k8 + tq];
                    b[fj][1] = Bs[cn*LDA + k8 + tq + 4];
                }
                #pragma unroll
                for (int fi = 0; fi < MFR; fi++)
                    #pragma unroll
                    for (int fj = 0; fj < 4; fj++)
                        mma_tf32(acc[fi][fj], a[fi], b[fj]);
            }
            __syncthreads();
        }
    }

    #pragma unroll
    for (int fj = 0; fj < 4; fj++) {
        int co0 = wn0 + fj*8 + 2*tq;
        float bv0 = bias[co0], bv1 = bias[co0+1];
        #pragma unroll
        for (int fi = 0; fi < MFR; fi++) {
            #pragma unroll
            for (int p = 0; p < 2; p++) {
                int m = wm0 + fi*16 + g + p*8;
                float2 v;
                v.x = fmaxf(acc[fi][fj][p*2+0] + bv0, 0.f);
                v.y = fmaxf(acc[fi][fj][p*2+1] + bv1, 0.f);
                size_t base;
                if (TOUT) base = ((size_t)(t0+m)*BF + bf)*COUT + co0;
                else      base = (((size_t)bf*NT + (t0+m))*WOUT + wo)*COUT + co0;
                *(float2*)(out + base) = v;
            }
        }
    }
}

// ---------------------------------------------------------------------------
// Input-projection GEMM, tf32 mma: G[dir][m][g] = X[m][:] @ W[g][:] + bias
// ---------------------------------------------------------------------------
__global__ void gemm_xw_k(const float* __restrict__ X,
                          const float* __restrict__ Wf, const float* __restrict__ Wb,
                          const float* __restrict__ bihf, const float* __restrict__ bhhf,
                          const float* __restrict__ bihb, const float* __restrict__ bhhb)
{
    const int dir = blockIdx.z;
    const float* W  = dir ? Wb   : Wf;
    const float* b1 = dir ? bihb : bihf;
    const float* b2 = dir ? bhhb : bhhf;
    float* out = g_G + (size_t)dir*65536*512;

    __shared__ uint32_t As[128][36];
    __shared__ uint32_t Bs[128][36];

    const int tid  = threadIdx.x;
    const int lane = tid & 31;
    const int wid  = tid >> 5;
    const int g    = lane >> 2, tq = lane & 3;
    const int wm0  = (wid & 1) * 64;
    const int wn0  = (wid >> 1) * 32;
    const int m0   = blockIdx.y * 128, n0 = blockIdx.x * 128;

    float acc[4][4][4];
    #pragma unroll
    for (int i = 0; i < 4; i++)
        #pragma unroll
        for (int j = 0; j < 4; j++)
            #pragma unroll
            for (int q = 0; q < 4; q++) acc[i][j][q] = 0.f;

    for (int kt = 0; kt < 128; kt += 32) {
        #pragma unroll
        for (int i = 0; i < 4; i++) {
            int l = i*256 + tid;
            int m = l >> 3, kq = l & 7;
            float4 v = *(const float4*)(X + (size_t)(m0+m)*128 + kt + kq*4);
            As[m][kq*4+0]=f2tf(v.x); As[m][kq*4+1]=f2tf(v.y);
            As[m][kq*4+2]=f2tf(v.z); As[m][kq*4+3]=f2tf(v.w);
            float4 u = *(const float4*)(W + (size_t)(n0+m)*128 + kt + kq*4);
            Bs[m][kq*4+0]=f2tf(u.x); Bs[m][kq*4+1]=f2tf(u.y);
            Bs[m][kq*4+2]=f2tf(u.z); Bs[m][kq*4+3]=f2tf(u.w);
        }
        __syncthreads();
        #pragma unroll
        for (int k8 = 0; k8 < 32; k8 += 8) {
            uint32_t a[4][4], b[4][2];
            #pragma unroll
            for (int fi = 0; fi < 4; fi++) {
                int r = wm0 + fi*16;
                a[fi][0] = As[r+g  ][k8+tq];
                a[fi][1] = As[r+g+8][k8+tq];
                a[fi][2] = As[r+g  ][k8+tq+4];
                a[fi][3] = As[r+g+8][k8+tq+4];
            }
            #pragma unroll
            for (int fj = 0; fj < 4; fj++) {
                int cn = wn0 + fj*8 + g;
                b[fj][0] = Bs[cn][k8+tq];
                b[fj][1] = Bs[cn][k8+tq+4];
            }
            #pragma unroll
            for (int fi = 0; fi < 4; fi++)
                #pragma unroll
                for (int fj = 0; fj < 4; fj++)
                    mma_tf32(acc[fi][fj], a[fi], b[fj]);
        }
        __syncthreads();
    }

    #pragma unroll
    for (int fj = 0; fj < 4; fj++) {
        int gate0 = n0 + wn0 + fj*8 + 2*tq;
        float bv0 = b1[gate0]   + b2[gate0];
        float bv1 = b1[gate0+1] + b2[gate0+1];
        #pragma unroll
        for (int fi = 0; fi < 4; fi++) {
            #pragma unroll
            for (int p = 0; p < 2; p++) {
                int m = m0 + wm0 + fi*16 + g + p*8;
                float2 v;
                v.x = acc[fi][fj][p*2+0] + bv0;
                v.y = acc[fi][fj][p*2+1] + bv1;
                *(float2*)(out + (size_t)m*512 + gate0) = v;
            }
        }
    }
}

// ---------------------------------------------------------------------------
// LSTM recurrence, tensor-core edition.
// Cluster of 2 CTAs; each CTA holds 256 gate rows of Whh as tf32 fragments
// IN REGISTERS (128 regs/thread, loaded once). Batch NB=16 per cluster fills
// the m16 dimension exactly. Grid (2, 16, 2) = 64 CTAs.
// Per step: phase A = 16 k-tiles x 4 n-tiles mma -> Z[16][256] in smem;
// phase B = gate combine + state update + DSMEM h exchange; 1 cluster barrier.
// ---------------------------------------------------------------------------
__device__ __forceinline__ float sigf(float x) { return 1.f / (1.f + expf(-x)); }

__global__ void __cluster_dims__(2,1,1) __launch_bounds__(256,1)
lstm_k(const float* __restrict__ Whhf, const float* __restrict__ Whhb)
{
    __shared__ float hbuf[2*16*132];     // [buf][batch][128+4]
    __shared__ float zsm[16][258];       // [batch][256 local gate rows + pad]

    const int tid  = threadIdx.x;
    const int lane = tid & 31;
    const int w    = tid >> 5;
    const int g    = lane >> 2, tq = lane & 3;
    const int rank = blockIdx.x & 1;
    const int dir  = blockIdx.z;
    const int nb0  = blockIdx.y * 16;
    const float* Whh = dir ? Whhb : Whhf;
    const float* G   = g_G + (size_t)dir*65536*512;

    // ---- load Whh fragments into registers (once) ----
    // local gate row r = w*32 + fj*8 + g  ->  global row (r>>6)*128 + rank*64 + (r&63)
    uint32_t wb[4][16][2];
    #pragma unroll
    for (int fj = 0; fj < 4; fj++) {
        int rl = w*32 + fj*8 + g;
        int grow = (rl >> 6)*128 + rank*64 + (rl & 63);
        const float* wr = Whh + (size_t)grow*128;
        #pragma unroll
        for (int kt = 0; kt < 16; kt++) {
            wb[fj][kt][0] = f2tf(wr[kt*8 + tq]);
            wb[fj][kt][1] = f2tf(wr[kt*8 + tq + 4]);
        }
    }

    for (int idx = tid; idx < 2*16*132; idx += 256) hbuf[idx] = 0.f;

    uint32_t hbuf_u32;
    { uint64_t tmp;
      asm("cvta.to.shared.u64 %0, %1;" : "=l"(tmp) : "l"((float*)hbuf));
      hbuf_u32 = (uint32_t)tmp; }

    asm volatile("barrier.cluster.arrive.aligned;\n\tbarrier.cluster.wait.aligned;" ::: "memory");

    const int j    = tid & 63;
    const int bq   = tid >> 6;           // phase-B batch quad
    const int gcol = rank*64 + j;
    const int peer = rank ^ 1;
    float c[4] = {0.f, 0.f, 0.f, 0.f};

    float Gc[4][4], Gn[4][4];
    {
        int t0 = dir ? 255 : 0;
        #pragma unroll
        for (int mm = 0; mm < 4; mm++)
            #pragma unroll
            for (int gt = 0; gt < 4; gt++)
                Gc[mm][gt] = G[((size_t)t0*256 + nb0 + bq*4 + mm)*512 + gt*128 + gcol];
    }

    for (int s = 0; s < 256; s++) {
        const int t   = dir ? (255 - s) : s;
        const int cur = s & 1, nxt = cur ^ 1;

        // ---- phase A: Z = h @ Whh_cta^T via tensor cores ----
        float acc[4][4];
        #pragma unroll
        for (int fj = 0; fj < 4; fj++)
            #pragma unroll
            for (int q = 0; q < 4; q++) acc[fj][q] = 0.f;

        const float* hb = hbuf + cur*16*132;
        #pragma unroll
        for (int kt = 0; kt < 16; kt++) {
            uint32_t a[4];
            const int k0 = kt*8;
            a[0] = f2tf(hb[(g  )*132 + k0 + tq]);
            a[1] = f2tf(hb[(g+8)*132 + k0 + tq]);
            a[2] = f2tf(hb[(g  )*132 + k0 + tq + 4]);
            a[3] = f2tf(hb[(g+8)*132 + k0 + tq + 4]);
            #pragma unroll
            for (int fj = 0; fj < 4; fj++)
                mma_tf32(acc[fj], a, wb[fj][kt]);
        }
        #pragma unroll
        for (int fj = 0; fj < 4; fj++) {
            int nloc = w*32 + fj*8 + 2*tq;
            *(float2*)&zsm[g  ][nloc] = make_float2(acc[fj][0], acc[fj][1]);
            *(float2*)&zsm[g+8][nloc] = make_float2(acc[fj][2], acc[fj][3]);
        }
        __syncthreads();

        // prefetch next step's G (lands during phase B + barrier)
        if (s < 255) {
            int tn = dir ? (254 - s) : (s + 1);
            #pragma unroll
            for (int mm = 0; mm < 4; mm++)
                #pragma unroll
                for (int gt = 0; gt < 4; gt++)
                    Gn[mm][gt] = G[((size_t)tn*256 + nb0 + bq*4 + mm)*512 + gt*128 + gcol];
        }

        // ---- phase B: gate combine + state update (4 batches per thread) ----
        #pragma unroll
        for (int mm = 0; mm < 4; mm++) {
            int m = bq*4 + mm;
            float ai = zsm[m][0*64 + j] + Gc[mm][0];
            float af = zsm[m][1*64 + j] + Gc[mm][1];
            float ag = zsm[m][2*64 + j] + Gc[mm][2];
            float ao = zsm[m][3*64 + j] + Gc[mm][3];
            float iv = sigf(ai);
            float fv = sigf(af);
            float gv = tanhf(ag);
            float ov = sigf(ao);
            c[mm] = fv*c[mm] + iv*gv;
            float hv = ov * tanhf(c[mm]);
            g_hcat[(size_t)(nb0+m)*65536 + t*256 + dir*128 + gcol] = hv;
            int off = (nxt*16 + m)*132 + gcol;
            hbuf[off] = hv;
            uint32_t raddr;
            asm volatile("mapa.shared::cluster.u32 %0, %1, %2;"
                         : "=r"(raddr) : "r"(hbuf_u32 + (uint32_t)off*4u), "r"(peer));
            asm volatile("st.shared::cluster.f32 [%0], %1;" :: "r"(raddr), "f"(hv) : "memory");
        }
        #pragma unroll
        for (int mm = 0; mm < 4; mm++)
            #pragma unroll
            for (int gt = 0; gt < 4; gt++) Gc[mm][gt] = Gn[mm][gt];
        asm volatile("barrier.cluster.arrive.aligned;\n\tbarrier.cluster.wait.aligned;" ::: "memory");
    }
}

// ---------------------------------------------------------------------------
// FC1 split-K partials with f32x2 (fp32 kept for accuracy on score path)
// ---------------------------------------------------------------------------
__global__ void fc1_part_k(const float* __restrict__ fw)
{
    __shared__ __align__(16) float As[16][68];
    __shared__ __align__(16) float Bs[16][132];
    const int tid = threadIdx.x;
    const int tx = tid & 15, ty = tid >> 4;
    const int m0 = blockIdx.x * 64;
    const int k0 = blockIdx.y * 1024;

    unsigned long long acc2[2][8];
    #pragma unroll
    for (int i = 0; i < 2; i++) {
        #pragma unroll
        for (int j = 0; j < 8; j++) acc2[i][j] = 0ull;
    }

    for (int kt = 0; kt < 1024; kt += 16) {
        {
            int l = tid;
            int row = l >> 2, kq = l & 3;
            float4 v = *(const float4*)(g_hcat + (size_t)(m0+row)*65536 + k0 + kt + kq*4);
            As[kq*4+0][row]=v.x; As[kq*4+1][row]=v.y; As[kq*4+2][row]=v.z; As[kq*4+3][row]=v.w;
        }
        #pragma unroll
        for (int i = 0; i < 2; i++) {
            int l = tid*2 + i;
            int row = l >> 2, kq = l & 3;
            float4 u = *(const float4*)(fw + (size_t)row*65536 + k0 + kt + kq*4);
            Bs[kq*4+0][row]=u.x; Bs[kq*4+1][row]=u.y; Bs[kq*4+2][row]=u.z; Bs[kq*4+3][row]=u.w;
        }
        __syncthreads();
        #pragma unroll
        for (int k = 0; k < 16; k++) {
            F2U a0;
            a0.v = *(const float4*)&As[k][ty*4];
            float b[8];
            *(float4*)(b  ) = *(const float4*)&Bs[k][tx*8];
            *(float4*)(b+4) = *(const float4*)&Bs[k][tx*8+4];
            #pragma unroll
            for (int j = 0; j < 8; j++) {
                unsigned long long bd = dup2(b[j]);
                acc2[0][j] = ffma2(a0.u[0], bd, acc2[0][j]);
                acc2[1][j] = ffma2(a0.u[1], bd, acc2[1][j]);
            }
        }
        __syncthreads();
    }
    #pragma unroll
    for (int i2 = 0; i2 < 2; i2++)
        #pragma unroll
        for (int jj = 0; jj < 8; jj++) {
            F2S s; s.u = acc2[i2][jj];
            g_fc1part[((size_t)blockIdx.y*256 + m0 + ty*4 + i2*2    )*128 + tx*8 + jj] = s.f[0];
            g_fc1part[((size_t)blockIdx.y*256 + m0 + ty*4 + i2*2 + 1)*128 + tx*8 + jj] = s.f[1];
        }
}

__global__ void fc1_reduce_k(const float* __restrict__ fc1b)
{
    int idx = blockIdx.x*256 + threadIdx.x;
    int m = idx >> 7, h = idx & 127;
    float s = fc1b[h];
    #pragma unroll 8
    for (int kc = 0; kc < 64; kc++)
        s += g_fc1part[((size_t)kc*256 + m)*128 + h];
    g_z1[(size_t)m*128 + h] = fmaxf(s, 0.f);
}

__global__ void score_k(const float* __restrict__ fsw, const float* __restrict__ fsb,
                        float* __restrict__ out)
{
    __shared__ float w[128];
    __shared__ float fr[256];
    int tid = threadIdx.x;
    if (tid < 128) w[tid] = fsw[tid];
    __syncthreads();
    float acc = fsb[0];
    #pragma unroll 8
    for (int h = 0; h < 128; h++) acc += g_z1[(size_t)tid*128 + h] * w[h];
    float sc = 1.f / (1.f + expf(-acc)) * 4.f + 1.f;
    out[16 + tid] = sc;
    fr[tid] = sc;
    __syncthreads();
    if (tid < 16) {
        float s = 0.f;
        #pragma unroll
        for (int f = 0; f < 16; f++) s += fr[tid*16 + f];
        out[tid] = s * (1.f/16.f);
    }
}

// ---------------------------------------------------------------------------
extern "C" void kernel_launch(void* const* d_in, const int* in_sizes, int n_in,
                              void* d_out, int out_size)
{
    const float *audio,*w0,*b0,*w1,*b1,*w2,*b2,*w3,*b3;
    const float *Wihf,*Whhf,*bihf,*bhhf,*Wihb,*Whhb,*bihb,*bhhb;
    const float *fc1w,*fc1b,*fsw,*fsb;
    if (n_in >= 22 && in_sizes[1] == 144) {
        audio=(const float*)d_in[0];
        w0=(const float*)d_in[1];  b0=(const float*)d_in[2];
        w1=(const float*)d_in[3];  b1=(const float*)d_in[4];
        w2=(const float*)d_in[5];  b2=(const float*)d_in[6];
        w3=(const float*)d_in[7];  b3=(const float*)d_in[8];
        Wihf=(const float*)d_in[9];  Whhf=(const float*)d_in[10];
        bihf=(const float*)d_in[11]; bhhf=(const float*)d_in[12];
        Wihb=(const float*)d_in[13]; Whhb=(const float*)d_in[14];
        bihb=(const float*)d_in[15]; bhhb=(const float*)d_in[16];
        fc1w=(const float*)d_in[17]; fc1b=(const float*)d_in[18];
        fsw=(const float*)d_in[19];  fsb=(const float*)d_in[20];
    } else {
        audio=(const float*)d_in[0];
        w0=(const float*)d_in[2];  b0=(const float*)d_in[3];
        w1=(const float*)d_in[4];  b1=(const float*)d_in[5];
        w2=(const float*)d_in[6];  b2=(const float*)d_in[7];
        w3=(const float*)d_in[8];  b3=(const float*)d_in[9];
        Wihf=(const float*)d_in[10]; Whhf=(const float*)d_in[11];
        bihf=(const float*)d_in[12]; bhhf=(const float*)d_in[13];
        Wihb=(const float*)d_in[14]; Whhb=(const float*)d_in[15];
        bihb=(const float*)d_in[16]; bhhb=(const float*)d_in[17];
        fc1w=(const float*)d_in[18]; fc1b=(const float*)d_in[19];
        fsw=(const float*)d_in[20];  fsb=(const float*)d_in[21];
    }

    float *x0,*x1,*x2,*xT,*wT1,*wT2,*wT3;
    cudaGetSymbolAddress((void**)&x0, g_x0);
    cudaGetSymbolAddress((void**)&x1, g_x1);
    cudaGetSymbolAddress((void**)&x2, g_x2);
    cudaGetSymbolAddress((void**)&xT, g_xT);
    cudaGetSymbolAddress((void**)&wT1, g_wT1);
    cudaGetSymbolAddress((void**)&wT2, g_wT2);
    cudaGetSymbolAddress((void**)&wT3, g_wT3);

    // conv_mma dynamic smem: (128 + COUT) * (CIN+4) * 4 bytes
    const int sc1 = (128 + 32) * (16 + 4) * 4;
    const int sc2 = (128 + 64) * (32 + 4) * 4;
    const int sc3 = (128 +128) * (64 + 4) * 4;
    cudaFuncSetAttribute(conv_mma_k<16, 32,27,9,false>, cudaFuncAttributeMaxDynamicSharedMemorySize, sc1);
    cudaFuncSetAttribute(conv_mma_k<32, 64, 9,3,false>, cudaFuncAttributeMaxDynamicSharedMemorySize, sc2);
    cudaFuncSetAttribute(conv_mma_k<64,128, 3,1,true >, cudaFuncAttributeMaxDynamicSharedMemorySize, sc3);

    // weight transforms (tiny)
    wtrans_k<<<(9*16*32 + 255)/256, 256>>>(w1, wT1, 16, 32);
    wtrans_k<<<(9*32*64 + 255)/256, 256>>>(w2, wT2, 32, 64);
    wtrans_k<<<(9*64*128+ 255)/256, 256>>>(w3, wT3, 64, 128);

    // conv stack (NHWC)
    conv0_k<<<(BF*NT*27)/256, 256>>>(audio, w0, b0, x0);
    conv_mma_k<16, 32,27,9,false><<<dim3(2,9,BF), 256, sc1>>>(x0, wT1, b1, x1);
    conv_mma_k<32, 64, 9,3,false><<<dim3(2,3,BF), 256, sc2>>>(x1, wT2, b2, x2);
    conv_mma_k<64,128, 3,1,true ><<<dim3(2,1,BF), 256, sc3>>>(x2, wT3, b3, xT);

    gemm_xw_k<<<dim3(4,512,2), 256>>>(xT, Wihf, Wihb, bihf, bhhf, bihb, bhhb);

    lstm_k<<<dim3(2,16,2), 256>>>(Whhf, Whhb);

    fc1_part_k<<<dim3(4,64), 256>>>(fc1w);
    fc1_reduce_k<<<128, 256>>>(fc1b);
    score_k<<<1, 256>>>(fsw, fsb, (float*)d_out);
}

// round 8
// speedup vs baseline: 2.7875x; 1.0034x over previous
#include <cuda_runtime.h>
#include <cuda_bf16.h>
#include <cstdint>
#include <math.h>

// ---------------------------------------------------------------------------
// Static scratch (no allocations allowed)
// ---------------------------------------------------------------------------
#define BF 256          // B*F = 16*16 frame windows
#define NT 256          // frames per window (time)
__device__ __align__(16) float g_x0[(size_t)BF*NT*27*16];    // conv0 out NHWC
__device__ __align__(16) float g_x1[(size_t)BF*NT*9*32];     // conv1 out NHWC
__device__ __align__(16) float g_x2[(size_t)BF*NT*3*64];     // conv2 out NHWC
__device__ __align__(16) float g_xT[(size_t)NT*BF*128];      // conv3 out, [t][n][c]
__device__ __align__(16) __nv_bfloat16 g_G[(size_t)2*65536*512]; // x@Wih.T + bias (bf16)
__device__ __align__(16) float g_hcat[(size_t)BF*65536];     // [n][t*256 + dir*128 + j]
__device__ __align__(16) float g_fc1part[(size_t)128*256*128];// split-K partials
__device__ __align__(16) float g_z1[(size_t)256*128];        // relu(fc1)
__device__ __align__(16) float g_wT1[9*32*16];               // conv1 weights [tap][co][ci]
__device__ __align__(16) float g_wT2[9*64*32];
__device__ __align__(16) float g_wT3[9*128*64];

// ---------------------------------------------------------------------------
// helpers
// ---------------------------------------------------------------------------
__device__ __forceinline__ uint32_t f2tf(float f)
{
    uint32_t r;
    asm("cvt.rna.tf32.f32 %0, %1;" : "=r"(r) : "f"(f));
    return r;
}
__device__ __forceinline__ void mma_tf32(float* d, const uint32_t* a, const uint32_t* b)
{
    asm("mma.sync.aligned.m16n8k8.row.col.f32.tf32.tf32.f32 "
        "{%0,%1,%2,%3}, {%4,%5,%6,%7}, {%8,%9}, {%0,%1,%2,%3};"
        : "+f"(d[0]), "+f"(d[1]), "+f"(d[2]), "+f"(d[3])
        : "r"(a[0]), "r"(a[1]), "r"(a[2]), "r"(a[3]), "r"(b[0]), "r"(b[1]));
}

// ---------------------------------------------------------------------------
// Weight transform: w[co][ci][kh][kw] -> wT[tap][co][ci]
// ---------------------------------------------------------------------------
__global__ void wtrans_k(const float* __restrict__ w, float* __restrict__ wT,
                         int CIN, int COUT)
{
    int idx = blockIdx.x*256 + threadIdx.x;
    int total = 9*CIN*COUT;
    if (idx >= total) return;
    int ci  = idx % CIN;
    int r   = idx / CIN;
    int co  = r % COUT;
    int tap = r / COUT;
    wT[idx] = w[(co*CIN + ci)*9 + tap];
}

// ---------------------------------------------------------------------------
// conv0: CIN=1 -> 16, direct (memory bound). out NHWC [bf][t][27][16].
// ---------------------------------------------------------------------------
__global__ void conv0_k(const float* __restrict__ audio, const float* __restrict__ w,
                        const float* __restrict__ bias, float* __restrict__ out)
{
    __shared__ float wsm[9][16];
    __shared__ float bsm[16];
    int tid = threadIdx.x;
    if (tid < 144) wsm[tid % 9][tid / 9] = w[tid];
    if (tid < 16)  bsm[tid] = bias[tid];
    __syncthreads();

    size_t idx = (size_t)blockIdx.x*256 + tid;   // (bf, t, wo)
    int wo = (int)(idx % 27);
    size_t r = idx / 27;
    int t  = (int)(r % NT);
    int bf = (int)(r / NT);

    float acc[16];
    #pragma unroll
    for (int co = 0; co < 16; co++) acc[co] = bsm[co];

    #pragma unroll
    for (int kh = 0; kh < 3; kh++) {
        int ti = t + kh - 1;
        if (ti < 0 || ti >= NT) continue;
        #pragma unroll
        for (int kw = 0; kw < 3; kw++) {
            int wc = 3*wo + kw - 1;
            if (wc < 0 || wc >= 81) continue;
            float v = audio[((size_t)bf*NT + ti)*81 + wc];
            #pragma unroll
            for (int co = 0; co < 16; co++) acc[co] += v * wsm[kh*3+kw][co];
        }
    }
    float* o = out + idx*16;
    #pragma unroll
    for (int q = 0; q < 4; q++) {
        float4 v;
        v.x = fmaxf(acc[q*4+0], 0.f); v.y = fmaxf(acc[q*4+1], 0.f);
        v.z = fmaxf(acc[q*4+2], 0.f); v.w = fmaxf(acc[q*4+3], 0.f);
        *(float4*)(o + q*4) = v;
    }
}

// ---------------------------------------------------------------------------
// Implicit-GEMM conv with tf32 mma. Block = (t-tile 128, wo, bf).
// ---------------------------------------------------------------------------
template<int CIN,int COUT,int WIN,int WOUT,bool TOUT>
__global__ void conv_mma_k(const float* __restrict__ x, const float* __restrict__ wT,
                           const float* __restrict__ bias, float* __restrict__ out)
{
    constexpr int NWN = COUT/32;         // warps along n
    constexpr int WMW = 8/NWN;           // warps along m
    constexpr int MFR = 128/WMW/16;      // m-frags per warp
    constexpr int LDA = CIN + 4;
    extern __shared__ uint32_t dynsm[];
    uint32_t* As = dynsm;                // [128][LDA]
    uint32_t* Bs = dynsm + 128*LDA;      // [COUT][LDA]

    const int tid  = threadIdx.x;
    const int lane = tid & 31;
    const int wid  = tid >> 5;
    const int g    = lane >> 2, tq = lane & 3;
    const int wm0  = (wid % WMW) * (128/WMW);
    const int wn0  = (wid / WMW) * 32;
    const int t0   = blockIdx.x * 128;
    const int wo   = blockIdx.y;
    const int bf   = blockIdx.z;

    float acc[MFR][4][4];
    #pragma unroll
    for (int i = 0; i < MFR; i++)
        #pragma unroll
        for (int j = 0; j < 4; j++)
            #pragma unroll
            for (int q = 0; q < 4; q++) acc[i][j][q] = 0.f;

    #pragma unroll
    for (int kh = 0; kh < 3; kh++) {
        #pragma unroll
        for (int kw = 0; kw < 3; kw++) {
            const int wc = 3*wo + kw - 1;
            if (wc < 0 || wc >= WIN) continue;
            const int tap = kh*3 + kw;
            for (int l = tid; l < 128*(CIN/4); l += 256) {
                int m = l / (CIN/4), kq = l % (CIN/4);
                int t_in = t0 + m + kh - 1;
                float4 v = make_float4(0.f,0.f,0.f,0.f);
                if (t_in >= 0 && t_in < NT)
                    v = *(const float4*)(x + (((size_t)bf*NT + t_in)*WIN + wc)*CIN + kq*4);
                uint32_t* a = As + m*LDA + kq*4;
                a[0]=f2tf(v.x); a[1]=f2tf(v.y); a[2]=f2tf(v.z); a[3]=f2tf(v.w);
            }
            const float* wtap = wT + (size_t)tap*COUT*CIN;
            for (int l = tid; l < COUT*(CIN/4); l += 256) {
                int co = l / (CIN/4), kq = l % (CIN/4);
                float4 v = *(const float4*)(wtap + co*CIN + kq*4);
                uint32_t* b = Bs + co*LDA + kq*4;
                b[0]=f2tf(v.x); b[1]=f2tf(v.y); b[2]=f2tf(v.z); b[3]=f2tf(v.w);
            }
            __syncthreads();
            #pragma unroll
            for (int k8 = 0; k8 < CIN; k8 += 8) {
                uint32_t a[MFR][4], b[4][2];
                #pragma unroll
                for (int fi = 0; fi < MFR; fi++) {
                    int r = wm0 + fi*16;
                    a[fi][0] = As[(r+g  )*LDA + k8 + tq];
                    a[fi][1] = As[(r+g+8)*LDA + k8 + tq];
                    a[fi][2] = As[(r+g  )*LDA + k8 + tq + 4];
                    a[fi][3] = As[(r+g+8)*LDA + k8 + tq + 4];
                }
                #pragma unroll
                for (int fj = 0; fj < 4; fj++) {
                    int cn = wn0 + fj*8 + g;
                    b[fj][0] = Bs[cn*LDA + k8 + tq];
                    b[fj][1] = Bs[cn*LDA + k8 + tq + 4];
                }
                #pragma unroll
                for (int fi = 0; fi < MFR; fi++)
                    #pragma unroll
                    for (int fj = 0; fj < 4; fj++)
                        mma_tf32(acc[fi][fj], a[fi], b[fj]);
            }
            __syncthreads();
        }
    }

    #pragma unroll
    for (int fj = 0; fj < 4; fj++) {
        int co0 = wn0 + fj*8 + 2*tq;
        float bv0 = bias[co0], bv1 = bias[co0+1];
        #pragma unroll
        for (int fi = 0; fi < MFR; fi++) {
            #pragma unroll
            for (int p = 0; p < 2; p++) {
                int m = wm0 + fi*16 + g + p*8;
                float2 v;
                v.x = fmaxf(acc[fi][fj][p*2+0] + bv0, 0.f);
                v.y = fmaxf(acc[fi][fj][p*2+1] + bv1, 0.f);
                size_t base;
                if (TOUT) base = ((size_t)(t0+m)*BF + bf)*COUT + co0;
                else      base = (((size_t)bf*NT + (t0+m))*WOUT + wo)*COUT + co0;
                *(float2*)(out + base) = v;
            }
        }
    }
}

// ---------------------------------------------------------------------------
// Input-projection GEMM, tf32 mma, bf16 output G.
// ---------------------------------------------------------------------------
__global__ void gemm_xw_k(const float* __restrict__ X,
                          const float* __restrict__ Wf, const float* __restrict__ Wb,
                          const float* __restrict__ bihf, const float* __restrict__ bhhf,
                          const float* __restrict__ bihb, const float* __restrict__ bhhb)
{
    const int dir = blockIdx.z;
    const float* W  = dir ? Wb   : Wf;
    const float* b1 = dir ? bihb : bihf;
    const float* b2 = dir ? bhhb : bhhf;
    __nv_bfloat16* out = g_G + (size_t)dir*65536*512;

    __shared__ uint32_t As[128][36];
    __shared__ uint32_t Bs[128][36];

    const int tid  = threadIdx.x;
    const int lane = tid & 31;
    const int wid  = tid >> 5;
    const int g    = lane >> 2, tq = lane & 3;
    const int wm0  = (wid & 1) * 64;
    const int wn0  = (wid >> 1) * 32;
    const int m0   = blockIdx.y * 128, n0 = blockIdx.x * 128;

    float acc[4][4][4];
    #pragma unroll
    for (int i = 0; i < 4; i++)
        #pragma unroll
        for (int j = 0; j < 4; j++)
            #pragma unroll
            for (int q = 0; q < 4; q++) acc[i][j][q] = 0.f;

    for (int kt = 0; kt < 128; kt += 32) {
        #pragma unroll
        for (int i = 0; i < 4; i++) {
            int l = i*256 + tid;
            int m = l >> 3, kq = l & 7;
            float4 v = *(const float4*)(X + (size_t)(m0+m)*128 + kt + kq*4);
            As[m][kq*4+0]=f2tf(v.x); As[m][kq*4+1]=f2tf(v.y);
            As[m][kq*4+2]=f2tf(v.z); As[m][kq*4+3]=f2tf(v.w);
            float4 u = *(const float4*)(W + (size_t)(n0+m)*128 + kt + kq*4);
            Bs[m][kq*4+0]=f2tf(u.x); Bs[m][kq*4+1]=f2tf(u.y);
            Bs[m][kq*4+2]=f2tf(u.z); Bs[m][kq*4+3]=f2tf(u.w);
        }
        __syncthreads();
        #pragma unroll
        for (int k8 = 0; k8 < 32; k8 += 8) {
            uint32_t a[4][4], b[4][2];
            #pragma unroll
            for (int fi = 0; fi < 4; fi++) {
                int r = wm0 + fi*16;
                a[fi][0] = As[r+g  ][k8+tq];
                a[fi][1] = As[r+g+8][k8+tq];
                a[fi][2] = As[r+g  ][k8+tq+4];
                a[fi][3] = As[r+g+8][k8+tq+4];
            }
            #pragma unroll
            for (int fj = 0; fj < 4; fj++) {
                int cn = wn0 + fj*8 + g;
                b[fj][0] = Bs[cn][k8+tq];
                b[fj][1] = Bs[cn][k8+tq+4];
            }
            #pragma unroll
            for (int fi = 0; fi < 4; fi++)
                #pragma unroll
                for (int fj = 0; fj < 4; fj++)
                    mma_tf32(acc[fi][fj], a[fi], b[fj]);
        }
        __syncthreads();
    }

    #pragma unroll
    for (int fj = 0; fj < 4; fj++) {
        int gate0 = n0 + wn0 + fj*8 + 2*tq;
        float bv0 = b1[gate0]   + b2[gate0];
        float bv1 = b1[gate0+1] + b2[gate0+1];
        #pragma unroll
        for (int fi = 0; fi < 4; fi++) {
            #pragma unroll
            for (int p = 0; p < 2; p++) {
                int m = m0 + wm0 + fi*16 + g + p*8;
                __nv_bfloat162 v = __floats2bfloat162_rn(acc[fi][fj][p*2+0] + bv0,
                                                         acc[fi][fj][p*2+1] + bv1);
                *(__nv_bfloat162*)(out + (size_t)m*512 + gate0) = v;
            }
        }
    }
}

// ---------------------------------------------------------------------------
// LSTM recurrence, tensor-core edition (G now bf16).
// ---------------------------------------------------------------------------
__device__ __forceinline__ float sigf(float x) { return 1.f / (1.f + expf(-x)); }

__global__ void __cluster_dims__(2,1,1) __launch_bounds__(256,1)
lstm_k(const float* __restrict__ Whhf, const float* __restrict__ Whhb)
{
    __shared__ float hbuf[2*16*132];     // [buf][batch][128+4]
    __shared__ float zsm[16][258];       // [batch][256 local gate rows + pad]

    const int tid  = threadIdx.x;
    const int lane = tid & 31;
    const int w    = tid >> 5;
    const int g    = lane >> 2, tq = lane & 3;
    const int rank = blockIdx.x & 1;
    const int dir  = blockIdx.z;
    const int nb0  = blockIdx.y * 16;
    const float* Whh = dir ? Whhb : Whhf;
    const __nv_bfloat16* G = g_G + (size_t)dir*65536*512;

    uint32_t wb[4][16][2];
    #pragma unroll
    for (int fj = 0; fj < 4; fj++) {
        int rl = w*32 + fj*8 + g;
        int grow = (rl >> 6)*128 + rank*64 + (rl & 63);
        const float* wr = Whh + (size_t)grow*128;
        #pragma unroll
        for (int kt = 0; kt < 16; kt++) {
            wb[fj][kt][0] = f2tf(wr[kt*8 + tq]);
            wb[fj][kt][1] = f2tf(wr[kt*8 + tq + 4]);
        }
    }

    for (int idx = tid; idx < 2*16*132; idx += 256) hbuf[idx] = 0.f;

    uint32_t hbuf_u32;
    { uint64_t tmp;
      asm("cvta.to.shared.u64 %0, %1;" : "=l"(tmp) : "l"((float*)hbuf));
      hbuf_u32 = (uint32_t)tmp; }

    asm volatile("barrier.cluster.arrive.aligned;\n\tbarrier.cluster.wait.aligned;" ::: "memory");

    const int j    = tid & 63;
    const int bq   = tid >> 6;
    const int gcol = rank*64 + j;
    const int peer = rank ^ 1;
    float c[4] = {0.f, 0.f, 0.f, 0.f};

    float Gc[4][4], Gn[4][4];
    {
        int t0 = dir ? 255 : 0;
        #pragma unroll
        for (int mm = 0; mm < 4; mm++)
            #pragma unroll
            for (int gt = 0; gt < 4; gt++)
                Gc[mm][gt] = __bfloat162float(G[((size_t)t0*256 + nb0 + bq*4 + mm)*512 + gt*128 + gcol]);
    }

    for (int s = 0; s < 256; s++) {
        const int t   = dir ? (255 - s) : s;
        const int cur = s & 1, nxt = cur ^ 1;

        float acc[4][4];
        #pragma unroll
        for (int fj = 0; fj < 4; fj++)
            #pragma unroll
            for (int q = 0; q < 4; q++) acc[fj][q] = 0.f;

        const float* hb = hbuf + cur*16*132;
        #pragma unroll
        for (int kt = 0; kt < 16; kt++) {
            uint32_t a[4];
            const int k0 = kt*8;
            a[0] = f2tf(hb[(g  )*132 + k0 + tq]);
            a[1] = f2tf(hb[(g+8)*132 + k0 + tq]);
            a[2] = f2tf(hb[(g  )*132 + k0 + tq + 4]);
            a[3] = f2tf(hb[(g+8)*132 + k0 + tq + 4]);
            #pragma unroll
            for (int fj = 0; fj < 4; fj++)
                mma_tf32(acc[fj], a, wb[fj][kt]);
        }
        #pragma unroll
        for (int fj = 0; fj < 4; fj++) {
            int nloc = w*32 + fj*8 + 2*tq;
            *(float2*)&zsm[g  ][nloc] = make_float2(acc[fj][0], acc[fj][1]);
            *(float2*)&zsm[g+8][nloc] = make_float2(acc[fj][2], acc[fj][3]);
        }
        __syncthreads();

        if (s < 255) {
            int tn = dir ? (254 - s) : (s + 1);
            #pragma unroll
            for (int mm = 0; mm < 4; mm++)
                #pragma unroll
                for (int gt = 0; gt < 4; gt++)
                    Gn[mm][gt] = __bfloat162float(G[((size_t)tn*256 + nb0 + bq*4 + mm)*512 + gt*128 + gcol]);
        }

        #pragma unroll
        for (int mm = 0; mm < 4; mm++) {
            int m = bq*4 + mm;
            float ai = zsm[m][0*64 + j] + Gc[mm][0];
            float af = zsm[m][1*64 + j] + Gc[mm][1];
            float ag = zsm[m][2*64 + j] + Gc[mm][2];
            float ao = zsm[m][3*64 + j] + Gc[mm][3];
            float iv = sigf(ai);
            float fv = sigf(af);
            float gv = tanhf(ag);
            float ov = sigf(ao);
            c[mm] = fv*c[mm] + iv*gv;
            float hv = ov * tanhf(c[mm]);
            g_hcat[(size_t)(nb0+m)*65536 + t*256 + dir*128 + gcol] = hv;
            int off = (nxt*16 + m)*132 + gcol;
            hbuf[off] = hv;
            uint32_t raddr;
            asm volatile("mapa.shared::cluster.u32 %0, %1, %2;"
                         : "=r"(raddr) : "r"(hbuf_u32 + (uint32_t)off*4u), "r"(peer));
            asm volatile("st.shared::cluster.f32 [%0], %1;" :: "r"(raddr), "f"(hv) : "memory");
        }
        #pragma unroll
        for (int mm = 0; mm < 4; mm++)
            #pragma unroll
            for (int gt = 0; gt < 4; gt++) Gc[mm][gt] = Gn[mm][gt];
        asm volatile("barrier.cluster.arrive.aligned;\n\tbarrier.cluster.wait.aligned;" ::: "memory");
    }
}

// ---------------------------------------------------------------------------
// FC1 split-K partials, tf32 mma. Full M=256 per block, BN=128(all),
// K-chunk = 512, grid = 128 chunks. Reads hcat + fc1_w exactly once.
// 8 warps: 2 m-warps (128 rows each, MFR=8) x 4 n-warps (32 cols).
// ---------------------------------------------------------------------------
__global__ void fc1_mma_k(const float* __restrict__ fw)
{
    extern __shared__ uint32_t fsm[];
    uint32_t (*As)[36] = (uint32_t(*)[36])fsm;            // [256][36]
    uint32_t (*Bs)[36] = (uint32_t(*)[36])(fsm + 256*36); // [128][36]

    const int tid  = threadIdx.x;
    const int lane = tid & 31;
    const int wid  = tid >> 5;
    const int g    = lane >> 2, tq = lane & 3;
    const int wm0  = (wid & 1) * 128;
    const int wn0  = (wid >> 1) * 32;
    const int k0   = blockIdx.x * 512;

    float acc[8][4][4];
    #pragma unroll
    for (int i = 0; i < 8; i++)
        #pragma unroll
        for (int j = 0; j < 4; j++)
            #pragma unroll
            for (int q = 0; q < 4; q++) acc[i][j][q] = 0.f;

    for (int kt = 0; kt < 512; kt += 32) {
        #pragma unroll
        for (int i = 0; i < 8; i++) {        // A: 256 x 32
            int l = i*256 + tid;
            int m = l >> 3, kq = l & 7;
            float4 v = *(const float4*)(g_hcat + (size_t)m*65536 + k0 + kt + kq*4);
            As[m][kq*4+0]=f2tf(v.x); As[m][kq*4+1]=f2tf(v.y);
            As[m][kq*4+2]=f2tf(v.z); As[m][kq*4+3]=f2tf(v.w);
        }
        #pragma unroll
        for (int i = 0; i < 4; i++) {        // B: 128 x 32
            int l = i*256 + tid;
            int n = l >> 3, kq = l & 7;
            float4 u = *(const float4*)(fw + (size_t)n*65536 + k0 + kt + kq*4);
            Bs[n][kq*4+0]=f2tf(u.x); Bs[n][kq*4+1]=f2tf(u.y);
            Bs[n][kq*4+2]=f2tf(u.z); Bs[n][kq*4+3]=f2tf(u.w);
        }
        __syncthreads();
        #pragma unroll
        for (int k8 = 0; k8 < 32; k8 += 8) {
            uint32_t a[8][4], b[4][2];
            #pragma unroll
            for (int fi = 0; fi < 8; fi++) {
                int r = wm0 + fi*16;
                a[fi][0] = As[r+g  ][k8+tq];
                a[fi][1] = As[r+g+8][k8+tq];
                a[fi][2] = As[r+g  ][k8+tq+4];
                a[fi][3] = As[r+g+8][k8+tq+4];
            }
            #pragma unroll
            for (int fj = 0; fj < 4; fj++) {
                int cn = wn0 + fj*8 + g;
                b[fj][0] = Bs[cn][k8+tq];
                b[fj][1] = Bs[cn][k8+tq+4];
            }
            #pragma unroll
            for (int fi = 0; fi < 8; fi++)
                #pragma unroll
                for (int fj = 0; fj < 4; fj++)
                    mma_tf32(acc[fi][fj], a[fi], b[fj]);
        }
        __syncthreads();
    }

    float* part = g_fc1part + (size_t)blockIdx.x*256*128;
    #pragma unroll
    for (int fj = 0; fj < 4; fj++) {
        int n0 = wn0 + fj*8 + 2*tq;
        #pragma unroll
        for (int fi = 0; fi < 8; fi++) {
            #pragma unroll
            for (int p = 0; p < 2; p++) {
                int m = wm0 + fi*16 + g + p*8;
                *(float2*)(part + (size_t)m*128 + n0) =
                    make_float2(acc[fi][fj][p*2+0], acc[fi][fj][p*2+1]);
            }
        }
    }
}

__global__ void fc1_reduce_k(const float* __restrict__ fc1b)
{
    int idx = blockIdx.x*256 + threadIdx.x;
    int m = idx >> 7, h = idx & 127;
    float s = fc1b[h];
    #pragma unroll 8
    for (int kc = 0; kc < 128; kc++)
        s += g_fc1part[((size_t)kc*256 + m)*128 + h];
    g_z1[(size_t)m*128 + h] = fmaxf(s, 0.f);
}

__global__ void score_k(const float* __restrict__ fsw, const float* __restrict__ fsb,
                        float* __restrict__ out)
{
    __shared__ float w[128];
    __shared__ float fr[256];
    int tid = threadIdx.x;
    if (tid < 128) w[tid] = fsw[tid];
    __syncthreads();
    float acc = fsb[0];
    #pragma unroll 8
    for (int h = 0; h < 128; h++) acc += g_z1[(size_t)tid*128 + h] * w[h];
    float sc = 1.f / (1.f + expf(-acc)) * 4.f + 1.f;
    out[16 + tid] = sc;
    fr[tid] = sc;
    __syncthreads();
    if (tid < 16) {
        float s = 0.f;
        #pragma unroll
        for (int f = 0; f < 16; f++) s += fr[tid*16 + f];
        out[tid] = s * (1.f/16.f);
    }
}

// ---------------------------------------------------------------------------
extern "C" void kernel_launch(void* const* d_in, const int* in_sizes, int n_in,
                              void* d_out, int out_size)
{
    const float *audio,*w0,*b0,*w1,*b1,*w2,*b2,*w3,*b3;
    const float *Wihf,*Whhf,*bihf,*bhhf,*Wihb,*Whhb,*bihb,*bhhb;
    const float *fc1w,*fc1b,*fsw,*fsb;
    if (n_in >= 22 && in_sizes[1] == 144) {
        audio=(const float*)d_in[0];
        w0=(const float*)d_in[1];  b0=(const float*)d_in[2];
        w1=(const float*)d_in[3];  b1=(const float*)d_in[4];
        w2=(const float*)d_in[5];  b2=(const float*)d_in[6];
        w3=(const float*)d_in[7];  b3=(const float*)d_in[8];
        Wihf=(const float*)d_in[9];  Whhf=(const float*)d_in[10];
        bihf=(const float*)d_in[11]; bhhf=(const float*)d_in[12];
        Wihb=(const float*)d_in[13]; Whhb=(const float*)d_in[14];
        bihb=(const float*)d_in[15]; bhhb=(const float*)d_in[16];
        fc1w=(const float*)d_in[17]; fc1b=(const float*)d_in[18];
        fsw=(const float*)d_in[19];  fsb=(const float*)d_in[20];
    } else {
        audio=(const float*)d_in[0];
        w0=(const float*)d_in[2];  b0=(const float*)d_in[3];
        w1=(const float*)d_in[4];  b1=(const float*)d_in[5];
        w2=(const float*)d_in[6];  b2=(const float*)d_in[7];
        w3=(const float*)d_in[8];  b3=(const float*)d_in[9];
        Wihf=(const float*)d_in[10]; Whhf=(const float*)d_in[11];
        bihf=(const float*)d_in[12]; bhhf=(const float*)d_in[13];
        Wihb=(const float*)d_in[14]; Whhb=(const float*)d_in[15];
        bihb=(const float*)d_in[16]; bhhb=(const float*)d_in[17];
        fc1w=(const float*)d_in[18]; fc1b=(const float*)d_in[19];
        fsw=(const float*)d_in[20];  fsb=(const float*)d_in[21];
    }

    float *x0,*x1,*x2,*xT,*wT1,*wT2,*wT3;
    cudaGetSymbolAddress((void**)&x0, g_x0);
    cudaGetSymbolAddress((void**)&x1, g_x1);
    cudaGetSymbolAddress((void**)&x2, g_x2);
    cudaGetSymbolAddress((void**)&xT, g_xT);
    cudaGetSymbolAddress((void**)&wT1, g_wT1);
    cudaGetSymbolAddress((void**)&wT2, g_wT2);
    cudaGetSymbolAddress((void**)&wT3, g_wT3);

    // conv_mma dynamic smem: (128 + COUT) * (CIN+4) * 4 bytes
    const int sc1 = (128 + 32) * (16 + 4) * 4;
    const int sc2 = (128 + 64) * (32 + 4) * 4;
    const int sc3 = (128 +128) * (64 + 4) * 4;
    const int sf  = (256 + 128) * 36 * 4;        // 55.3 KB
    cudaFuncSetAttribute(conv_mma_k<16, 32,27,9,false>, cudaFuncAttributeMaxDynamicSharedMemorySize, sc1);
    cudaFuncSetAttribute(conv_mma_k<32, 64, 9,3,false>, cudaFuncAttributeMaxDynamicSharedMemorySize, sc2);
    cudaFuncSetAttribute(conv_mma_k<64,128, 3,1,true >, cudaFuncAttributeMaxDynamicSharedMemorySize, sc3);
    cudaFuncSetAttribute(fc1_mma_k, cudaFuncAttributeMaxDynamicSharedMemorySize, sf);

    // weight transforms (tiny)
    wtrans_k<<<(9*16*32 + 255)/256, 256>>>(w1, wT1, 16, 32);
    wtrans_k<<<(9*32*64 + 255)/256, 256>>>(w2, wT2, 32, 64);
    wtrans_k<<<(9*64*128+ 255)/256, 256>>>(w3, wT3, 64, 128);

    // conv stack (NHWC)
    conv0_k<<<(BF*NT*27)/256, 256>>>(audio, w0, b0, x0);
    conv_mma_k<16, 32,27,9,false><<<dim3(2,9,BF), 256, sc1>>>(x0, wT1, b1, x1);
    conv_mma_k<32, 64, 9,3,false><<<dim3(2,3,BF), 256, sc2>>>(x1, wT2, b2, x2);
    conv_mma_k<64,128, 3,1,true ><<<dim3(2,1,BF), 256, sc3>>>(x2, wT3, b3, xT);

    gemm_xw_k<<<dim3(4,512,2), 256>>>(xT, Wihf, Wihb, bihf, bhhf, bihb, bhhb);

    lstm_k<<<dim3(2,16,2), 256>>>(Whhf, Whhb);

    fc1_mma_k<<<128, 256, sf>>>(fc1w);
    fc1_reduce_k<<<128, 256>>>(fc1b);
    score_k<<<1, 256>>>(fsw, fsb, (float*)d_out);
}

// round 9
// speedup vs baseline: 3.5441x; 1.2714x over previous
#include <cuda_runtime.h>
#include <cuda_bf16.h>
#include <cstdint>
#include <math.h>

// ---------------------------------------------------------------------------
// Static scratch (no allocations allowed). All intermediates bf16.
// ---------------------------------------------------------------------------
#define BF 256          // B*F = 16*16 frame windows
#define NT 256          // frames per window (time)
__device__ __align__(16) __nv_bfloat16 g_x0[(size_t)BF*NT*27*16];
__device__ __align__(16) __nv_bfloat16 g_x1[(size_t)BF*NT*9*32];
__device__ __align__(16) __nv_bfloat16 g_x2[(size_t)BF*NT*3*64];
__device__ __align__(16) __nv_bfloat16 g_xT[(size_t)NT*BF*128];     // [t][n][c]
__device__ __align__(16) __nv_bfloat16 g_G[(size_t)2*65536*512];
__device__ __align__(16) __nv_bfloat16 g_hcat[(size_t)BF*65536];
__device__ __align__(16) float g_fc1part[(size_t)128*256*128];
__device__ __align__(16) float g_z1[(size_t)256*128];
__device__ __align__(16) __nv_bfloat16 g_wT1[9*32*16];              // [tap][co][ci]
__device__ __align__(16) __nv_bfloat16 g_wT2[9*64*32];
__device__ __align__(16) __nv_bfloat16 g_wT3[9*128*64];

// ---------------------------------------------------------------------------
// helpers
// ---------------------------------------------------------------------------
__device__ __forceinline__ uint32_t packbf(float lo, float hi)
{
    __nv_bfloat162 h = __floats2bfloat162_rn(lo, hi);
    return *(uint32_t*)&h;
}
__device__ __forceinline__ void mma_bf16(float* d, const uint32_t* a, const uint32_t* b)
{
    asm("mma.sync.aligned.m16n8k16.row.col.f32.bf16.bf16.f32 "
        "{%0,%1,%2,%3}, {%4,%5,%6,%7}, {%8,%9}, {%0,%1,%2,%3};"
        : "+f"(d[0]), "+f"(d[1]), "+f"(d[2]), "+f"(d[3])
        : "r"(a[0]), "r"(a[1]), "r"(a[2]), "r"(a[3]), "r"(b[0]), "r"(b[1]));
}

// ---------------------------------------------------------------------------
// Weight transform (all three convs in one launch):
// w[co][ci][kh][kw] (fp32) -> wT[tap][co][ci] (bf16)
// ---------------------------------------------------------------------------
__global__ void wtrans_k(const float* __restrict__ w1, const float* __restrict__ w2,
                         const float* __restrict__ w3)
{
    int idx = blockIdx.x*256 + threadIdx.x;
    const float* w; __nv_bfloat16* wT; int CIN, COUT;
    if (idx < 4608)        { w = w1; wT = g_wT1; CIN = 16; COUT = 32; }
    else if (idx < 23040)  { w = w2; wT = g_wT2; CIN = 32; COUT = 64; idx -= 4608; }
    else if (idx < 96768)  { w = w3; wT = g_wT3; CIN = 64; COUT = 128; idx -= 23040; }
    else return;
    int ci  = idx % CIN;
    int r   = idx / CIN;
    int co  = r % COUT;
    int tap = r / COUT;
    wT[idx + 0] = __float2bfloat16(w[(co*CIN + ci)*9 + tap]);
}

// ---------------------------------------------------------------------------
// conv0: CIN=1 -> 16, direct. out NHWC bf16 [bf][t][27][16].
// ---------------------------------------------------------------------------
__global__ void conv0_k(const float* __restrict__ audio, const float* __restrict__ w,
                        const float* __restrict__ bias, __nv_bfloat16* __restrict__ out)
{
    __shared__ float wsm[9][16];
    __shared__ float bsm[16];
    int tid = threadIdx.x;
    if (tid < 144) wsm[tid % 9][tid / 9] = w[tid];
    if (tid < 16)  bsm[tid] = bias[tid];
    __syncthreads();

    size_t idx = (size_t)blockIdx.x*256 + tid;   // (bf, t, wo)
    int wo = (int)(idx % 27);
    size_t r = idx / 27;
    int t  = (int)(r % NT);
    int bf = (int)(r / NT);

    float acc[16];
    #pragma unroll
    for (int co = 0; co < 16; co++) acc[co] = bsm[co];

    #pragma unroll
    for (int kh = 0; kh < 3; kh++) {
        int ti = t + kh - 1;
        if (ti < 0 || ti >= NT) continue;
        #pragma unroll
        for (int kw = 0; kw < 3; kw++) {
            int wc = 3*wo + kw - 1;
            if (wc < 0 || wc >= 81) continue;
            float v = audio[((size_t)bf*NT + ti)*81 + wc];
            #pragma unroll
            for (int co = 0; co < 16; co++) acc[co] += v * wsm[kh*3+kw][co];
        }
    }
    uint32_t* o = (uint32_t*)(out + idx*16);
    #pragma unroll
    for (int q = 0; q < 8; q++)
        o[q] = packbf(fmaxf(acc[q*2+0], 0.f), fmaxf(acc[q*2+1], 0.f));
}

// ---------------------------------------------------------------------------
// Implicit-GEMM conv, bf16 m16n8k16 mma. Block = (t-tile 128, wo, bf).
// smem holds packed bf16 pairs as uint32: LDA = CIN/2 + 4 (uint32 units).
// ---------------------------------------------------------------------------
template<int CIN,int COUT,int WIN,int WOUT,bool TOUT>
__global__ void conv_mma_k(const __nv_bfloat16* __restrict__ x,
                           const __nv_bfloat16* __restrict__ wT,
                           const float* __restrict__ bias,
                           __nv_bfloat16* __restrict__ out)
{
    constexpr int NWN = COUT/32;
    constexpr int WMW = 8/NWN;
    constexpr int MFR = 128/WMW/16;
    constexpr int LDA = CIN/2 + 4;       // uint32 (bf16-pair) units
    constexpr int NK16 = CIN/16;
    extern __shared__ uint32_t dynsm[];
    uint32_t* As = dynsm;                // [128][LDA]
    uint32_t* Bs = dynsm + 128*LDA;      // [COUT][LDA]

    const int tid  = threadIdx.x;
    const int lane = tid & 31;
    const int wid  = tid >> 5;
    const int g    = lane >> 2, tq = lane & 3;
    const int wm0  = (wid % WMW) * (128/WMW);
    const int wn0  = (wid / WMW) * 32;
    const int t0   = blockIdx.x * 128;
    const int wo   = blockIdx.y;
    const int bf   = blockIdx.z;

    float acc[MFR][4][4];
    #pragma unroll
    for (int i = 0; i < MFR; i++)
        #pragma unroll
        for (int j = 0; j < 4; j++)
            #pragma unroll
            for (int q = 0; q < 4; q++) acc[i][j][q] = 0.f;

    #pragma unroll
    for (int kh = 0; kh < 3; kh++) {
        #pragma unroll
        for (int kw = 0; kw < 3; kw++) {
            const int wc = 3*wo + kw - 1;
            if (wc < 0 || wc >= WIN) continue;
            const int tap = kh*3 + kw;
            // A fill: 128 rows x CIN bf16, pure uint4 copies
            for (int l = tid; l < 128*(CIN/8); l += 256) {
                int m = l / (CIN/8), kq = l % (CIN/8);
                int t_in = t0 + m + kh - 1;
                uint4 v = make_uint4(0u,0u,0u,0u);
                if (t_in >= 0 && t_in < NT)
                    v = *(const uint4*)(x + (((size_t)bf*NT + t_in)*WIN + wc)*CIN + kq*8);
                *(uint4*)(As + m*LDA + kq*4) = v;
            }
            // B fill: COUT rows x CIN bf16, uint4 copies
            const __nv_bfloat16* wtap = wT + (size_t)tap*COUT*CIN;
            for (int l = tid; l < COUT*(CIN/8); l += 256) {
                int co = l / (CIN/8), kq = l % (CIN/8);
                *(uint4*)(Bs + co*LDA + kq*4) = *(const uint4*)(wtap + co*CIN + kq*8);
            }
            __syncthreads();
            #pragma unroll
            for (int k16 = 0; k16 < NK16; k16++) {
                const int kp = k16*8;
                uint32_t a[MFR][4], b[4][2];
                #pragma unroll
                for (int fi = 0; fi < MFR; fi++) {
                    int r = wm0 + fi*16;
                    a[fi][0] = As[(r+g  )*LDA + kp + tq];
                    a[fi][1] = As[(r+g+8)*LDA + kp + tq];
                    a[fi][2] = As[(r+g  )*LDA + kp + tq + 4];
                    a[fi][3] = As[(r+g+8)*LDA + kp + tq + 4];
                }
                #pragma unroll
                for (int fj = 0; fj < 4; fj++) {
                    int cn = wn0 + fj*8 + g;
                    b[fj][0] = Bs[cn*LDA + kp + tq];
                    b[fj][1] = Bs[cn*LDA + kp + tq + 4];
                }
                #pragma unroll
                for (int fi = 0; fi < MFR; fi++)
                    #pragma unroll
                    for (int fj = 0; fj < 4; fj++)
                        mma_bf16(acc[fi][fj], a[fi], b[fj]);
            }
            __syncthreads();
        }
    }

    #pragma unroll
    for (int fj = 0; fj < 4; fj++) {
        int co0 = wn0 + fj*8 + 2*tq;
        float bv0 = bias[co0], bv1 = bias[co0+1];
        #pragma unroll
        for (int fi = 0; fi < MFR; fi++) {
            #pragma unroll
            for (int p = 0; p < 2; p++) {
                int m = wm0 + fi*16 + g + p*8;
                uint32_t v = packbf(fmaxf(acc[fi][fj][p*2+0] + bv0, 0.f),
                                    fmaxf(acc[fi][fj][p*2+1] + bv1, 0.f));
                size_t base;
                if (TOUT) base = ((size_t)(t0+m)*BF + bf)*COUT + co0;
                else      base = (((size_t)bf*NT + (t0+m))*WOUT + wo)*COUT + co0;
                *(uint32_t*)(out + base) = v;
            }
        }
    }
}

// ---------------------------------------------------------------------------
// Input-projection GEMM, bf16 mma: G = X @ W^T + bias. X bf16, W fp32->cvt.
// BM=BN=128, BK=32 (16 pairs). 8 warps (2m x 4n).
// ---------------------------------------------------------------------------
__global__ void gemm_xw_k(const __nv_bfloat16* __restrict__ X,
                          const float* __restrict__ Wf, const float* __restrict__ Wb,
                          const float* __restrict__ bihf, const float* __restrict__ bhhf,
                          const float* __restrict__ bihb, const float* __restrict__ bhhb)
{
    const int dir = blockIdx.z;
    const float* W  = dir ? Wb   : Wf;
    const float* b1 = dir ? bihb : bihf;
    const float* b2 = dir ? bhhb : bhhf;
    __nv_bfloat16* out = g_G + (size_t)dir*65536*512;

    __shared__ uint32_t As[128][20];   // 16 pairs + pad
    __shared__ uint32_t Bs[128][20];

    const int tid  = threadIdx.x;
    const int lane = tid & 31;
    const int wid  = tid >> 5;
    const int g    = lane >> 2, tq = lane & 3;
    const int wm0  = (wid & 1) * 64;
    const int wn0  = (wid >> 1) * 32;
    const int m0   = blockIdx.y * 128, n0 = blockIdx.x * 128;

    float acc[4][4][4];
    #pragma unroll
    for (int i = 0; i < 4; i++)
        #pragma unroll
        for (int j = 0; j < 4; j++)
            #pragma unroll
            for (int q = 0; q < 4; q++) acc[i][j][q] = 0.f;

    for (int kt = 0; kt < 128; kt += 32) {
        #pragma unroll
        for (int i = 0; i < 2; i++) {        // A: 128 x 32 bf16 = 512 uint4
            int l = i*256 + tid;
            int m = l >> 2, kq = l & 3;
            *(uint4*)(&As[m][kq*4]) =
                *(const uint4*)(X + (size_t)(m0+m)*128 + kt + kq*8);
        }
        #pragma unroll
        for (int i = 0; i < 4; i++) {        // B: 128 x 32 fp32 -> cvt
            int l = i*256 + tid;
            int n = l >> 3, kq = l & 7;
            float4 u = *(const float4*)(W + (size_t)(n0+n)*128 + kt + kq*4);
            Bs[n][kq*2+0] = packbf(u.x, u.y);
            Bs[n][kq*2+1] = packbf(u.z, u.w);
        }
        __syncthreads();
        #pragma unroll
        for (int k16 = 0; k16 < 2; k16++) {
            const int kp = k16*8;
            uint32_t a[4][4], b[4][2];
            #pragma unroll
            for (int fi = 0; fi < 4; fi++) {
                int r = wm0 + fi*16;
                a[fi][0] = As[r+g  ][kp+tq];
                a[fi][1] = As[r+g+8][kp+tq];
                a[fi][2] = As[r+g  ][kp+tq+4];
                a[fi][3] = As[r+g+8][kp+tq+4];
            }
            #pragma unroll
            for (int fj = 0; fj < 4; fj++) {
                int cn = wn0 + fj*8 + g;
                b[fj][0] = Bs[cn][kp+tq];
                b[fj][1] = Bs[cn][kp+tq+4];
            }
            #pragma unroll
            for (int fi = 0; fi < 4; fi++)
                #pragma unroll
                for (int fj = 0; fj < 4; fj++)
                    mma_bf16(acc[fi][fj], a[fi], b[fj]);
        }
        __syncthreads();
    }

    #pragma unroll
    for (int fj = 0; fj < 4; fj++) {
        int gate0 = n0 + wn0 + fj*8 + 2*tq;
        float bv0 = b1[gate0]   + b2[gate0];
        float bv1 = b1[gate0+1] + b2[gate0+1];
        #pragma unroll
        for (int fi = 0; fi < 4; fi++) {
            #pragma unroll
            for (int p = 0; p < 2; p++) {
                int m = m0 + wm0 + fi*16 + g + p*8;
                *(uint32_t*)(out + (size_t)m*512 + gate0) =
                    packbf(acc[fi][fj][p*2+0] + bv0, acc[fi][fj][p*2+1] + bv1);
            }
        }
    }
}

// ---------------------------------------------------------------------------
// LSTM recurrence, bf16 tensor-core edition. Whh fragments in registers
// (64 regs/thread). h ring buffer in smem as bf16. 1 cluster barrier/step.
// ---------------------------------------------------------------------------
__device__ __forceinline__ float sigf(float x) { return 1.f / (1.f + expf(-x)); }

__global__ void __cluster_dims__(2,1,1) __launch_bounds__(256,1)
lstm_k(const float* __restrict__ Whhf, const float* __restrict__ Whhb)
{
    __shared__ __nv_bfloat16 hbuf[2*16*136];  // [buf][batch][128+8]
    __shared__ float zsm[16][258];

    const int tid  = threadIdx.x;
    const int lane = tid & 31;
    const int w    = tid >> 5;
    const int g    = lane >> 2, tq = lane & 3;
    const int rank = blockIdx.x & 1;
    const int dir  = blockIdx.z;
    const int nb0  = blockIdx.y * 16;
    const float* Whh = dir ? Whhb : Whhf;
    const __nv_bfloat16* G = g_G + (size_t)dir*65536*512;

    // Whh bf16 fragments, K=128 -> 8 k16 tiles
    uint32_t wb[4][8][2];
    #pragma unroll
    for (int fj = 0; fj < 4; fj++) {
        int rl = w*32 + fj*8 + g;
        int grow = (rl >> 6)*128 + rank*64 + (rl & 63);
        const float* wr = Whh + (size_t)grow*128;
        #pragma unroll
        for (int kt = 0; kt < 8; kt++) {
            wb[fj][kt][0] = packbf(wr[kt*16 + 2*tq    ], wr[kt*16 + 2*tq + 1]);
            wb[fj][kt][1] = packbf(wr[kt*16 + 2*tq + 8], wr[kt*16 + 2*tq + 9]);
        }
    }

    {
        uint32_t* hz = (uint32_t*)hbuf;
        for (int idx = tid; idx < 2*16*136/2; idx += 256) hz[idx] = 0u;
    }

    uint32_t hbuf_u32;
    { uint64_t tmp;
      asm("cvta.to.shared.u64 %0, %1;" : "=l"(tmp) : "l"((__nv_bfloat16*)hbuf));
      hbuf_u32 = (uint32_t)tmp; }

    asm volatile("barrier.cluster.arrive.aligned;\n\tbarrier.cluster.wait.aligned;" ::: "memory");

    const int j    = tid & 63;
    const int bq   = tid >> 6;
    const int gcol = rank*64 + j;
    const int peer = rank ^ 1;
    float c[4] = {0.f, 0.f, 0.f, 0.f};

    float Gc[4][4], Gn[4][4];
    {
        int t0 = dir ? 255 : 0;
        #pragma unroll
        for (int mm = 0; mm < 4; mm++)
            #pragma unroll
            for (int gt = 0; gt < 4; gt++)
                Gc[mm][gt] = __bfloat162float(G[((size_t)t0*256 + nb0 + bq*4 + mm)*512 + gt*128 + gcol]);
    }

    for (int s = 0; s < 256; s++) {
        const int t   = dir ? (255 - s) : s;
        const int cur = s & 1, nxt = cur ^ 1;

        // phase A: Z = h @ Whh_cta^T (bf16 mma, 32 mma/warp)
        float acc[4][4];
        #pragma unroll
        for (int fj = 0; fj < 4; fj++)
            #pragma unroll
            for (int q = 0; q < 4; q++) acc[fj][q] = 0.f;

        const uint32_t* hb = (const uint32_t*)(hbuf + cur*16*136);  // row stride 68 u32
        #pragma unroll
        for (int kt = 0; kt < 8; kt++) {
            const int kp = kt*8;
            uint32_t a[4];
            a[0] = hb[(g  )*68 + kp + tq];
            a[1] = hb[(g+8)*68 + kp + tq];
            a[2] = hb[(g  )*68 + kp + tq + 4];
            a[3] = hb[(g+8)*68 + kp + tq + 4];
            #pragma unroll
            for (int fj = 0; fj < 4; fj++)
                mma_bf16(acc[fj], a, wb[fj][kt]);
        }
        #pragma unroll
        for (int fj = 0; fj < 4; fj++) {
            int nloc = w*32 + fj*8 + 2*tq;
            *(float2*)&zsm[g  ][nloc] = make_float2(acc[fj][0], acc[fj][1]);
            *(float2*)&zsm[g+8][nloc] = make_float2(acc[fj][2], acc[fj][3]);
        }
        __syncthreads();

        if (s < 255) {
            int tn = dir ? (254 - s) : (s + 1);
            #pragma unroll
            for (int mm = 0; mm < 4; mm++)
                #pragma unroll
                for (int gt = 0; gt < 4; gt++)
                    Gn[mm][gt] = __bfloat162float(G[((size_t)tn*256 + nb0 + bq*4 + mm)*512 + gt*128 + gcol]);
        }

        // phase B: gate combine + state update (4 batches/thread)
        #pragma unroll
        for (int mm = 0; mm < 4; mm++) {
            int m = bq*4 + mm;
            float ai = zsm[m][0*64 + j] + Gc[mm][0];
            float af = zsm[m][1*64 + j] + Gc[mm][1];
            float ag = zsm[m][2*64 + j] + Gc[mm][2];
            float ao = zsm[m][3*64 + j] + Gc[mm][3];
            float iv = sigf(ai);
            float fv = sigf(af);
            float gv = tanhf(ag);
            float ov = sigf(ao);
            c[mm] = fv*c[mm] + iv*gv;
            float hv = ov * tanhf(c[mm]);
            __nv_bfloat16 hb16 = __float2bfloat16(hv);
            g_hcat[(size_t)(nb0+m)*65536 + t*256 + dir*128 + gcol] = hb16;
            int off = (nxt*16 + m)*136 + gcol;
            hbuf[off] = hb16;
            unsigned short hu = *(unsigned short*)&hb16;
            uint32_t raddr;
            asm volatile("mapa.shared::cluster.u32 %0, %1, %2;"
                         : "=r"(raddr) : "r"(hbuf_u32 + (uint32_t)off*2u), "r"(peer));
            asm volatile("st.shared::cluster.b16 [%0], %1;" :: "r"(raddr), "h"(hu) : "memory");
        }
        #pragma unroll
        for (int mm = 0; mm < 4; mm++)
            #pragma unroll
            for (int gt = 0; gt < 4; gt++) Gc[mm][gt] = Gn[mm][gt];
        asm volatile("barrier.cluster.arrive.aligned;\n\tbarrier.cluster.wait.aligned;" ::: "memory");
    }
}

// ---------------------------------------------------------------------------
// FC1 split-K, bf16 mma. M=256 full, N=128 full, K-chunk 512, 128 blocks.
// ---------------------------------------------------------------------------
__global__ void fc1_mma_k(const float* __restrict__ fw)
{
    extern __shared__ uint32_t fsm[];
    uint32_t (*As)[20] = (uint32_t(*)[20])fsm;            // [256][20]
    uint32_t (*Bs)[20] = (uint32_t(*)[20])(fsm + 256*20); // [128][20]

    const int tid  = threadIdx.x;
    const int lane = tid & 31;
    const int wid  = tid >> 5;
    const int g    = lane >> 2, tq = lane & 3;
    const int wm0  = (wid & 1) * 128;
    const int wn0  = (wid >> 1) * 32;
    const int k0   = blockIdx.x * 512;

    float acc[8][4][4];
    #pragma unroll
    for (int i = 0; i < 8; i++)
        #pragma unroll
        for (int j = 0; j < 4; j++)
            #pragma unroll
            for (int q = 0; q < 4; q++) acc[i][j][q] = 0.f;

    for (int kt = 0; kt < 512; kt += 32) {
        #pragma unroll
        for (int i = 0; i < 4; i++) {        // A: 256 x 32 bf16 = 1024 uint4 copies
            int l = i*256 + tid;
            int m = l >> 2, kq = l & 3;
            *(uint4*)(&As[m][kq*4]) =
                *(const uint4*)(g_hcat + (size_t)m*65536 + k0 + kt + kq*8);
        }
        #pragma unroll
        for (int i = 0; i < 4; i++) {        // B: 128 x 32 fp32 -> cvt
            int l = i*256 + tid;
            int n = l >> 3, kq = l & 7;
            float4 u = *(const float4*)(fw + (size_t)n*65536 + k0 + kt + kq*4);
            Bs[n][kq*2+0] = packbf(u.x, u.y);
            Bs[n][kq*2+1] = packbf(u.z, u.w);
        }
        __syncthreads();
        #pragma unroll
        for (int k16 = 0; k16 < 2; k16++) {
            const int kp = k16*8;
            uint32_t a[8][4], b[4][2];
            #pragma unroll
            for (int fi = 0; fi < 8; fi++) {
                int r = wm0 + fi*16;
                a[fi][0] = As[r+g  ][kp+tq];
                a[fi][1] = As[r+g+8][kp+tq];
                a[fi][2] = As[r+g  ][kp+tq+4];
                a[fi][3] = As[r+g+8][kp+tq+4];
            }
            #pragma unroll
            for (int fj = 0; fj < 4; fj++) {
                int cn = wn0 + fj*8 + g;
                b[fj][0] = Bs[cn][kp+tq];
                b[fj][1] = Bs[cn][kp+tq+4];
            }
            #pragma unroll
            for (int fi = 0; fi < 8; fi++)
                #pragma unroll
                for (int fj = 0; fj < 4; fj++)
                    mma_bf16(acc[fi][fj], a[fi], b[fj]);
        }
        __syncthreads();
    }

    float* part = g_fc1part + (size_t)blockIdx.x*256*128;
    #pragma unroll
    for (int fj = 0; fj < 4; fj++) {
        int n0 = wn0 + fj*8 + 2*tq;
        #pragma unroll
        for (int fi = 0; fi < 8; fi++) {
            #pragma unroll
            for (int p = 0; p < 2; p++) {
                int m = wm0 + fi*16 + g + p*8;
                *(float2*)(part + (size_t)m*128 + n0) =
                    make_float2(acc[fi][fj][p*2+0], acc[fi][fj][p*2+1]);
            }
        }
    }
}

__global__ void fc1_reduce_k(const float* __restrict__ fc1b)
{
    int idx = blockIdx.x*256 + threadIdx.x;
    int m = idx >> 7, h = idx & 127;
    float s = fc1b[h];
    #pragma unroll 8
    for (int kc = 0; kc < 128; kc++)
        s += g_fc1part[((size_t)kc*256 + m)*128 + h];
    g_z1[(size_t)m*128 + h] = fmaxf(s, 0.f);
}

__global__ void score_k(const float* __restrict__ fsw, const float* __restrict__ fsb,
                        float* __restrict__ out)
{
    __shared__ float w[128];
    __shared__ float fr[256];
    int tid = threadIdx.x;
    if (tid < 128) w[tid] = fsw[tid];
    __syncthreads();
    float acc = fsb[0];
    #pragma unroll 8
    for (int h = 0; h < 128; h++) acc += g_z1[(size_t)tid*128 + h] * w[h];
    float sc = 1.f / (1.f + expf(-acc)) * 4.f + 1.f;
    out[16 + tid] = sc;
    fr[tid] = sc;
    __syncthreads();
    if (tid < 16) {
        float s = 0.f;
        #pragma unroll
        for (int f = 0; f < 16; f++) s += fr[tid*16 + f];
        out[tid] = s * (1.f/16.f);
    }
}

// ---------------------------------------------------------------------------
extern "C" void kernel_launch(void* const* d_in, const int* in_sizes, int n_in,
                              void* d_out, int out_size)
{
    const float *audio,*w0,*b0,*w1,*b1,*w2,*b2,*w3,*b3;
    const float *Wihf,*Whhf,*bihf,*bhhf,*Wihb,*Whhb,*bihb,*bhhb;
    const float *fc1w,*fc1b,*fsw,*fsb;
    if (n_in >= 22 && in_sizes[1] == 144) {
        audio=(const float*)d_in[0];
        w0=(const float*)d_in[1];  b0=(const float*)d_in[2];
        w1=(const float*)d_in[3];  b1=(const float*)d_in[4];
        w2=(const float*)d_in[5];  b2=(const float*)d_in[6];
        w3=(const float*)d_in[7];  b3=(const float*)d_in[8];
        Wihf=(const float*)d_in[9];  Whhf=(const float*)d_in[10];
        bihf=(const float*)d_in[11]; bhhf=(const float*)d_in[12];
        Wihb=(const float*)d_in[13]; Whhb=(const float*)d_in[14];
        bihb=(const float*)d_in[15]; bhhb=(const float*)d_in[16];
        fc1w=(const float*)d_in[17]; fc1b=(const float*)d_in[18];
        fsw=(const float*)d_in[19];  fsb=(const float*)d_in[20];
    } else {
        audio=(const float*)d_in[0];
        w0=(const float*)d_in[2];  b0=(const float*)d_in[3];
        w1=(const float*)d_in[4];  b1=(const float*)d_in[5];
        w2=(const float*)d_in[6];  b2=(const float*)d_in[7];
        w3=(const float*)d_in[8];  b3=(const float*)d_in[9];
        Wihf=(const float*)d_in[10]; Whhf=(const float*)d_in[11];
        bihf=(const float*)d_in[12]; bhhf=(const float*)d_in[13];
        Wihb=(const float*)d_in[14]; Whhb=(const float*)d_in[15];
        bihb=(const float*)d_in[16]; bhhb=(const float*)d_in[17];
        fc1w=(const float*)d_in[18]; fc1b=(const float*)d_in[19];
        fsw=(const float*)d_in[20];  fsb=(const float*)d_in[21];
    }

    __nv_bfloat16 *x0,*x1,*x2,*xT,*wT1,*wT2,*wT3;
    cudaGetSymbolAddress((void**)&x0, g_x0);
    cudaGetSymbolAddress((void**)&x1, g_x1);
    cudaGetSymbolAddress((void**)&x2, g_x2);
    cudaGetSymbolAddress((void**)&xT, g_xT);
    cudaGetSymbolAddress((void**)&wT1, g_wT1);
    cudaGetSymbolAddress((void**)&wT2, g_wT2);
    cudaGetSymbolAddress((void**)&wT3, g_wT3);

    // conv_mma dynamic smem: (128 + COUT) * (CIN/2 + 4) * 4 bytes
    const int sc1 = (128 + 32) * (16/2 + 4) * 4;
    const int sc2 = (128 + 64) * (32/2 + 4) * 4;
    const int sc3 = (128 +128) * (64/2 + 4) * 4;
    const int sf  = (256 + 128) * 20 * 4;
    cudaFuncSetAttribute(conv_mma_k<16, 32,27,9,false>, cudaFuncAttributeMaxDynamicSharedMemorySize, sc1);
    cudaFuncSetAttribute(conv_mma_k<32, 64, 9,3,false>, cudaFuncAttributeMaxDynamicSharedMemorySize, sc2);
    cudaFuncSetAttribute(conv_mma_k<64,128, 3,1,true >, cudaFuncAttributeMaxDynamicSharedMemorySize, sc3);
    cudaFuncSetAttribute(fc1_mma_k, cudaFuncAttributeMaxDynamicSharedMemorySize, sf);

    wtrans_k<<<(96768 + 255)/256, 256>>>(w1, w2, w3);

    conv0_k<<<(BF*NT*27)/256, 256>>>(audio, w0, b0, x0);
    conv_mma_k<16, 32,27,9,false><<<dim3(2,9,BF), 256, sc1>>>(x0, wT1, b1, x1);
    conv_mma_k<32, 64, 9,3,false><<<dim3(2,3,BF), 256, sc2>>>(x1, wT2, b2, x2);
    conv_mma_k<64,128, 3,1,true ><<<dim3(2,1,BF), 256, sc3>>>(x2, wT3, b3, xT);

    gemm_xw_k<<<dim3(4,512,2), 256>>>(xT, Wihf, Wihb, bihf, bhhf, bihb, bhhb);

    lstm_k<<<dim3(2,16,2), 256>>>(Whhf, Whhb);

    fc1_mma_k<<<128, 256, sf>>>(fc1w);
    fc1_reduce_k<<<128, 256>>>(fc1b);
    score_k<<<1, 256>>>(fsw, fsb, (float*)d_out);
}

// round 10
// speedup vs baseline: 3.7487x; 1.0577x over previous
#include <cuda_runtime.h>
#include <cuda_bf16.h>
#include <cstdint>
#include <math.h>

#define BF 256
#define NT 256

// ---------------------------------------------------------------------------
// Static scratch. All intermediates bf16.
// ---------------------------------------------------------------------------
__device__ __align__(16) __nv_bfloat16 g_x0[(size_t)BF*NT*27*16];
__device__ __align__(16) __nv_bfloat16 g_x1[(size_t)BF*NT*9*32];
__device__ __align__(16) __nv_bfloat16 g_x2[(size_t)BF*NT*3*64];
__device__ __align__(16) __nv_bfloat16 g_xT[(size_t)NT*BF*128];
__device__ __align__(16) __nv_bfloat16 g_G[(size_t)2*65536*512];
__device__ __align__(16) __nv_bfloat16 g_hcat[(size_t)BF*65536];
__device__ __align__(16) float g_fc1part[(size_t)128*256*128];
__device__ __align__(16) float g_z1[(size_t)256*128];
__device__ __align__(16) __nv_bfloat16 g_wT1[9*32*16];
__device__ __align__(16) __nv_bfloat16 g_wT2[9*64*32];
__device__ __align__(16) __nv_bfloat16 g_wT3[9*128*64];
__device__ __align__(16) __nv_bfloat16 g_Wihb16[(size_t)2*512*128];
__device__ __align__(16) __nv_bfloat16 g_fc1wb16[(size_t)128*65536];

// ---------------------------------------------------------------------------
// helpers
// ---------------------------------------------------------------------------
__device__ __forceinline__ uint32_t packbf(float lo, float hi)
{
    __nv_bfloat162 h = __floats2bfloat162_rn(lo, hi);
    return *(uint32_t*)&h;
}
__device__ __forceinline__ void mma_bf16(float* d, const uint32_t* a, const uint32_t* b)
{
    asm("mma.sync.aligned.m16n8k16.row.col.f32.bf16.bf16.f32 "
        "{%0,%1,%2,%3}, {%4,%5,%6,%7}, {%8,%9}, {%0,%1,%2,%3};"
        : "+f"(d[0]), "+f"(d[1]), "+f"(d[2]), "+f"(d[3])
        : "r"(a[0]), "r"(a[1]), "r"(a[2]), "r"(a[3]), "r"(b[0]), "r"(b[1]));
}
__device__ __forceinline__ uint32_t smem_u32(const void* p)
{
    return (uint32_t)__cvta_generic_to_shared(p);
}
__device__ __forceinline__ void cp16(uint32_t dst, const void* src)
{
    asm volatile("cp.async.cg.shared.global [%0], [%1], 16;" :: "r"(dst), "l"(src));
}
__device__ __forceinline__ void cp16z(uint32_t dst, const void* src)
{
    asm volatile("cp.async.cg.shared.global [%0], [%1], 16, 0;" :: "r"(dst), "l"(src));
}
__device__ __forceinline__ void cp_commit() { asm volatile("cp.async.commit_group;"); }
__device__ __forceinline__ void cp_wait0()  { asm volatile("cp.async.wait_group 0;"); }

// ---------------------------------------------------------------------------
// Prep: conv weights w[co][ci][kh][kw] fp32 -> wT[tap][co][ci] bf16
// ---------------------------------------------------------------------------
__global__ void wtrans_k(const float* __restrict__ w1, const float* __restrict__ w2,
                         const float* __restrict__ w3)
{
    int idx = blockIdx.x*256 + threadIdx.x;
    const float* w; __nv_bfloat16* wT; int CIN, COUT;
    if (idx < 4608)        { w = w1; wT = g_wT1; CIN = 16; COUT = 32; }
    else if (idx < 23040)  { w = w2; wT = g_wT2; CIN = 32; COUT = 64; idx -= 4608; }
    else if (idx < 96768)  { w = w3; wT = g_wT3; CIN = 64; COUT = 128; idx -= 23040; }
    else return;
    int ci  = idx % CIN;
    int r   = idx / CIN;
    int co  = r % COUT;
    int tap = r / COUT;
    wT[idx] = __float2bfloat16(w[(co*CIN + ci)*9 + tap]);
}

// Prep: Wih (both dirs) + fc1_w fp32 -> bf16
__global__ void prep_bf16_k(const float* __restrict__ Wihf, const float* __restrict__ Wihb,
                            const float* __restrict__ fc1w)
{
    const size_t total = 131072 + 8388608;
    for (size_t i = (size_t)blockIdx.x*256 + threadIdx.x; i < total;
         i += (size_t)gridDim.x*256) {
        if (i < 65536)        g_Wihb16[i] = __float2bfloat16(Wihf[i]);
        else if (i < 131072)  g_Wihb16[i] = __float2bfloat16(Wihb[i-65536]);
        else                  g_fc1wb16[i-131072] = __float2bfloat16(fc1w[i-131072]);
    }
}

// ---------------------------------------------------------------------------
// conv0: CIN=1 -> 16, direct. out NHWC bf16 [bf][t][27][16].
// ---------------------------------------------------------------------------
__global__ void conv0_k(const float* __restrict__ audio, const float* __restrict__ w,
                        const float* __restrict__ bias, __nv_bfloat16* __restrict__ out)
{
    __shared__ float wsm[9][16];
    __shared__ float bsm[16];
    int tid = threadIdx.x;
    if (tid < 144) wsm[tid % 9][tid / 9] = w[tid];
    if (tid < 16)  bsm[tid] = bias[tid];
    __syncthreads();

    size_t idx = (size_t)blockIdx.x*256 + tid;
    int wo = (int)(idx % 27);
    size_t r = idx / 27;
    int t  = (int)(r % NT);
    int bf = (int)(r / NT);

    float acc[16];
    #pragma unroll
    for (int co = 0; co < 16; co++) acc[co] = bsm[co];

    #pragma unroll
    for (int kh = 0; kh < 3; kh++) {
        int ti = t + kh - 1;
        if (ti < 0 || ti >= NT) continue;
        #pragma unroll
        for (int kw = 0; kw < 3; kw++) {
            int wc = 3*wo + kw - 1;
            if (wc < 0 || wc >= 81) continue;
            float v = audio[((size_t)bf*NT + ti)*81 + wc];
            #pragma unroll
            for (int co = 0; co < 16; co++) acc[co] += v * wsm[kh*3+kw][co];
        }
    }
    uint32_t* o = (uint32_t*)(out + idx*16);
    #pragma unroll
    for (int q = 0; q < 8; q++)
        o[q] = packbf(fmaxf(acc[q*2+0], 0.f), fmaxf(acc[q*2+1], 0.f));
}

// ---------------------------------------------------------------------------
// Conv, bf16 mma, SINGLE tile load per block. Block = (t-tile 128, bf).
// A tile: [130][WIN][CIN] bf16 (haloed, zero-padded via cp.async src-size 0).
// B tile: all 9 taps [9][COUT][CIN] bf16. One __syncthreads total, then
// pure mma over (wo, valid taps, k16) with conflict-free padded strides.
// ---------------------------------------------------------------------------
template<int CIN,int COUT,int WIN,int WOUT,bool TOUT>
__global__ void conv_mma_k(const __nv_bfloat16* __restrict__ x,
                           const __nv_bfloat16* __restrict__ wT,
                           const float* __restrict__ bias,
                           __nv_bfloat16* __restrict__ out)
{
    constexpr int CU  = CIN/2;            // u32 per CIN
    constexpr int LDT = WIN*CU + 4;       // A tile row stride (u32)
    constexpr int LDB = CU + 4;           // B row stride (u32)
    constexpr int NWN = COUT/32, WMW = 8/NWN, MFR = 128/WMW/16;
    constexpr int NK16 = CIN/16;
    extern __shared__ uint32_t sm[];
    uint32_t* At = sm;                    // [130][LDT]
    uint32_t* Bt = sm + 130*LDT;          // [9][COUT][LDB]

    const int tid  = threadIdx.x;
    const int lane = tid & 31;
    const int wid  = tid >> 5;
    const int g    = lane >> 2, tq = lane & 3;
    const int wm0  = (wid % WMW) * (128/WMW);
    const int wn0  = (wid / WMW) * 32;
    const int t0   = blockIdx.x * 128;
    const int bf   = blockIdx.y;

    // --- A fill: 130 rows x WIN*CIN bf16 contiguous per row ---
    constexpr int ACH = WIN*CU/4;         // 16B chunks per row
    for (int l = tid; l < 130*ACH; l += 256) {
        int row = l / ACH, ch = l % ACH;
        int t_in = t0 + row - 1;
        uint32_t dst = smem_u32(At + row*LDT + ch*4);
        const __nv_bfloat16* src = x + ((size_t)bf*NT + (t_in < 0 ? 0 : (t_in >= NT ? NT-1 : t_in)))*WIN*CIN + ch*8;
        if (t_in >= 0 && t_in < NT) cp16(dst, src);
        else                        cp16z(dst, src);
    }
    // --- B fill: 9*COUT rows x CIN bf16 ---
    constexpr int BCH = CU/4;
    for (int l = tid; l < 9*COUT*BCH; l += 256) {
        int r = l / BCH, ch = l % BCH;
        cp16(smem_u32(Bt + r*LDB + ch*4), wT + (size_t)r*CIN + ch*8);
    }
    cp_commit();
    cp_wait0();
    __syncthreads();

    float bv[4][2];
    #pragma unroll
    for (int fj = 0; fj < 4; fj++) {
        int co0 = wn0 + fj*8 + 2*tq;
        bv[fj][0] = bias[co0]; bv[fj][1] = bias[co0+1];
    }

    #pragma unroll 1
    for (int wo = 0; wo < WOUT; wo++) {
        float acc[MFR][4][4];
        #pragma unroll
        for (int i = 0; i < MFR; i++)
            #pragma unroll
            for (int j = 0; j < 4; j++)
                #pragma unroll
                for (int q = 0; q < 4; q++) acc[i][j][q] = 0.f;

        #pragma unroll
        for (int kh = 0; kh < 3; kh++) {
            #pragma unroll
            for (int kw = 0; kw < 3; kw++) {
                const int wc = 3*wo + kw - 1;
                if (wc < 0 || wc >= WIN) continue;
                const uint32_t* Btap = Bt + (size_t)(kh*3+kw)*COUT*LDB;
                #pragma unroll
                for (int k16 = 0; k16 < NK16; k16++) {
                    const int kp = k16*8;
                    const int ac = wc*CU + kp;
                    uint32_t a[MFR][4], b[4][2];
                    #pragma unroll
                    for (int fi = 0; fi < MFR; fi++) {
                        int r = wm0 + fi*16 + g + kh;   // haloed tile row
                        a[fi][0] = At[(r  )*LDT + ac + tq];
                        a[fi][1] = At[(r+8)*LDT + ac + tq];
                        a[fi][2] = At[(r  )*LDT + ac + tq + 4];
                        a[fi][3] = At[(r+8)*LDT + ac + tq + 4];
                    }
                    #pragma unroll
                    for (int fj = 0; fj < 4; fj++) {
                        int cn = wn0 + fj*8 + g;
                        b[fj][0] = Btap[cn*LDB + kp + tq];
                        b[fj][1] = Btap[cn*LDB + kp + tq + 4];
                    }
                    #pragma unroll
                    for (int fi = 0; fi < MFR; fi++)
                        #pragma unroll
                        for (int fj = 0; fj < 4; fj++)
                            mma_bf16(acc[fi][fj], a[fi], b[fj]);
                }
            }
        }

        // epilogue for this wo
        #pragma unroll
        for (int fj = 0; fj < 4; fj++) {
            int co0 = wn0 + fj*8 + 2*tq;
            #pragma unroll
            for (int fi = 0; fi < MFR; fi++) {
                #pragma unroll
                for (int p = 0; p < 2; p++) {
                    int m = wm0 + fi*16 + g + p*8;
                    uint32_t v = packbf(fmaxf(acc[fi][fj][p*2+0] + bv[fj][0], 0.f),
                                        fmaxf(acc[fi][fj][p*2+1] + bv[fj][1], 0.f));
                    size_t base;
                    if (TOUT) base = ((size_t)(t0+m)*BF + bf)*COUT + co0;
                    else      base = (((size_t)bf*NT + (t0+m))*WOUT + wo)*COUT + co0;
                    *(uint32_t*)(out + base) = v;
                }
            }
        }
    }
}

// ---------------------------------------------------------------------------
// Input-projection GEMM, bf16 mma, cp.async double-buffered k-loop.
// ---------------------------------------------------------------------------
__global__ void gemm_xw_k(const __nv_bfloat16* __restrict__ X,
                          const float* __restrict__ bihf, const float* __restrict__ bhhf,
                          const float* __restrict__ bihb, const float* __restrict__ bhhb)
{
    const int dir = blockIdx.z;
    const __nv_bfloat16* W = g_Wihb16 + (size_t)dir*65536;
    const float* b1 = dir ? bihb : bihf;
    const float* b2 = dir ? bhhb : bhhf;
    __nv_bfloat16* out = g_G + (size_t)dir*65536*512;

    __shared__ uint32_t As[2][128][20];
    __shared__ uint32_t Bs[2][128][20];

    const int tid  = threadIdx.x;
    const int lane = tid & 31;
    const int wid  = tid >> 5;
    const int g    = lane >> 2, tq = lane & 3;
    const int wm0  = (wid & 1) * 64;
    const int wn0  = (wid >> 1) * 32;
    const int m0   = blockIdx.y * 128, n0 = blockIdx.x * 128;

    const int l = tid, l2 = 256 + tid;
    const int ma = l >> 2, ka = l & 3, mb = l2 >> 2, kb = l2 & 3;

    float acc[4][4][4];
    #pragma unroll
    for (int i = 0; i < 4; i++)
        #pragma unroll
        for (int j = 0; j < 4; j++)
            #pragma unroll
            for (int q = 0; q < 4; q++) acc[i][j][q] = 0.f;

    // prefetch kt=0
    cp16(smem_u32(&As[0][ma][ka*4]), X + (size_t)(m0+ma)*128 + ka*8);
    cp16(smem_u32(&As[0][mb][kb*4]), X + (size_t)(m0+mb)*128 + kb*8);
    cp16(smem_u32(&Bs[0][ma][ka*4]), W + (size_t)(n0+ma)*128 + ka*8);
    cp16(smem_u32(&Bs[0][mb][kb*4]), W + (size_t)(n0+mb)*128 + kb*8);
    cp_commit();
    cp_wait0();
    __syncthreads();

    for (int it = 0; it < 4; it++) {
        const int b = it & 1;
        if (it < 3) {
            int kt = (it+1)*32;
            cp16(smem_u32(&As[b^1][ma][ka*4]), X + (size_t)(m0+ma)*128 + kt + ka*8);
            cp16(smem_u32(&As[b^1][mb][kb*4]), X + (size_t)(m0+mb)*128 + kt + kb*8);
            cp16(smem_u32(&Bs[b^1][ma][ka*4]), W + (size_t)(n0+ma)*128 + kt + ka*8);
            cp16(smem_u32(&Bs[b^1][mb][kb*4]), W + (size_t)(n0+mb)*128 + kt + kb*8);
            cp_commit();
        }
        #pragma unroll
        for (int k16 = 0; k16 < 2; k16++) {
            const int kp = k16*8;
            uint32_t a[4][4], bb[4][2];
            #pragma unroll
            for (int fi = 0; fi < 4; fi++) {
                int r = wm0 + fi*16;
                a[fi][0] = As[b][r+g  ][kp+tq];
                a[fi][1] = As[b][r+g+8][kp+tq];
                a[fi][2] = As[b][r+g  ][kp+tq+4];
                a[fi][3] = As[b][r+g+8][kp+tq+4];
            }
            #pragma unroll
            for (int fj = 0; fj < 4; fj++) {
                int cn = wn0 + fj*8 + g;
                bb[fj][0] = Bs[b][cn][kp+tq];
                bb[fj][1] = Bs[b][cn][kp+tq+4];
            }
            #pragma unroll
            for (int fi = 0; fi < 4; fi++)
                #pragma unroll
                for (int fj = 0; fj < 4; fj++)
                    mma_bf16(acc[fi][fj], a[fi], bb[fj]);
        }
        if (it < 3) cp_wait0();
        __syncthreads();
    }

    #pragma unroll
    for (int fj = 0; fj < 4; fj++) {
        int gate0 = n0 + wn0 + fj*8 + 2*tq;
        float bv0 = b1[gate0]   + b2[gate0];
        float bv1 = b1[gate0+1] + b2[gate0+1];
        #pragma unroll
        for (int fi = 0; fi < 4; fi++) {
            #pragma unroll
            for (int p = 0; p < 2; p++) {
                int m = m0 + wm0 + fi*16 + g + p*8;
                *(uint32_t*)(out + (size_t)m*512 + gate0) =
                    packbf(acc[fi][fj][p*2+0] + bv0, acc[fi][fj][p*2+1] + bv1);
            }
        }
    }
}

// ---------------------------------------------------------------------------
// LSTM recurrence (unchanged from R9).
// ---------------------------------------------------------------------------
__device__ __forceinline__ float sigf(float x) { return 1.f / (1.f + expf(-x)); }

__global__ void __cluster_dims__(2,1,1) __launch_bounds__(256,1)
lstm_k(const float* __restrict__ Whhf, const float* __restrict__ Whhb)
{
    __shared__ __nv_bfloat16 hbuf[2*16*136];
    __shared__ float zsm[16][258];

    const int tid  = threadIdx.x;
    const int lane = tid & 31;
    const int w    = tid >> 5;
    const int g    = lane >> 2, tq = lane & 3;
    const int rank = blockIdx.x & 1;
    const int dir  = blockIdx.z;
    const int nb0  = blockIdx.y * 16;
    const float* Whh = dir ? Whhb : Whhf;
    const __nv_bfloat16* G = g_G + (size_t)dir*65536*512;

    uint32_t wb[4][8][2];
    #pragma unroll
    for (int fj = 0; fj < 4; fj++) {
        int rl = w*32 + fj*8 + g;
        int grow = (rl >> 6)*128 + rank*64 + (rl & 63);
        const float* wr = Whh + (size_t)grow*128;
        #pragma unroll
        for (int kt = 0; kt < 8; kt++) {
            wb[fj][kt][0] = packbf(wr[kt*16 + 2*tq    ], wr[kt*16 + 2*tq + 1]);
            wb[fj][kt][1] = packbf(wr[kt*16 + 2*tq + 8], wr[kt*16 + 2*tq + 9]);
        }
    }

    {
        uint32_t* hz = (uint32_t*)hbuf;
        for (int idx = tid; idx < 2*16*136/2; idx += 256) hz[idx] = 0u;
    }

    uint32_t hbuf_u32;
    { uint64_t tmp;
      asm("cvta.to.shared.u64 %0, %1;" : "=l"(tmp) : "l"((__nv_bfloat16*)hbuf));
      hbuf_u32 = (uint32_t)tmp; }

    asm volatile("barrier.cluster.arrive.aligned;\n\tbarrier.cluster.wait.aligned;" ::: "memory");

    const int j    = tid & 63;
    const int bq   = tid >> 6;
    const int gcol = rank*64 + j;
    const int peer = rank ^ 1;
    float c[4] = {0.f, 0.f, 0.f, 0.f};

    float Gc[4][4], Gn[4][4];
    {
        int t0 = dir ? 255 : 0;
        #pragma unroll
        for (int mm = 0; mm < 4; mm++)
            #pragma unroll
            for (int gt = 0; gt < 4; gt++)
                Gc[mm][gt] = __bfloat162float(G[((size_t)t0*256 + nb0 + bq*4 + mm)*512 + gt*128 + gcol]);
    }

    for (int s = 0; s < 256; s++) {
        const int t   = dir ? (255 - s) : s;
        const int cur = s & 1, nxt = cur ^ 1;

        float acc[4][4];
        #pragma unroll
        for (int fj = 0; fj < 4; fj++)
            #pragma unroll
            for (int q = 0; q < 4; q++) acc[fj][q] = 0.f;

        const uint32_t* hb = (const uint32_t*)(hbuf + cur*16*136);
        #pragma unroll
        for (int kt = 0; kt < 8; kt++) {
            const int kp = kt*8;
            uint32_t a[4];
            a[0] = hb[(g  )*68 + kp + tq];
            a[1] = hb[(g+8)*68 + kp + tq];
            a[2] = hb[(g  )*68 + kp + tq + 4];
            a[3] = hb[(g+8)*68 + kp + tq + 4];
            #pragma unroll
            for (int fj = 0; fj < 4; fj++)
                mma_bf16(acc[fj], a, wb[fj][kt]);
        }
        #pragma unroll
        for (int fj = 0; fj < 4; fj++) {
            int nloc = w*32 + fj*8 + 2*tq;
            *(float2*)&zsm[g  ][nloc] = make_float2(acc[fj][0], acc[fj][1]);
            *(float2*)&zsm[g+8][nloc] = make_float2(acc[fj][2], acc[fj][3]);
        }
        __syncthreads();

        if (s < 255) {
            int tn = dir ? (254 - s) : (s + 1);
            #pragma unroll
            for (int mm = 0; mm < 4; mm++)
                #pragma unroll
                for (int gt = 0; gt < 4; gt++)
                    Gn[mm][gt] = __bfloat162float(G[((size_t)tn*256 + nb0 + bq*4 + mm)*512 + gt*128 + gcol]);
        }

        #pragma unroll
        for (int mm = 0; mm < 4; mm++) {
            int m = bq*4 + mm;
            float ai = zsm[m][0*64 + j] + Gc[mm][0];
            float af = zsm[m][1*64 + j] + Gc[mm][1];
            float ag = zsm[m][2*64 + j] + Gc[mm][2];
            float ao = zsm[m][3*64 + j] + Gc[mm][3];
            float iv = sigf(ai);
            float fv = sigf(af);
            float gv = tanhf(ag);
            float ov = sigf(ao);
            c[mm] = fv*c[mm] + iv*gv;
            float hv = ov * tanhf(c[mm]);
            __nv_bfloat16 hb16 = __float2bfloat16(hv);
            g_hcat[(size_t)(nb0+m)*65536 + t*256 + dir*128 + gcol] = hb16;
            int off = (nxt*16 + m)*136 + gcol;
            hbuf[off] = hb16;
            unsigned short hu = *(unsigned short*)&hb16;
            uint32_t raddr;
            asm volatile("mapa.shared::cluster.u32 %0, %1, %2;"
                         : "=r"(raddr) : "r"(hbuf_u32 + (uint32_t)off*2u), "r"(peer));
            asm volatile("st.shared::cluster.b16 [%0], %1;" :: "r"(raddr), "h"(hu) : "memory");
        }
        #pragma unroll
        for (int mm = 0; mm < 4; mm++)
            #pragma unroll
            for (int gt = 0; gt < 4; gt++) Gc[mm][gt] = Gn[mm][gt];
        asm volatile("barrier.cluster.arrive.aligned;\n\tbarrier.cluster.wait.aligned;" ::: "memory");
    }
}

// ---------------------------------------------------------------------------
// FC1 split-K, bf16 mma, cp.async double-buffered. M=256, N=128, Kchunk=512.
// ---------------------------------------------------------------------------
__global__ void fc1_mma_k()
{
    extern __shared__ uint32_t fsm[];
    uint32_t (*As)[20] = (uint32_t(*)[20])fsm;               // [2][256][20]
    uint32_t (*Bs)[20] = (uint32_t(*)[20])(fsm + 2*256*20);  // [2][128][20]

    const int tid  = threadIdx.x;
    const int lane = tid & 31;
    const int wid  = tid >> 5;
    const int g    = lane >> 2, tq = lane & 3;
    const int wm0  = (wid & 1) * 128;
    const int wn0  = (wid >> 1) * 32;
    const int k0   = blockIdx.x * 512;

    float acc[8][4][4];
    #pragma unroll
    for (int i = 0; i < 8; i++)
        #pragma unroll
        for (int j = 0; j < 4; j++)
            #pragma unroll
            for (int q = 0; q < 4; q++) acc[i][j][q] = 0.f;

    auto prefetch = [&](int b, int kt) {
        #pragma unroll
        for (int i = 0; i < 4; i++) {           // A: 256x32 bf16 = 1024 chunks
            int l = i*256 + tid;
            int m = l >> 2, kq = l & 3;
            cp16(smem_u32(&As[b*256 + m][kq*4]),
                 g_hcat + (size_t)m*65536 + k0 + kt + kq*8);
        }
        #pragma unroll
        for (int i = 0; i < 2; i++) {           // B: 128x32 bf16 = 512 chunks
            int l = i*256 + tid;
            int n = l >> 2, kq = l & 3;
            cp16(smem_u32(&Bs[b*128 + n][kq*4]),
                 g_fc1wb16 + (size_t)n*65536 + k0 + kt + kq*8);
        }
    };

    prefetch(0, 0);
    cp_commit();
    cp_wait0();
    __syncthreads();

    for (int it = 0; it < 16; it++) {
        const int b = it & 1;
        if (it < 15) { prefetch(b^1, (it+1)*32); cp_commit(); }
        #pragma unroll
        for (int k16 = 0; k16 < 2; k16++) {
            const int kp = k16*8;
            uint32_t a[8][4], bb[4][2];
            #pragma unroll
            for (int fi = 0; fi < 8; fi++) {
                int r = b*256 + wm0 + fi*16;
                a[fi][0] = As[r+g  ][kp+tq];
                a[fi][1] = As[r+g+8][kp+tq];
                a[fi][2] = As[r+g  ][kp+tq+4];
                a[fi][3] = As[r+g+8][kp+tq+4];
            }
            #pragma unroll
            for (int fj = 0; fj < 4; fj++) {
                int cn = b*128 + wn0 + fj*8 + g;
                bb[fj][0] = Bs[cn][kp+tq];
                bb[fj][1] = Bs[cn][kp+tq+4];
            }
            #pragma unroll
            for (int fi = 0; fi < 8; fi++)
                #pragma unroll
                for (int fj = 0; fj < 4; fj++)
                    mma_bf16(acc[fi][fj], a[fi], bb[fj]);
        }
        if (it < 15) cp_wait0();
        __syncthreads();
    }

    float* part = g_fc1part + (size_t)blockIdx.x*256*128;
    #pragma unroll
    for (int fj = 0; fj < 4; fj++) {
        int n0 = wn0 + fj*8 + 2*tq;
        #pragma unroll
        for (int fi = 0; fi < 8; fi++) {
            #pragma unroll
            for (int p = 0; p < 2; p++) {
                int m = wm0 + fi*16 + g + p*8;
                *(float2*)(part + (size_t)m*128 + n0) =
                    make_float2(acc[fi][fj][p*2+0], acc[fi][fj][p*2+1]);
            }
        }
    }
}

__global__ void fc1_reduce_k(const float* __restrict__ fc1b)
{
    int idx = blockIdx.x*256 + threadIdx.x;
    int m = idx >> 7, h = idx & 127;
    float s = fc1b[h];
    #pragma unroll 8
    for (int kc = 0; kc < 128; kc++)
        s += g_fc1part[((size_t)kc*256 + m)*128 + h];
    g_z1[(size_t)m*128 + h] = fmaxf(s, 0.f);
}

__global__ void score_k(const float* __restrict__ fsw, const float* __restrict__ fsb,
                        float* __restrict__ out)
{
    __shared__ float w[128];
    __shared__ float fr[256];
    int tid = threadIdx.x;
    if (tid < 128) w[tid] = fsw[tid];
    __syncthreads();
    float acc = fsb[0];
    #pragma unroll 8
    for (int h = 0; h < 128; h++) acc += g_z1[(size_t)tid*128 + h] * w[h];
    float sc = 1.f / (1.f + expf(-acc)) * 4.f + 1.f;
    out[16 + tid] = sc;
    fr[tid] = sc;
    __syncthreads();
    if (tid < 16) {
        float s = 0.f;
        #pragma unroll
        for (int f = 0; f < 16; f++) s += fr[tid*16 + f];
        out[tid] = s * (1.f/16.f);
    }
}

// ---------------------------------------------------------------------------
extern "C" void kernel_launch(void* const* d_in, const int* in_sizes, int n_in,
                              void* d_out, int out_size)
{
    const float *audio,*w0,*b0,*w1,*b1,*w2,*b2,*w3,*b3;
    const float *Wihf,*Whhf,*bihf,*bhhf,*Wihb,*Whhb,*bihb,*bhhb;
    const float *fc1w,*fc1b,*fsw,*fsb;
    if (n_in >= 22 && in_sizes[1] == 144) {
        audio=(const float*)d_in[0];
        w0=(const float*)d_in[1];  b0=(const float*)d_in[2];
        w1=(const float*)d_in[3];  b1=(const float*)d_in[4];
        w2=(const float*)d_in[5];  b2=(const float*)d_in[6];
        w3=(const float*)d_in[7];  b3=(const float*)d_in[8];
        Wihf=(const float*)d_in[9];  Whhf=(const float*)d_in[10];
        bihf=(const float*)d_in[11]; bhhf=(const float*)d_in[12];
        Wihb=(const float*)d_in[13]; Whhb=(const float*)d_in[14];
        bihb=(const float*)d_in[15]; bhhb=(const float*)d_in[16];
        fc1w=(const float*)d_in[17]; fc1b=(const float*)d_in[18];
        fsw=(const float*)d_in[19];  fsb=(const float*)d_in[20];
    } else {
        audio=(const float*)d_in[0];
        w0=(const float*)d_in[2];  b0=(const float*)d_in[3];
        w1=(const float*)d_in[4];  b1=(const float*)d_in[5];
        w2=(const float*)d_in[6];  b2=(const float*)d_in[7];
        w3=(const float*)d_in[8];  b3=(const float*)d_in[9];
        Wihf=(const float*)d_in[10]; Whhf=(const float*)d_in[11];
        bihf=(const float*)d_in[12]; bhhf=(const float*)d_in[13];
        Wihb=(const float*)d_in[14]; Whhb=(const float*)d_in[15];
        bihb=(const float*)d_in[16]; bhhb=(const float*)d_in[17];
        fc1w=(const float*)d_in[18]; fc1b=(const float*)d_in[19];
        fsw=(const float*)d_in[20];  fsb=(const float*)d_in[21];
    }

    __nv_bfloat16 *x0,*x1,*x2,*xT,*wT1,*wT2,*wT3;
    cudaGetSymbolAddress((void**)&x0, g_x0);
    cudaGetSymbolAddress((void**)&x1, g_x1);
    cudaGetSymbolAddress((void**)&x2, g_x2);
    cudaGetSymbolAddress((void**)&xT, g_xT);
    cudaGetSymbolAddress((void**)&wT1, g_wT1);
    cudaGetSymbolAddress((void**)&wT2, g_wT2);
    cudaGetSymbolAddress((void**)&wT3, g_wT3);

    // conv smem: 130*LDT*4 + 9*COUT*LDB*4
    const int sc1 = (130*(27*8 +4) + 9*32 *(8 +4))*4;   // 128,224
    const int sc2 = (130*(9*16 +4) + 9*64 *(16+4))*4;   // 123,040
    const int sc3 = (130*(3*32 +4) + 9*128*(32+4))*4;   // 217,888
    const int sf  = 2*(256 + 128)*20*4;                 // 61,440
    cudaFuncSetAttribute(conv_mma_k<16, 32,27,9,false>, cudaFuncAttributeMaxDynamicSharedMemorySize, sc1);
    cudaFuncSetAttribute(conv_mma_k<32, 64, 9,3,false>, cudaFuncAttributeMaxDynamicSharedMemorySize, sc2);
    cudaFuncSetAttribute(conv_mma_k<64,128, 3,1,true >, cudaFuncAttributeMaxDynamicSharedMemorySize, sc3);
    cudaFuncSetAttribute(fc1_mma_k, cudaFuncAttributeMaxDynamicSharedMemorySize, sf);

    wtrans_k<<<(96768 + 255)/256, 256>>>(w1, w2, w3);
    prep_bf16_k<<<8192, 256>>>(Wihf, Wihb, fc1w);

    conv0_k<<<(BF*NT*27)/256, 256>>>(audio, w0, b0, x0);
    conv_mma_k<16, 32,27,9,false><<<dim3(2,BF), 256, sc1>>>(x0, wT1, b1, x1);
    conv_mma_k<32, 64, 9,3,false><<<dim3(2,BF), 256, sc2>>>(x1, wT2, b2, x2);
    conv_mma_k<64,128, 3,1,true ><<<dim3(2,BF), 256, sc3>>>(x2, wT3, b3, xT);

    gemm_xw_k<<<dim3(4,512,2), 256>>>(xT, bihf, bhhf, bihb, bhhb);

    lstm_k<<<dim3(2,16,2), 256>>>(Whhf, Whhb);

    fc1_mma_k<<<128, 256, sf>>>();
    fc1_reduce_k<<<128, 256>>>(fc1b);
    score_k<<<1, 256>>>(fsw, fsb, (float*)d_out);
}